// round 10
// baseline (speedup 1.0000x reference)
#include <cuda_runtime.h>
#include <cstdint>

// Problem constants: B=2, C=256, T=512, F=128, N=4 heads, H=CN=64, D=H*F=8192
#define TFsz 65536            // T*F
typedef unsigned long long u64;

// -------- scratch (device globals; no allocations allowed) --------
__device__ float g_Y3[100663296];   // [3][B][256][TF] Q,K,V (pre-norm)
__device__ float g_Sp[8388608];     // [4 kchunks][8 g][512][512] partial scores
__device__ float g_S[2097152];      // [8][512][512] attention probs
__device__ float g_Z[33554432];     // [B][256][TF] permuted attention output
__device__ float g_Yp[33554432];    // [B][256][TF] final conv output (pre-norm)
__device__ float2 g_part[12288];    // partial (sum, sumsq) from GEMM epilogues
__device__ float2 g_stats[32];      // (mu, rstd): [0..23] qkv groups, [24..25] final

// -------- PTX helpers (portable; no "a"-gated features) --------
__device__ __forceinline__ uint32_t smem_u32(const void* p) {
    uint32_t a;
    asm("{ .reg .u64 t; cvta.to.shared.u64 t, %1; cvt.u32.u64 %0, t; }" : "=r"(a) : "l"(p));
    return a;
}
#define CP16(dst, src) \
    asm volatile("cp.async.cg.shared.global [%0], [%1], 16;" :: "r"(dst), "l"(src))
#define CP_COMMIT() asm volatile("cp.async.commit_group;" ::: "memory")
#define CP_WAIT1()  asm volatile("cp.async.wait_group 1;" ::: "memory")
#define CP_WAIT0()  asm volatile("cp.async.wait_group 0;" ::: "memory")

// Raw fp32 bits into tf32 mma: tensor core reads the high 19 bits (truncation).
__device__ __forceinline__ void mma_tf32(float c[4], const uint32_t a[4], const uint32_t b[2]) {
    asm volatile(
        "mma.sync.aligned.m16n8k8.row.col.f32.tf32.tf32.f32 "
        "{%0,%1,%2,%3}, {%4,%5,%6,%7}, {%8,%9}, {%0,%1,%2,%3};"
        : "+f"(c[0]), "+f"(c[1]), "+f"(c[2]), "+f"(c[3])
        : "r"(a[0]), "r"(a[1]), "r"(a[2]), "r"(a[3]), "r"(b[0]), "r"(b[1]));
}
__device__ __forceinline__ float napply(float v, float gg, float of) {
    float y = fmaf(v, gg, of);
    return (y >= 0.f) ? y : 0.25f * y;
}

// ---------------------------------------------------------------------------
// X-resident tf32 conv GEMM: block loads X tile [256 c][128 j] into smem ONCE,
// then loops over 2*nTens output slabs (tens, o-half) streaming only W chunks
// (cp.async double-buffered, 32-k). X DRAM traffic drops 6x -> 1x.
// Dynamic smem (words): Xs[256*136] @0, Ws[2][128*36] @34816 (+4608 per buf).
// Accumulation order per output identical to prior rounds (bit-identical).
// grid (512 j-tiles, B), 256 threads, 1 CTA/SM (176 KB smem).
// ---------------------------------------------------------------------------
__global__ void __launch_bounds__(256, 1) conv_mma2_kernel(
    const float* __restrict__ X, float* __restrict__ Out,
    const float* __restrict__ W0, const float* __restrict__ W1, const float* __restrict__ W2,
    const float* __restrict__ b0_, const float* __restrict__ b1_, const float* __restrict__ b2_,
    float2* __restrict__ part, int nTens)
{
    extern __shared__ __align__(16) uint32_t dsm[];
    const uint32_t sb = smem_u32(dsm);

    const int bb = blockIdx.y;
    const int j0 = blockIdx.x * 128;
    const float* Xb = X + (size_t)bb * (256 * (size_t)TFsz);

    const int tid = threadIdx.x;
    const int w = tid >> 5, l = tid & 31;
    const int g = l >> 2, t = l & 3;
    const int orow = w >> 2, jcol = w & 3;

    const int xr0 = tid >> 5, xc4 = tid & 31;    // X copy coords (+it*8 rows, 32 its)
    const int wrow0 = tid >> 3, wc4 = tid & 7;   // W copy coords (+it*32 rows)

    const float* Wt0 = W0; const float* Wt1 = W1; const float* Wt2 = W2;
    const int total = nTens * 16;                // total W chunks (2 o-halves x 8 kc)

#define ISSUE_W(Q) do {                                                       \
    int _q = (Q);                                                             \
    int _y = _q >> 3, _kc = _q & 7;                                           \
    int _tens = _y >> 1, _o0 = (_y & 1) * 128;                                \
    const float* _W = (_tens == 0) ? Wt0 : (_tens == 1) ? Wt1 : Wt2;          \
    uint32_t _wdst = sb + (34816 + (_q & 1) * 4608) * 4;                      \
    _Pragma("unroll")                                                         \
    for (int it = 0; it < 4; it++) {                                          \
        int row = wrow0 + it * 32;                                            \
        CP16(_wdst + (row * 36 + wc4 * 4) * 4,                                \
             &_W[(size_t)(_o0 + row) * 256 + _kc * 32 + wc4 * 4]);            \
    }                                                                         \
    CP_COMMIT();                                                              \
} while (0)

    // X tile load (one-time) + W chunk 0 in the same cp.async group
#pragma unroll
    for (int it = 0; it < 32; it++) {
        int row = xr0 + it * 8;
        CP16(sb + (row * 136 + xc4 * 4) * 4,
             &Xb[(size_t)row * TFsz + j0 + xc4 * 4]);
    }
    {
        int _y = 0, _kc = 0;
        int _o0 = 0;
        const float* _W = Wt0;
        uint32_t _wdst = sb + 34816 * 4;
#pragma unroll
        for (int it = 0; it < 4; it++) {
            int row = wrow0 + it * 32;
            CP16(_wdst + (row * 36 + wc4 * 4) * 4,
                 &_W[(size_t)(_o0 + row) * 256 + _kc * 32 + wc4 * 4]);
        }
        CP_COMMIT();
        (void)_y;
    }

    for (int y = 0; y < 2 * nTens; y++) {
        const int tens = y >> 1;
        const int o0 = (y & 1) * 128;
        const float* bias = (tens == 0) ? b0_ : (tens == 1) ? b1_ : b2_;
        const int slab = (nTens == 3) ? (tens * 2 + bb) : bb;
        float* O = Out + (size_t)slab * (256 * (size_t)TFsz);

        float c[4][4][4];
#pragma unroll
        for (int mt = 0; mt < 4; mt++)
#pragma unroll
            for (int nt = 0; nt < 4; nt++)
#pragma unroll
                for (int i = 0; i < 4; i++) c[mt][nt][i] = 0.f;

        for (int kc = 0; kc < 8; kc++) {
            const int q = y * 8 + kc;
            if (q < total - 1) { ISSUE_W(q + 1); CP_WAIT1(); }
            else               { CP_WAIT0(); }
            __syncthreads();

            const uint32_t* Wsb = dsm + 34816 + (q & 1) * 4608;
#pragma unroll
            for (int ks = 0; ks < 4; ks++) {
                const int kk = ks * 8;
                uint32_t a[4][4], b[4][2];
#pragma unroll
                for (int mt = 0; mt < 4; mt++) {
                    int ow = orow * 64 + mt * 16 + g;
                    a[mt][0] = Wsb[ow * 36 + kk + t];
                    a[mt][1] = Wsb[(ow + 8) * 36 + kk + t];
                    a[mt][2] = Wsb[ow * 36 + kk + t + 4];
                    a[mt][3] = Wsb[(ow + 8) * 36 + kk + t + 4];
                }
#pragma unroll
                for (int nt = 0; nt < 4; nt++) {
                    int jw = jcol * 32 + nt * 8 + g;
                    b[nt][0] = dsm[(kc * 32 + kk + t) * 136 + jw];
                    b[nt][1] = dsm[(kc * 32 + kk + t + 4) * 136 + jw];
                }
#pragma unroll
                for (int mt = 0; mt < 4; mt++)
#pragma unroll
                    for (int nt = 0; nt < 4; nt++)
                        mma_tf32(c[mt][nt], a[mt], b[nt]);
            }
            __syncthreads();
        }

        // epilogue for slab y: bias + stores + stats partials
        float bl[4], bh[4];
#pragma unroll
        for (int mt = 0; mt < 4; mt++) {
            bl[mt] = __ldg(&bias[o0 + orow * 64 + mt * 16 + g]);
            bh[mt] = __ldg(&bias[o0 + orow * 64 + mt * 16 + g + 8]);
        }
        float s = 0.f, sq = 0.f;
#pragma unroll
        for (int mt = 0; mt < 4; mt++) {
            const int o_lo = o0 + orow * 64 + mt * 16 + g;
#pragma unroll
            for (int nt = 0; nt < 4; nt++) {
                const int jj = j0 + jcol * 32 + nt * 8 + 2 * t;
                float v0 = c[mt][nt][0] + bl[mt];
                float v1 = c[mt][nt][1] + bl[mt];
                float v2 = c[mt][nt][2] + bh[mt];
                float v3 = c[mt][nt][3] + bh[mt];
                *reinterpret_cast<float2*>(&O[(size_t)o_lo * TFsz + jj]) = make_float2(v0, v1);
                *reinterpret_cast<float2*>(&O[(size_t)(o_lo + 8) * TFsz + jj]) = make_float2(v2, v3);
                s  += (v0 + v1) + (v2 + v3);
                sq += (v0 * v0 + v1 * v1) + (v2 * v2 + v3 * v3);
            }
        }

        // stats reduce: scratch = just-consumed W buffer (in-flight chunk is in
        // the OTHER buffer; next write to this buffer happens after our sync)
        const int qlast = y * 8 + 7;
        float* redS = reinterpret_cast<float*>(dsm + 34816 + (qlast & 1) * 4608);
        float* redQ = redS + 256;
        redS[tid] = s; redQ[tid] = sq;
        __syncthreads();
        const int r = tid & 127;
        for (int off = 64; off > 0; off >>= 1) {
            if (r < off) { redS[tid] += redS[tid + off]; redQ[tid] += redQ[tid + off]; }
            __syncthreads();
        }
        if (r == 0) {
            int og = (y & 1) * 2 + (tid >> 7);
            part[((size_t)slab * 4 + og) * 512 + blockIdx.x] =
                make_float2(redS[tid], redQ[tid]);
        }
        __syncthreads();   // protect scratch before next y's W issue reuses it
    }
#undef ISSUE_W
}

// ---------------------------------------------------------------------------
// Final reduction over `count` consecutive partials per group -> (mu, rstd)
// ---------------------------------------------------------------------------
__global__ void __launch_bounds__(256) reduce_final_kernel(
    const float2* __restrict__ part, float2* __restrict__ stats, int count, float inv_n)
{
    const int g = blockIdx.x;
    float s = 0.f, s2 = 0.f;
    for (int i = threadIdx.x; i < count; i += 256) {
        float2 v = part[(size_t)g * count + i];
        s += v.x; s2 += v.y;
    }
    __shared__ float sh[256], sh2[256];
    int t = threadIdx.x;
    sh[t] = s; sh2[t] = s2;
    __syncthreads();
    for (int off = 128; off > 0; off >>= 1) {
        if (t < off) { sh[t] += sh[t + off]; sh2[t] += sh2[t + off]; }
        __syncthreads();
    }
    if (t == 0) {
        float mu = sh[0] * inv_n;
        float var = fmaxf(sh2[0] * inv_n - mu * mu, 0.f);
        stats[g] = make_float2(mu, rsqrtf(var + 1e-6f));
    }
}

// ---------------------------------------------------------------------------
// QK via tf32 mma.sync (NT, split-K x4): Sp[c][g][t][s] = scale*sum Q'(t,k)K'(s,k)
// Norm+PReLU at smem store (raw float bits; mma truncates to tf32).
// grid (4 s-tiles, 4 t-tiles, 32 = g*4+c), 256 threads.
// ---------------------------------------------------------------------------
__global__ void __launch_bounds__(256, 2) qk_mma_kernel(
    const float* __restrict__ gq, const float* __restrict__ betaq,
    const float* __restrict__ gk, const float* __restrict__ betak)
{
    __shared__ __align__(16) float Qs[128][36];
    __shared__ __align__(16) float Ks[128][36];
    __shared__ float sgg[2][64], sof[2][64];

    const int z = blockIdx.z;
    const int g = z >> 2, c = z & 3;
    const int n = g & 3;
    const float* Q  = g_Y3 + (size_t)g * 4194304;
    const float* Km = g_Y3 + 8ull * 4194304 + (size_t)g * 4194304;
    const int t0 = blockIdx.y * 128, s0 = blockIdx.x * 128;
    const int tid = threadIdx.x;
    const int w = tid >> 5, l = tid & 31;
    const int fg = l >> 2, ft = l & 3;
    const int orow = w >> 2, jcol = w & 3;

    if (tid < 128) {
        int which = tid >> 6, h = tid & 63, o = n * 64 + h;
        float2 st = g_stats[which * 8 + g];
        const float* gw = which ? gk : gq;
        const float* bw = which ? betak : betaq;
        float gg = gw[o] * st.y;
        sgg[which][h] = gg;
        sof[which][h] = bw[o] - st.x * gg;
    }
    __syncthreads();

    float acc[4][4][4];
#pragma unroll
    for (int mt = 0; mt < 4; mt++)
#pragma unroll
        for (int nt = 0; nt < 4; nt++)
#pragma unroll
            for (int i = 0; i < 4; i++) acc[mt][nt][i] = 0.f;

    for (int kc = 0; kc < 64; kc++) {
        const int k0 = c * 2048 + kc * 32;
        const int h = k0 >> 7;
        const size_t hb = (size_t)h * 65536 + (size_t)(k0 & 127);
        const float ggq = sgg[0][h], ofq = sof[0][h];
        const float ggk = sgg[1][h], ofk = sof[1][h];
        float4 qv[4], kv[4];
#pragma unroll
        for (int it = 0; it < 4; it++) {
            int i4 = tid + it * 256;
            int r = i4 >> 3, c4 = i4 & 7;
            qv[it] = *reinterpret_cast<const float4*>(&Q[hb + (size_t)(t0 + r) * 128 + c4 * 4]);
            kv[it] = *reinterpret_cast<const float4*>(&Km[hb + (size_t)(s0 + r) * 128 + c4 * 4]);
        }
        __syncthreads();
#pragma unroll
        for (int it = 0; it < 4; it++) {
            int i4 = tid + it * 256;
            int r = i4 >> 3, c4 = i4 & 7;
            float4 uq, uk;
            uq.x = napply(qv[it].x, ggq, ofq);
            uq.y = napply(qv[it].y, ggq, ofq);
            uq.z = napply(qv[it].z, ggq, ofq);
            uq.w = napply(qv[it].w, ggq, ofq);
            *reinterpret_cast<float4*>(&Qs[r][c4 * 4]) = uq;
            uk.x = napply(kv[it].x, ggk, ofk);
            uk.y = napply(kv[it].y, ggk, ofk);
            uk.z = napply(kv[it].z, ggk, ofk);
            uk.w = napply(kv[it].w, ggk, ofk);
            *reinterpret_cast<float4*>(&Ks[r][c4 * 4]) = uk;
        }
        __syncthreads();

#pragma unroll
        for (int ks = 0; ks < 4; ks++) {
            const int kk = ks * 8;
            uint32_t a[4][4], b[4][2];
#pragma unroll
            for (int mt = 0; mt < 4; mt++) {
                int tw = orow * 64 + mt * 16 + fg;
                a[mt][0] = __float_as_uint(Qs[tw][kk + ft]);
                a[mt][1] = __float_as_uint(Qs[tw + 8][kk + ft]);
                a[mt][2] = __float_as_uint(Qs[tw][kk + ft + 4]);
                a[mt][3] = __float_as_uint(Qs[tw + 8][kk + ft + 4]);
            }
#pragma unroll
            for (int nt = 0; nt < 4; nt++) {
                int sw = jcol * 32 + nt * 8 + fg;
                b[nt][0] = __float_as_uint(Ks[sw][kk + ft]);
                b[nt][1] = __float_as_uint(Ks[sw][kk + ft + 4]);
            }
#pragma unroll
            for (int mt = 0; mt < 4; mt++)
#pragma unroll
                for (int nt = 0; nt < 4; nt++)
                    mma_tf32(acc[mt][nt], a[mt], b[nt]);
        }
        __syncthreads();
    }

    const float scale = 0.011048543456039806f;   // 1/sqrt(8192)
    float* Sg = g_Sp + (size_t)c * 2097152 + (size_t)g * 262144;
#pragma unroll
    for (int mt = 0; mt < 4; mt++) {
        const int tl = t0 + orow * 64 + mt * 16 + fg;
#pragma unroll
        for (int nt = 0; nt < 4; nt++) {
            const int sl = s0 + jcol * 32 + nt * 8 + 2 * ft;
            *reinterpret_cast<float2*>(&Sg[(size_t)tl * 512 + sl]) =
                make_float2(acc[mt][nt][0] * scale, acc[mt][nt][1] * scale);
            *reinterpret_cast<float2*>(&Sg[(size_t)(tl + 8) * 512 + sl]) =
                make_float2(acc[mt][nt][2] * scale, acc[mt][nt][3] * scale);
        }
    }
}

// ---------------------------------------------------------------------------
// Row softmax over 512, fusing the split-K partial sum. 4096 blocks.
// ---------------------------------------------------------------------------
__global__ void __launch_bounds__(256) softmax_kernel()
{
    const size_t row = (size_t)blockIdx.x * 512;
    const int t = threadIdx.x;
    float a = 0.f, b = 0.f;
#pragma unroll
    for (int c = 0; c < 4; c++) {
        const float* p = g_Sp + (size_t)c * 2097152 + row;
        a += p[t]; b += p[t + 256];
    }
    __shared__ float sh[256];
    sh[t] = fmaxf(a, b);
    __syncthreads();
    for (int off = 128; off > 0; off >>= 1) {
        if (t < off) sh[t] = fmaxf(sh[t], sh[t + off]);
        __syncthreads();
    }
    float m = sh[0];
    __syncthreads();
    float e0 = __expf(a - m), e1 = __expf(b - m);
    sh[t] = e0 + e1;
    __syncthreads();
    for (int off = 128; off > 0; off >>= 1) {
        if (t < off) sh[t] += sh[t + off];
        __syncthreads();
    }
    float inv = 1.0f / sh[0];
    float* q = g_S + row;
    q[t] = e0 * inv;
    q[t + 256] = e1 * inv;
}

// ---------------------------------------------------------------------------
// PV via tf32 mma.sync, output-transposed: M=f(128), N=t(128), K=s(512).
// Zt[f][t] = sum_s V'[s][f] * P[t][s]  ->  Z[b][n*64+cn][f*512+t]
// Norm+PReLU at smem store (raw bits). grid (64 cn, 4 t-tiles, 8 groups).
// ---------------------------------------------------------------------------
__global__ void __launch_bounds__(256, 2) pv_mma_kernel(
    const float* __restrict__ gv, const float* __restrict__ betav)
{
    __shared__ __align__(16) float Vs[32][136];   // [s][f]
    __shared__ __align__(16) float Ps[128][36];   // [t][s]

    const int g = blockIdx.z;
    const int n = g & 3, bb = g >> 2;
    const float* P = g_S + (size_t)g * 262144;
    const int cn = blockIdx.x;
    const float* Vb = g_Y3 + 16ull * 4194304 + (size_t)g * 4194304 + (size_t)cn * 65536;
    const int t0 = blockIdx.y * 128;
    float* Zb = g_Z + ((size_t)bb * 256 + (size_t)(n * 64 + cn)) * 65536;

    const int tid = threadIdx.x;
    const int w = tid >> 5, l = tid & 31;
    const int fg = l >> 2, ft = l & 3;
    const int orow = w >> 2, jcol = w & 3;

    float2 stv = g_stats[16 + g];
    const float ggv = gv[n * 64 + cn] * stv.y;
    const float ofv = betav[n * 64 + cn] - stv.x * ggv;

    float acc[4][4][4];
#pragma unroll
    for (int mt = 0; mt < 4; mt++)
#pragma unroll
        for (int nt = 0; nt < 4; nt++)
#pragma unroll
            for (int i = 0; i < 4; i++) acc[mt][nt][i] = 0.f;

    for (int kc = 0; kc < 16; kc++) {
        float4 vv[4], pp[4];
#pragma unroll
        for (int it = 0; it < 4; it++) {
            int i4 = tid + it * 256;
            int vr = i4 >> 5, vc4 = i4 & 31;
            vv[it] = *reinterpret_cast<const float4*>(&Vb[(size_t)(kc * 32 + vr) * 128 + vc4 * 4]);
            int pr = i4 >> 3, pc4 = i4 & 7;
            pp[it] = *reinterpret_cast<const float4*>(&P[(size_t)(t0 + pr) * 512 + kc * 32 + pc4 * 4]);
        }
        __syncthreads();
#pragma unroll
        for (int it = 0; it < 4; it++) {
            int i4 = tid + it * 256;
            int vr = i4 >> 5, vc4 = i4 & 31;
            float4 u;
            u.x = napply(vv[it].x, ggv, ofv);
            u.y = napply(vv[it].y, ggv, ofv);
            u.z = napply(vv[it].z, ggv, ofv);
            u.w = napply(vv[it].w, ggv, ofv);
            *reinterpret_cast<float4*>(&Vs[vr][vc4 * 4]) = u;
            int pr = i4 >> 3, pc4 = i4 & 7;
            *reinterpret_cast<float4*>(&Ps[pr][pc4 * 4]) = pp[it];
        }
        __syncthreads();

#pragma unroll
        for (int ks = 0; ks < 4; ks++) {
            const int kk = ks * 8;
            uint32_t a[4][4], b[4][2];
#pragma unroll
            for (int mt = 0; mt < 4; mt++) {
                int fw = orow * 64 + mt * 16 + fg;
                a[mt][0] = __float_as_uint(Vs[kk + ft][fw]);
                a[mt][1] = __float_as_uint(Vs[kk + ft][fw + 8]);
                a[mt][2] = __float_as_uint(Vs[kk + ft + 4][fw]);
                a[mt][3] = __float_as_uint(Vs[kk + ft + 4][fw + 8]);
            }
#pragma unroll
            for (int nt = 0; nt < 4; nt++) {
                int tw = jcol * 32 + nt * 8 + fg;
                b[nt][0] = __float_as_uint(Ps[tw][kk + ft]);
                b[nt][1] = __float_as_uint(Ps[tw][kk + ft + 4]);
            }
#pragma unroll
            for (int mt = 0; mt < 4; mt++)
#pragma unroll
                for (int nt = 0; nt < 4; nt++)
                    mma_tf32(acc[mt][nt], a[mt], b[nt]);
        }
        __syncthreads();
    }

    // C: (m=f, n=t_local); c0/c1 consecutive t, c2/c3 at f+8
#pragma unroll
    for (int mt = 0; mt < 4; mt++) {
        const int f = orow * 64 + mt * 16 + fg;
#pragma unroll
        for (int nt = 0; nt < 4; nt++) {
            const int tt = t0 + jcol * 32 + nt * 8 + 2 * ft;
            *reinterpret_cast<float2*>(&Zb[(size_t)f * 512 + tt]) =
                make_float2(acc[mt][nt][0], acc[mt][nt][1]);
            *reinterpret_cast<float2*>(&Zb[(size_t)(f + 8) * 512 + tt]) =
                make_float2(acc[mt][nt][2], acc[mt][nt][3]);
        }
    }
}

// ---------------------------------------------------------------------------
// Final: out = PReLU(norm(Yp)*gp + betap) + x
// ---------------------------------------------------------------------------
__global__ void __launch_bounds__(256) apply_final_kernel(
    const float* __restrict__ x, const float* __restrict__ gp,
    const float* __restrict__ betap, const float2* __restrict__ stats2,
    float* __restrict__ out)
{
    size_t i = ((size_t)blockIdx.x * 256 + threadIdx.x) * 4;
    int r = (int)(i >> 16);
    int bidx = r >> 8;
    int o = r & 255;
    float2 st = stats2[bidx];
    float gg = gp[o] * st.y;
    float ofs = betap[o] - st.x * gg;
    float4 v  = *reinterpret_cast<const float4*>(&g_Yp[i]);
    float4 xr = *reinterpret_cast<const float4*>(&x[i]);
    v.x = fmaf(v.x, gg, ofs); v.x = ((v.x >= 0.f) ? v.x : 0.25f * v.x) + xr.x;
    v.y = fmaf(v.y, gg, ofs); v.y = ((v.y >= 0.f) ? v.y : 0.25f * v.y) + xr.y;
    v.z = fmaf(v.z, gg, ofs); v.z = ((v.z >= 0.f) ? v.z : 0.25f * v.z) + xr.z;
    v.w = fmaf(v.w, gg, ofs); v.w = ((v.w >= 0.f) ? v.w : 0.25f * v.w) + xr.w;
    *reinterpret_cast<float4*>(&out[i]) = v;
}

// ---------------------------------------------------------------------------
extern "C" void kernel_launch(void* const* d_in, const int* in_sizes, int n_in,
                              void* d_out, int out_size)
{
    const float* x     = (const float*)d_in[0];
    const float* Wq    = (const float*)d_in[1];
    const float* bq    = (const float*)d_in[2];
    const float* gq    = (const float*)d_in[3];
    const float* betaq = (const float*)d_in[4];
    const float* Wk    = (const float*)d_in[5];
    const float* bk    = (const float*)d_in[6];
    const float* gk    = (const float*)d_in[7];
    const float* betak = (const float*)d_in[8];
    const float* Wv    = (const float*)d_in[9];
    const float* bv    = (const float*)d_in[10];
    const float* gv    = (const float*)d_in[11];
    const float* betav = (const float*)d_in[12];
    const float* Wp    = (const float*)d_in[13];
    const float* bp    = (const float*)d_in[14];
    const float* gp    = (const float*)d_in[15];
    const float* betap = (const float*)d_in[16];

    float *Y3, *Z, *Yp;
    float2 *part, *stats;
    cudaGetSymbolAddress((void**)&Y3,   g_Y3);
    cudaGetSymbolAddress((void**)&Z,    g_Z);
    cudaGetSymbolAddress((void**)&Yp,   g_Yp);
    cudaGetSymbolAddress((void**)&part, g_part);
    cudaGetSymbolAddress((void**)&stats, g_stats);

    const int SM_CONV2 = 176128;   // (256*136 + 2*128*36) words * 4B
    cudaFuncSetAttribute(conv_mma2_kernel, cudaFuncAttributeMaxDynamicSharedMemorySize, SM_CONV2);

    // 1) QKV projections, X-resident (+ fused norm partials)
    conv_mma2_kernel<<<dim3(512, 2), 256, SM_CONV2>>>(x, Y3, Wq, Wk, Wv, bq, bk, bv, part, 3);
    // 2) finalize QKV GroupNorm stats: 24 groups x 512 partials
    reduce_final_kernel<<<24, 256>>>(part, stats, 512, 1.0f / 4194304.0f);
    // 3) S partials = scale * Q'K'^T  (mma.sync, split-K x4, norm fused)
    qk_mma_kernel<<<dim3(4, 4, 32), 256>>>(gq, betaq, gk, betak);
    // 4) softmax rows (fuses split-K reduction)
    softmax_kernel<<<4096, 256>>>();
    // 5) Vo = P V' (mma.sync, norm fused), permuted write into Z
    pv_mma_kernel<<<dim3(64, 4, 8), 256>>>(gv, betav);
    // 6) final projection, Z-resident (+ fused norm partials)
    conv_mma2_kernel<<<dim3(512, 2), 256, SM_CONV2>>>(Z, Yp, Wp, Wp, Wp, bp, bp, bp, part, 1);
    // 7) finalize per-sample stats: 2 groups x 2048 partials
    reduce_final_kernel<<<2, 256>>>(part, stats + 24, 2048, 1.0f / 16777216.0f);
    // 8) normalize + PReLU + residual
    apply_final_kernel<<<32768, 256>>>(x, gp, betap, stats + 24, (float*)d_out);
}

// round 11
// speedup vs baseline: 1.0999x; 1.0999x over previous
#include <cuda_runtime.h>
#include <cstdint>

// Problem constants: B=2, C=256, T=512, F=128, N=4 heads, H=CN=64, D=H*F=8192
#define TFsz 65536            // T*F
typedef unsigned long long u64;

// -------- scratch (device globals; no allocations allowed) --------
__device__ float g_Y3[100663296];   // [3][B][256][TF] Q,K,V (pre-norm)
__device__ float g_Sp[4194304];     // [2 kchunks][8 g][512][512] partial scores
__device__ float g_S[2097152];      // [8][512][512] attention probs
__device__ float g_Z[33554432];     // [B][256][TF] permuted attention output
__device__ float g_Yp[33554432];    // [B][256][TF] final conv output (pre-norm)
__device__ float2 g_part[12288];    // partial (sum, sumsq) from GEMM epilogues
__device__ float2 g_stats[32];      // (mu, rstd): [0..23] qkv groups, [24..25] final

// -------- PTX helpers (portable; no "a"-gated features) --------
__device__ __forceinline__ uint32_t smem_u32(const void* p) {
    uint32_t a;
    asm("{ .reg .u64 t; cvta.to.shared.u64 t, %1; cvt.u32.u64 %0, t; }" : "=r"(a) : "l"(p));
    return a;
}
#define CP16(dst, src) \
    asm volatile("cp.async.cg.shared.global [%0], [%1], 16;" :: "r"(dst), "l"(src))
#define CP_COMMIT() asm volatile("cp.async.commit_group;" ::: "memory")
#define CP_WAIT1()  asm volatile("cp.async.wait_group 1;" ::: "memory")
#define CP_WAIT0()  asm volatile("cp.async.wait_group 0;" ::: "memory")

// Raw fp32 bits into tf32 mma: tensor core reads the high 19 bits (truncation).
__device__ __forceinline__ void mma_tf32(float c[4], const uint32_t a[4], const uint32_t b[2]) {
    asm volatile(
        "mma.sync.aligned.m16n8k8.row.col.f32.tf32.tf32.f32 "
        "{%0,%1,%2,%3}, {%4,%5,%6,%7}, {%8,%9}, {%0,%1,%2,%3};"
        : "+f"(c[0]), "+f"(c[1]), "+f"(c[2]), "+f"(c[3])
        : "r"(a[0]), "r"(a[1]), "r"(a[2]), "r"(a[3]), "r"(b[0]), "r"(b[1]));
}
__device__ __forceinline__ float napply(float v, float gg, float of) {
    float y = fmaf(v, gg, of);
    return (y >= 0.f) ? y : 0.25f * y;
}

// ---------------------------------------------------------------------------
// tf32 mma.sync conv GEMM (cp.async double-buffered, raw fp32 operands):
//   Out[tens*2+b][o][j] = bias[o] + sum_c W[o][c] * X[b][c][j]
// Block 128(o) x 128(j), K-chunks of 32; 8 warps, each 4x4 m16n8k8.
// Dynamic smem (words): Ws[2][128*36] @0/4608, Xs[2][32*136] @9216/13568.
// Epilogue fuses bias + per-64-channel-group (sum,sumsq) partials.
// ---------------------------------------------------------------------------
__global__ void __launch_bounds__(256, 2) conv_mma_kernel(
    const float* __restrict__ X, float* __restrict__ Out,
    const float* __restrict__ W0, const float* __restrict__ W1, const float* __restrict__ W2,
    const float* __restrict__ b0_, const float* __restrict__ b1_, const float* __restrict__ b2_,
    float2* __restrict__ part)
{
    extern __shared__ __align__(16) uint32_t dsm[];
    const uint32_t sb = smem_u32(dsm);

    const int bb = blockIdx.z;
    const int y = blockIdx.y;
    const int tens = y >> 1;
    const int o0 = (y & 1) * 128;
    const int j0 = blockIdx.x * 128;
    const float* W    = (tens == 0) ? W0 : (tens == 1) ? W1 : W2;
    const float* bias = (tens == 0) ? b0_ : (tens == 1) ? b1_ : b2_;
    const float* Xb = X + (size_t)bb * (256 * (size_t)TFsz);
    float* O = Out + ((size_t)tens * 2 + bb) * (256 * (size_t)TFsz);

    const int tid = threadIdx.x;
    const int w = tid >> 5, l = tid & 31;
    const int g = l >> 2, t = l & 3;
    const int orow = w >> 2, jcol = w & 3;

    const int wrow0 = tid >> 3, wc4 = tid & 7;   // W copy coords (+it*32 rows)
    const int xr0 = tid >> 5, xc4 = tid & 31;    // X copy coords (+it*8 rows)

    float c[4][4][4];
#pragma unroll
    for (int mt = 0; mt < 4; mt++)
#pragma unroll
        for (int nt = 0; nt < 4; nt++)
#pragma unroll
            for (int i = 0; i < 4; i++) c[mt][nt][i] = 0.f;

#define CONV_ISSUE(KC, BUF) do {                                              \
    uint32_t wdst = sb + (BUF) * 18432;                                       \
    uint32_t xdst = sb + 36864 + (BUF) * 17408;                               \
    _Pragma("unroll")                                                         \
    for (int it = 0; it < 4; it++) {                                          \
        int row = wrow0 + it * 32;                                            \
        CP16(wdst + (row * 36 + wc4 * 4) * 4,                                 \
             &W[(size_t)(o0 + row) * 256 + (KC) * 32 + wc4 * 4]);             \
        int xr = xr0 + it * 8;                                                \
        CP16(xdst + (xr * 136 + xc4 * 4) * 4,                                 \
             &Xb[(size_t)((KC) * 32 + xr) * TFsz + j0 + xc4 * 4]);            \
    }                                                                         \
    CP_COMMIT();                                                              \
} while (0)

    CONV_ISSUE(0, 0);
    for (int kc = 0; kc < 8; kc++) {
        const int buf = kc & 1;
        if (kc < 7) { CONV_ISSUE(kc + 1, buf ^ 1); CP_WAIT1(); }
        else        { CP_WAIT0(); }
        __syncthreads();

        const uint32_t* Wsb = dsm + buf * 4608;
        const uint32_t* Xsb = dsm + 9216 + buf * 4352;
#pragma unroll
        for (int ks = 0; ks < 4; ks++) {
            const int kk = ks * 8;
            uint32_t a[4][4], b[4][2];
#pragma unroll
            for (int mt = 0; mt < 4; mt++) {
                int ow = orow * 64 + mt * 16 + g;
                a[mt][0] = Wsb[ow * 36 + kk + t];
                a[mt][1] = Wsb[(ow + 8) * 36 + kk + t];
                a[mt][2] = Wsb[ow * 36 + kk + t + 4];
                a[mt][3] = Wsb[(ow + 8) * 36 + kk + t + 4];
            }
#pragma unroll
            for (int nt = 0; nt < 4; nt++) {
                int jw = jcol * 32 + nt * 8 + g;
                b[nt][0] = Xsb[(kk + t) * 136 + jw];
                b[nt][1] = Xsb[(kk + t + 4) * 136 + jw];
            }
#pragma unroll
            for (int mt = 0; mt < 4; mt++)
#pragma unroll
                for (int nt = 0; nt < 4; nt++)
                    mma_tf32(c[mt][nt], a[mt], b[nt]);
        }
        __syncthreads();
    }
#undef CONV_ISSUE

    float bl[4], bh[4];
#pragma unroll
    for (int mt = 0; mt < 4; mt++) {
        bl[mt] = __ldg(&bias[o0 + orow * 64 + mt * 16 + g]);
        bh[mt] = __ldg(&bias[o0 + orow * 64 + mt * 16 + g + 8]);
    }
    float s = 0.f, sq = 0.f;
#pragma unroll
    for (int mt = 0; mt < 4; mt++) {
        const int o_lo = o0 + orow * 64 + mt * 16 + g;
#pragma unroll
        for (int nt = 0; nt < 4; nt++) {
            const int jj = j0 + jcol * 32 + nt * 8 + 2 * t;
            float v0 = c[mt][nt][0] + bl[mt];
            float v1 = c[mt][nt][1] + bl[mt];
            float v2 = c[mt][nt][2] + bh[mt];
            float v3 = c[mt][nt][3] + bh[mt];
            *reinterpret_cast<float2*>(&O[(size_t)o_lo * TFsz + jj]) = make_float2(v0, v1);
            *reinterpret_cast<float2*>(&O[(size_t)(o_lo + 8) * TFsz + jj]) = make_float2(v2, v3);
            s  += (v0 + v1) + (v2 + v3);
            sq += (v0 * v0 + v1 * v1) + (v2 * v2 + v3 * v3);
        }
    }

    __syncthreads();
    float* redS = reinterpret_cast<float*>(dsm);
    float* redQ = redS + 256;
    redS[tid] = s; redQ[tid] = sq;
    __syncthreads();
    const int r = tid & 127;
    for (int off = 64; off > 0; off >>= 1) {
        if (r < off) { redS[tid] += redS[tid + off]; redQ[tid] += redQ[tid + off]; }
        __syncthreads();
    }
    if (r == 0) {
        int og = (y & 1) * 2 + (tid >> 7);
        part[(((size_t)tens * 2 + bb) * 4 + og) * 512 + blockIdx.x] =
            make_float2(redS[tid], redQ[tid]);
    }
}

// ---------------------------------------------------------------------------
// Final reduction over `count` consecutive partials per group -> (mu, rstd)
// ---------------------------------------------------------------------------
__global__ void __launch_bounds__(256) reduce_final_kernel(
    const float2* __restrict__ part, float2* __restrict__ stats, int count, float inv_n)
{
    const int g = blockIdx.x;
    float s = 0.f, s2 = 0.f;
    for (int i = threadIdx.x; i < count; i += 256) {
        float2 v = part[(size_t)g * count + i];
        s += v.x; s2 += v.y;
    }
    __shared__ float sh[256], sh2[256];
    int t = threadIdx.x;
    sh[t] = s; sh2[t] = s2;
    __syncthreads();
    for (int off = 128; off > 0; off >>= 1) {
        if (t < off) { sh[t] += sh[t + off]; sh2[t] += sh2[t + off]; }
        __syncthreads();
    }
    if (t == 0) {
        float mu = sh[0] * inv_n;
        float var = fmaxf(sh2[0] * inv_n - mu * mu, 0.f);
        stats[g] = make_float2(mu, rsqrtf(var + 1e-6f));
    }
}

// ---------------------------------------------------------------------------
// QK via tf32 mma.sync (NT, split-K x2, 64-k chunks):
//   Sp[c][g][t][s] = scale * sum_{k in half} Q'(t,k) K'(s,k)
// grid (4 s-tiles, 4 t-tiles, 16 = g*2+c) = 256 blocks = ONE full wave.
// Dynamic smem (words): Qs[128][68] @0, Ks[128][68] @8704 (pitch 68 = 4 mod 32,
// conflict-free). Norm+PReLU at smem store (raw bits; mma truncates).
// ---------------------------------------------------------------------------
__global__ void __launch_bounds__(256, 2) qk_mma_kernel(
    const float* __restrict__ gq, const float* __restrict__ betaq,
    const float* __restrict__ gk, const float* __restrict__ betak)
{
    extern __shared__ __align__(16) uint32_t dsm[];
    float* Qs = reinterpret_cast<float*>(dsm);          // [128][68]
    float* Ks = reinterpret_cast<float*>(dsm + 8704);   // [128][68]
    __shared__ float sgg[2][64], sof[2][64];

    const int z = blockIdx.z;
    const int g = z >> 1, c = z & 1;
    const int n = g & 3;
    const float* Q  = g_Y3 + (size_t)g * 4194304;
    const float* Km = g_Y3 + 8ull * 4194304 + (size_t)g * 4194304;
    const int t0 = blockIdx.y * 128, s0 = blockIdx.x * 128;
    const int tid = threadIdx.x;
    const int w = tid >> 5, l = tid & 31;
    const int fg = l >> 2, ft = l & 3;
    const int orow = w >> 2, jcol = w & 3;

    if (tid < 128) {
        int which = tid >> 6, h = tid & 63, o = n * 64 + h;
        float2 st = g_stats[which * 8 + g];
        const float* gw = which ? gk : gq;
        const float* bw = which ? betak : betaq;
        float gg = gw[o] * st.y;
        sgg[which][h] = gg;
        sof[which][h] = bw[o] - st.x * gg;
    }
    __syncthreads();

    float acc[4][4][4];
#pragma unroll
    for (int mt = 0; mt < 4; mt++)
#pragma unroll
        for (int nt = 0; nt < 4; nt++)
#pragma unroll
            for (int i = 0; i < 4; i++) acc[mt][nt][i] = 0.f;

    for (int kc = 0; kc < 64; kc++) {
        const int k0 = c * 4096 + kc * 64;      // 64-k chunk, within one h
        const int h = k0 >> 7;
        const size_t hb = (size_t)h * 65536 + (size_t)(k0 & 127);
        const float ggq = sgg[0][h], ofq = sof[0][h];
        const float ggk = sgg[1][h], ofk = sof[1][h];
        float4 qv[8], kv[8];
#pragma unroll
        for (int it = 0; it < 8; it++) {
            int i4 = tid + it * 256;
            int r = i4 >> 4, c4 = i4 & 15;
            qv[it] = *reinterpret_cast<const float4*>(&Q[hb + (size_t)(t0 + r) * 128 + c4 * 4]);
            kv[it] = *reinterpret_cast<const float4*>(&Km[hb + (size_t)(s0 + r) * 128 + c4 * 4]);
        }
        __syncthreads();
#pragma unroll
        for (int it = 0; it < 8; it++) {
            int i4 = tid + it * 256;
            int r = i4 >> 4, c4 = i4 & 15;
            float4 uq, uk;
            uq.x = napply(qv[it].x, ggq, ofq);
            uq.y = napply(qv[it].y, ggq, ofq);
            uq.z = napply(qv[it].z, ggq, ofq);
            uq.w = napply(qv[it].w, ggq, ofq);
            *reinterpret_cast<float4*>(&Qs[r * 68 + c4 * 4]) = uq;
            uk.x = napply(kv[it].x, ggk, ofk);
            uk.y = napply(kv[it].y, ggk, ofk);
            uk.z = napply(kv[it].z, ggk, ofk);
            uk.w = napply(kv[it].w, ggk, ofk);
            *reinterpret_cast<float4*>(&Ks[r * 68 + c4 * 4]) = uk;
        }
        __syncthreads();

#pragma unroll
        for (int ks = 0; ks < 8; ks++) {
            const int kk = ks * 8;
            uint32_t a[4][4], b[4][2];
#pragma unroll
            for (int mt = 0; mt < 4; mt++) {
                int tw = orow * 64 + mt * 16 + fg;
                a[mt][0] = __float_as_uint(Qs[tw * 68 + kk + ft]);
                a[mt][1] = __float_as_uint(Qs[(tw + 8) * 68 + kk + ft]);
                a[mt][2] = __float_as_uint(Qs[tw * 68 + kk + ft + 4]);
                a[mt][3] = __float_as_uint(Qs[(tw + 8) * 68 + kk + ft + 4]);
            }
#pragma unroll
            for (int nt = 0; nt < 4; nt++) {
                int sw = jcol * 32 + nt * 8 + fg;
                b[nt][0] = __float_as_uint(Ks[sw * 68 + kk + ft]);
                b[nt][1] = __float_as_uint(Ks[sw * 68 + kk + ft + 4]);
            }
#pragma unroll
            for (int mt = 0; mt < 4; mt++)
#pragma unroll
                for (int nt = 0; nt < 4; nt++)
                    mma_tf32(acc[mt][nt], a[mt], b[nt]);
        }
        __syncthreads();
    }

    const float scale = 0.011048543456039806f;   // 1/sqrt(8192)
    float* Sg = g_Sp + (size_t)c * 2097152 + (size_t)g * 262144;
#pragma unroll
    for (int mt = 0; mt < 4; mt++) {
        const int tl = t0 + orow * 64 + mt * 16 + fg;
#pragma unroll
        for (int nt = 0; nt < 4; nt++) {
            const int sl = s0 + jcol * 32 + nt * 8 + 2 * ft;
            *reinterpret_cast<float2*>(&Sg[(size_t)tl * 512 + sl]) =
                make_float2(acc[mt][nt][0] * scale, acc[mt][nt][1] * scale);
            *reinterpret_cast<float2*>(&Sg[(size_t)(tl + 8) * 512 + sl]) =
                make_float2(acc[mt][nt][2] * scale, acc[mt][nt][3] * scale);
        }
    }
}

// ---------------------------------------------------------------------------
// Row softmax over 512, fusing the split-K (x2) partial sum. 4096 blocks.
// ---------------------------------------------------------------------------
__global__ void __launch_bounds__(256) softmax_kernel()
{
    const size_t row = (size_t)blockIdx.x * 512;
    const int t = threadIdx.x;
    float a = 0.f, b = 0.f;
#pragma unroll
    for (int c = 0; c < 2; c++) {
        const float* p = g_Sp + (size_t)c * 2097152 + row;
        a += p[t]; b += p[t + 256];
    }
    __shared__ float sh[256];
    sh[t] = fmaxf(a, b);
    __syncthreads();
    for (int off = 128; off > 0; off >>= 1) {
        if (t < off) sh[t] = fmaxf(sh[t], sh[t + off]);
        __syncthreads();
    }
    float m = sh[0];
    __syncthreads();
    float e0 = __expf(a - m), e1 = __expf(b - m);
    sh[t] = e0 + e1;
    __syncthreads();
    for (int off = 128; off > 0; off >>= 1) {
        if (t < off) sh[t] += sh[t + off];
        __syncthreads();
    }
    float inv = 1.0f / sh[0];
    float* q = g_S + row;
    q[t] = e0 * inv;
    q[t + 256] = e1 * inv;
}

// ---------------------------------------------------------------------------
// PV via tf32 mma.sync, output-transposed: M=f(128), N=t(128), K=s(512).
// Zt[f][t] = sum_s V'[s][f] * P[t][s]  ->  Z[b][n*64+cn][f*512+t]
// Norm+PReLU at smem store (raw bits). grid (64 cn, 4 t-tiles, 8 groups).
// ---------------------------------------------------------------------------
__global__ void __launch_bounds__(256, 2) pv_mma_kernel(
    const float* __restrict__ gv, const float* __restrict__ betav)
{
    __shared__ __align__(16) float Vs[32][136];   // [s][f]
    __shared__ __align__(16) float Ps[128][36];   // [t][s]

    const int g = blockIdx.z;
    const int n = g & 3, bb = g >> 2;
    const float* P = g_S + (size_t)g * 262144;
    const int cn = blockIdx.x;
    const float* Vb = g_Y3 + 16ull * 4194304 + (size_t)g * 4194304 + (size_t)cn * 65536;
    const int t0 = blockIdx.y * 128;
    float* Zb = g_Z + ((size_t)bb * 256 + (size_t)(n * 64 + cn)) * 65536;

    const int tid = threadIdx.x;
    const int w = tid >> 5, l = tid & 31;
    const int fg = l >> 2, ft = l & 3;
    const int orow = w >> 2, jcol = w & 3;

    float2 stv = g_stats[16 + g];
    const float ggv = gv[n * 64 + cn] * stv.y;
    const float ofv = betav[n * 64 + cn] - stv.x * ggv;

    float acc[4][4][4];
#pragma unroll
    for (int mt = 0; mt < 4; mt++)
#pragma unroll
        for (int nt = 0; nt < 4; nt++)
#pragma unroll
            for (int i = 0; i < 4; i++) acc[mt][nt][i] = 0.f;

    for (int kc = 0; kc < 16; kc++) {
        float4 vv[4], pp[4];
#pragma unroll
        for (int it = 0; it < 4; it++) {
            int i4 = tid + it * 256;
            int vr = i4 >> 5, vc4 = i4 & 31;
            vv[it] = *reinterpret_cast<const float4*>(&Vb[(size_t)(kc * 32 + vr) * 128 + vc4 * 4]);
            int pr = i4 >> 3, pc4 = i4 & 7;
            pp[it] = *reinterpret_cast<const float4*>(&P[(size_t)(t0 + pr) * 512 + kc * 32 + pc4 * 4]);
        }
        __syncthreads();
#pragma unroll
        for (int it = 0; it < 4; it++) {
            int i4 = tid + it * 256;
            int vr = i4 >> 5, vc4 = i4 & 31;
            float4 u;
            u.x = napply(vv[it].x, ggv, ofv);
            u.y = napply(vv[it].y, ggv, ofv);
            u.z = napply(vv[it].z, ggv, ofv);
            u.w = napply(vv[it].w, ggv, ofv);
            *reinterpret_cast<float4*>(&Vs[vr][vc4 * 4]) = u;
            int pr = i4 >> 3, pc4 = i4 & 7;
            *reinterpret_cast<float4*>(&Ps[pr][pc4 * 4]) = pp[it];
        }
        __syncthreads();

#pragma unroll
        for (int ks = 0; ks < 4; ks++) {
            const int kk = ks * 8;
            uint32_t a[4][4], b[4][2];
#pragma unroll
            for (int mt = 0; mt < 4; mt++) {
                int fw = orow * 64 + mt * 16 + fg;
                a[mt][0] = __float_as_uint(Vs[kk + ft][fw]);
                a[mt][1] = __float_as_uint(Vs[kk + ft][fw + 8]);
                a[mt][2] = __float_as_uint(Vs[kk + ft + 4][fw]);
                a[mt][3] = __float_as_uint(Vs[kk + ft + 4][fw + 8]);
            }
#pragma unroll
            for (int nt = 0; nt < 4; nt++) {
                int tw = jcol * 32 + nt * 8 + fg;
                b[nt][0] = __float_as_uint(Ps[tw][kk + ft]);
                b[nt][1] = __float_as_uint(Ps[tw][kk + ft + 4]);
            }
#pragma unroll
            for (int mt = 0; mt < 4; mt++)
#pragma unroll
                for (int nt = 0; nt < 4; nt++)
                    mma_tf32(acc[mt][nt], a[mt], b[nt]);
        }
        __syncthreads();
    }

    // C: (m=f, n=t_local); c0/c1 consecutive t, c2/c3 at f+8
#pragma unroll
    for (int mt = 0; mt < 4; mt++) {
        const int f = orow * 64 + mt * 16 + fg;
#pragma unroll
        for (int nt = 0; nt < 4; nt++) {
            const int tt = t0 + jcol * 32 + nt * 8 + 2 * ft;
            *reinterpret_cast<float2*>(&Zb[(size_t)f * 512 + tt]) =
                make_float2(acc[mt][nt][0], acc[mt][nt][1]);
            *reinterpret_cast<float2*>(&Zb[(size_t)(f + 8) * 512 + tt]) =
                make_float2(acc[mt][nt][2], acc[mt][nt][3]);
        }
    }
}

// ---------------------------------------------------------------------------
// Final: out = PReLU(norm(Yp)*gp + betap) + x
// ---------------------------------------------------------------------------
__global__ void __launch_bounds__(256) apply_final_kernel(
    const float* __restrict__ x, const float* __restrict__ gp,
    const float* __restrict__ betap, const float2* __restrict__ stats2,
    float* __restrict__ out)
{
    size_t i = ((size_t)blockIdx.x * 256 + threadIdx.x) * 4;
    int r = (int)(i >> 16);
    int bidx = r >> 8;
    int o = r & 255;
    float2 st = stats2[bidx];
    float gg = gp[o] * st.y;
    float ofs = betap[o] - st.x * gg;
    float4 v  = *reinterpret_cast<const float4*>(&g_Yp[i]);
    float4 xr = *reinterpret_cast<const float4*>(&x[i]);
    v.x = fmaf(v.x, gg, ofs); v.x = ((v.x >= 0.f) ? v.x : 0.25f * v.x) + xr.x;
    v.y = fmaf(v.y, gg, ofs); v.y = ((v.y >= 0.f) ? v.y : 0.25f * v.y) + xr.y;
    v.z = fmaf(v.z, gg, ofs); v.z = ((v.z >= 0.f) ? v.z : 0.25f * v.z) + xr.z;
    v.w = fmaf(v.w, gg, ofs); v.w = ((v.w >= 0.f) ? v.w : 0.25f * v.w) + xr.w;
    *reinterpret_cast<float4*>(&out[i]) = v;
}

// ---------------------------------------------------------------------------
extern "C" void kernel_launch(void* const* d_in, const int* in_sizes, int n_in,
                              void* d_out, int out_size)
{
    const float* x     = (const float*)d_in[0];
    const float* Wq    = (const float*)d_in[1];
    const float* bq    = (const float*)d_in[2];
    const float* gq    = (const float*)d_in[3];
    const float* betaq = (const float*)d_in[4];
    const float* Wk    = (const float*)d_in[5];
    const float* bk    = (const float*)d_in[6];
    const float* gk    = (const float*)d_in[7];
    const float* betak = (const float*)d_in[8];
    const float* Wv    = (const float*)d_in[9];
    const float* bv    = (const float*)d_in[10];
    const float* gv    = (const float*)d_in[11];
    const float* betav = (const float*)d_in[12];
    const float* Wp    = (const float*)d_in[13];
    const float* bp    = (const float*)d_in[14];
    const float* gp    = (const float*)d_in[15];
    const float* betap = (const float*)d_in[16];

    float *Y3, *Z, *Yp;
    float2 *part, *stats;
    cudaGetSymbolAddress((void**)&Y3,   g_Y3);
    cudaGetSymbolAddress((void**)&Z,    g_Z);
    cudaGetSymbolAddress((void**)&Yp,   g_Yp);
    cudaGetSymbolAddress((void**)&part, g_part);
    cudaGetSymbolAddress((void**)&stats, g_stats);

    const int SM_CONV = 71680;   // 2*(128*36 + 32*136) words * 4B
    const int SM_QK   = 69632;   // 2*(128*68) words * 4B
    cudaFuncSetAttribute(conv_mma_kernel, cudaFuncAttributeMaxDynamicSharedMemorySize, SM_CONV);
    cudaFuncSetAttribute(qk_mma_kernel,   cudaFuncAttributeMaxDynamicSharedMemorySize, SM_QK);

    // 1) QKV projections via tf32 mma.sync (cp.async, + fused norm partials)
    conv_mma_kernel<<<dim3(512, 6, 2), 256, SM_CONV>>>(x, Y3, Wq, Wk, Wv, bq, bk, bv, part);
    // 2) finalize QKV GroupNorm stats: 24 groups x 512 partials
    reduce_final_kernel<<<24, 256>>>(part, stats, 512, 1.0f / 4194304.0f);
    // 3) S partials = scale * Q'K'^T  (split-K x2, 256 blocks = one wave)
    qk_mma_kernel<<<dim3(4, 4, 16), 256, SM_QK>>>(gq, betaq, gk, betak);
    // 4) softmax rows (fuses split-K x2 reduction)
    softmax_kernel<<<4096, 256>>>();
    // 5) Vo = P V' (mma.sync, norm fused), permuted write into Z
    pv_mma_kernel<<<dim3(64, 4, 8), 256>>>(gv, betav);
    // 6) final projection via tf32 mma.sync (cp.async, + fused norm partials)
    conv_mma_kernel<<<dim3(512, 2, 2), 256, SM_CONV>>>(Z, Yp, Wp, Wp, Wp, bp, bp, bp, part);
    // 7) finalize per-sample stats: 2 groups x 2048 partials
    reduce_final_kernel<<<2, 256>>>(part, stats + 24, 2048, 1.0f / 16777216.0f);
    // 8) normalize + PReLU + residual
    apply_final_kernel<<<32768, 256>>>(x, gp, betap, stats + 24, (float*)d_out);
}

// round 12
// speedup vs baseline: 1.1036x; 1.0034x over previous
#include <cuda_runtime.h>
#include <cstdint>

// Problem constants: B=2, C=256, T=512, F=128, N=4 heads, H=CN=64, D=H*F=8192
#define TFsz 65536            // T*F
typedef unsigned long long u64;

// -------- scratch (device globals; no allocations allowed) --------
__device__ float g_Y3[100663296];   // [3][B][256][TF] Q,K,V (pre-norm)
__device__ float g_Sp[4194304];     // [2 kchunks][8 g][512][512] partial scores
__device__ float g_S[2097152];      // [8][512][512] attention probs
__device__ float g_Z[33554432];     // [B][256][TF] permuted attention output
__device__ float g_Yp[33554432];    // [B][256][TF] final conv output (pre-norm)
__device__ float2 g_part[12288];    // partial (sum, sumsq) from GEMM epilogues
__device__ float2 g_stats[32];      // (mu, rstd): [0..23] qkv groups, [24..25] final

// -------- PTX helpers (portable; no "a"-gated features) --------
__device__ __forceinline__ uint32_t smem_u32(const void* p) {
    uint32_t a;
    asm("{ .reg .u64 t; cvta.to.shared.u64 t, %1; cvt.u32.u64 %0, t; }" : "=r"(a) : "l"(p));
    return a;
}
#define CP16(dst, src) \
    asm volatile("cp.async.cg.shared.global [%0], [%1], 16;" :: "r"(dst), "l"(src))
#define CP_COMMIT() asm volatile("cp.async.commit_group;" ::: "memory")
#define CP_WAIT1()  asm volatile("cp.async.wait_group 1;" ::: "memory")
#define CP_WAIT0()  asm volatile("cp.async.wait_group 0;" ::: "memory")

// Raw fp32 bits into tf32 mma: tensor core reads the high 19 bits (truncation).
__device__ __forceinline__ void mma_tf32(float c[4], const uint32_t a[4], const uint32_t b[2]) {
    asm volatile(
        "mma.sync.aligned.m16n8k8.row.col.f32.tf32.tf32.f32 "
        "{%0,%1,%2,%3}, {%4,%5,%6,%7}, {%8,%9}, {%0,%1,%2,%3};"
        : "+f"(c[0]), "+f"(c[1]), "+f"(c[2]), "+f"(c[3])
        : "r"(a[0]), "r"(a[1]), "r"(a[2]), "r"(a[3]), "r"(b[0]), "r"(b[1]));
}
__device__ __forceinline__ float napply(float v, float gg, float of) {
    float y = fmaf(v, gg, of);
    return (y >= 0.f) ? y : 0.25f * y;
}

// ---------------------------------------------------------------------------
// tf32 mma.sync conv GEMM (cp.async 3-buffer prefetch-2, ONE sync per chunk):
//   Out[tens*2+b][o][j] = bias[o] + sum_c W[o][c] * X[b][c][j]
// Block 128(o) x 128(j), K-chunks of 32; 8 warps, each 4x4 m16n8k8.
// Dynamic smem (words): Ws[3][128*36] @0/4608/9216, Xs[3][32*136] @13824+.
// Per iter kc: wait(group kc) -> sync -> issue(kc+2 into (kc+2)%3) -> mma.
// Issue-after-sync is safe: buffer (kc+2)%3 was last read at mma(kc-1),
// and every warp passed this iter's sync after finishing mma(kc-1).
// Epilogue fuses bias + per-64-channel-group (sum,sumsq) partials.
// ---------------------------------------------------------------------------
__global__ void __launch_bounds__(256, 2) conv_mma_kernel(
    const float* __restrict__ X, float* __restrict__ Out,
    const float* __restrict__ W0, const float* __restrict__ W1, const float* __restrict__ W2,
    const float* __restrict__ b0_, const float* __restrict__ b1_, const float* __restrict__ b2_,
    float2* __restrict__ part)
{
    extern __shared__ __align__(16) uint32_t dsm[];
    const uint32_t sb = smem_u32(dsm);

    const int bb = blockIdx.z;
    const int y = blockIdx.y;
    const int tens = y >> 1;
    const int o0 = (y & 1) * 128;
    const int j0 = blockIdx.x * 128;
    const float* W    = (tens == 0) ? W0 : (tens == 1) ? W1 : W2;
    const float* bias = (tens == 0) ? b0_ : (tens == 1) ? b1_ : b2_;
    const float* Xb = X + (size_t)bb * (256 * (size_t)TFsz);
    float* O = Out + ((size_t)tens * 2 + bb) * (256 * (size_t)TFsz);

    const int tid = threadIdx.x;
    const int w = tid >> 5, l = tid & 31;
    const int g = l >> 2, t = l & 3;
    const int orow = w >> 2, jcol = w & 3;

    const int wrow0 = tid >> 3, wc4 = tid & 7;   // W copy coords (+it*32 rows)
    const int xr0 = tid >> 5, xc4 = tid & 31;    // X copy coords (+it*8 rows)

    float c[4][4][4];
#pragma unroll
    for (int mt = 0; mt < 4; mt++)
#pragma unroll
        for (int nt = 0; nt < 4; nt++)
#pragma unroll
            for (int i = 0; i < 4; i++) c[mt][nt][i] = 0.f;

#define CONV_ISSUE(KC, BUF) do {                                              \
    uint32_t wdst = sb + (BUF) * 18432;                                       \
    uint32_t xdst = sb + 55296 + (BUF) * 17408;                               \
    _Pragma("unroll")                                                         \
    for (int it = 0; it < 4; it++) {                                          \
        int row = wrow0 + it * 32;                                            \
        CP16(wdst + (row * 36 + wc4 * 4) * 4,                                 \
             &W[(size_t)(o0 + row) * 256 + (KC) * 32 + wc4 * 4]);             \
        int xr = xr0 + it * 8;                                                \
        CP16(xdst + (xr * 136 + xc4 * 4) * 4,                                 \
             &Xb[(size_t)((KC) * 32 + xr) * TFsz + j0 + xc4 * 4]);            \
    }                                                                         \
    CP_COMMIT();                                                              \
} while (0)

    CONV_ISSUE(0, 0);
    CONV_ISSUE(1, 1);
    for (int kc = 0; kc < 8; kc++) {
        const int buf = kc % 3;
        if (kc < 7) CP_WAIT1();    // group kc arrived (kc+1 may stay pending)
        else        CP_WAIT0();
        __syncthreads();
        if (kc + 2 < 8) CONV_ISSUE(kc + 2, (kc + 2) % 3);

        const uint32_t* Wsb = dsm + buf * 4608;
        const uint32_t* Xsb = dsm + 13824 + buf * 4352;
#pragma unroll
        for (int ks = 0; ks < 4; ks++) {
            const int kk = ks * 8;
            uint32_t a[4][4], b[4][2];
#pragma unroll
            for (int mt = 0; mt < 4; mt++) {
                int ow = orow * 64 + mt * 16 + g;
                a[mt][0] = Wsb[ow * 36 + kk + t];
                a[mt][1] = Wsb[(ow + 8) * 36 + kk + t];
                a[mt][2] = Wsb[ow * 36 + kk + t + 4];
                a[mt][3] = Wsb[(ow + 8) * 36 + kk + t + 4];
            }
#pragma unroll
            for (int nt = 0; nt < 4; nt++) {
                int jw = jcol * 32 + nt * 8 + g;
                b[nt][0] = Xsb[(kk + t) * 136 + jw];
                b[nt][1] = Xsb[(kk + t + 4) * 136 + jw];
            }
#pragma unroll
            for (int mt = 0; mt < 4; mt++)
#pragma unroll
                for (int nt = 0; nt < 4; nt++)
                    mma_tf32(c[mt][nt], a[mt], b[nt]);
        }
    }
#undef CONV_ISSUE

    float bl[4], bh[4];
#pragma unroll
    for (int mt = 0; mt < 4; mt++) {
        bl[mt] = __ldg(&bias[o0 + orow * 64 + mt * 16 + g]);
        bh[mt] = __ldg(&bias[o0 + orow * 64 + mt * 16 + g + 8]);
    }
    float s = 0.f, sq = 0.f;
#pragma unroll
    for (int mt = 0; mt < 4; mt++) {
        const int o_lo = o0 + orow * 64 + mt * 16 + g;
#pragma unroll
        for (int nt = 0; nt < 4; nt++) {
            const int jj = j0 + jcol * 32 + nt * 8 + 2 * t;
            float v0 = c[mt][nt][0] + bl[mt];
            float v1 = c[mt][nt][1] + bl[mt];
            float v2 = c[mt][nt][2] + bh[mt];
            float v3 = c[mt][nt][3] + bh[mt];
            *reinterpret_cast<float2*>(&O[(size_t)o_lo * TFsz + jj]) = make_float2(v0, v1);
            *reinterpret_cast<float2*>(&O[(size_t)(o_lo + 8) * TFsz + jj]) = make_float2(v2, v3);
            s  += (v0 + v1) + (v2 + v3);
            sq += (v0 * v0 + v1 * v1) + (v2 * v2 + v3 * v3);
        }
    }

    __syncthreads();   // all mma reads done before dsm reuse
    float* redS = reinterpret_cast<float*>(dsm);
    float* redQ = redS + 256;
    redS[tid] = s; redQ[tid] = sq;
    __syncthreads();
    const int r = tid & 127;
    for (int off = 64; off > 0; off >>= 1) {
        if (r < off) { redS[tid] += redS[tid + off]; redQ[tid] += redQ[tid + off]; }
        __syncthreads();
    }
    if (r == 0) {
        int og = (y & 1) * 2 + (tid >> 7);
        part[(((size_t)tens * 2 + bb) * 4 + og) * 512 + blockIdx.x] =
            make_float2(redS[tid], redQ[tid]);
    }
}

// ---------------------------------------------------------------------------
// Final reduction over `count` consecutive partials per group -> (mu, rstd)
// ---------------------------------------------------------------------------
__global__ void __launch_bounds__(256) reduce_final_kernel(
    const float2* __restrict__ part, float2* __restrict__ stats, int count, float inv_n)
{
    const int g = blockIdx.x;
    float s = 0.f, s2 = 0.f;
    for (int i = threadIdx.x; i < count; i += 256) {
        float2 v = part[(size_t)g * count + i];
        s += v.x; s2 += v.y;
    }
    __shared__ float sh[256], sh2[256];
    int t = threadIdx.x;
    sh[t] = s; sh2[t] = s2;
    __syncthreads();
    for (int off = 128; off > 0; off >>= 1) {
        if (t < off) { sh[t] += sh[t + off]; sh2[t] += sh2[t + off]; }
        __syncthreads();
    }
    if (t == 0) {
        float mu = sh[0] * inv_n;
        float var = fmaxf(sh2[0] * inv_n - mu * mu, 0.f);
        stats[g] = make_float2(mu, rsqrtf(var + 1e-6f));
    }
}

// ---------------------------------------------------------------------------
// QK via tf32 mma.sync (NT, split-K x2, 64-k chunks):
//   Sp[c][g][t][s] = scale * sum_{k in half} Q'(t,k) K'(s,k)
// grid (4 s-tiles, 4 t-tiles, 16 = g*2+c) = 256 blocks = ONE full wave.
// Dynamic smem (words): Qs[128][68] @0, Ks[128][68] @8704 (pitch 68 = 4 mod 32,
// conflict-free). Norm+PReLU at smem store (raw bits; mma truncates).
// ---------------------------------------------------------------------------
__global__ void __launch_bounds__(256, 2) qk_mma_kernel(
    const float* __restrict__ gq, const float* __restrict__ betaq,
    const float* __restrict__ gk, const float* __restrict__ betak)
{
    extern __shared__ __align__(16) uint32_t dsm[];
    float* Qs = reinterpret_cast<float*>(dsm);          // [128][68]
    float* Ks = reinterpret_cast<float*>(dsm + 8704);   // [128][68]
    __shared__ float sgg[2][64], sof[2][64];

    const int z = blockIdx.z;
    const int g = z >> 1, c = z & 1;
    const int n = g & 3;
    const float* Q  = g_Y3 + (size_t)g * 4194304;
    const float* Km = g_Y3 + 8ull * 4194304 + (size_t)g * 4194304;
    const int t0 = blockIdx.y * 128, s0 = blockIdx.x * 128;
    const int tid = threadIdx.x;
    const int w = tid >> 5, l = tid & 31;
    const int fg = l >> 2, ft = l & 3;
    const int orow = w >> 2, jcol = w & 3;

    if (tid < 128) {
        int which = tid >> 6, h = tid & 63, o = n * 64 + h;
        float2 st = g_stats[which * 8 + g];
        const float* gw = which ? gk : gq;
        const float* bw = which ? betak : betaq;
        float gg = gw[o] * st.y;
        sgg[which][h] = gg;
        sof[which][h] = bw[o] - st.x * gg;
    }
    __syncthreads();

    float acc[4][4][4];
#pragma unroll
    for (int mt = 0; mt < 4; mt++)
#pragma unroll
        for (int nt = 0; nt < 4; nt++)
#pragma unroll
            for (int i = 0; i < 4; i++) acc[mt][nt][i] = 0.f;

    for (int kc = 0; kc < 64; kc++) {
        const int k0 = c * 4096 + kc * 64;      // 64-k chunk, within one h
        const int h = k0 >> 7;
        const size_t hb = (size_t)h * 65536 + (size_t)(k0 & 127);
        const float ggq = sgg[0][h], ofq = sof[0][h];
        const float ggk = sgg[1][h], ofk = sof[1][h];
        float4 qv[8], kv[8];
#pragma unroll
        for (int it = 0; it < 8; it++) {
            int i4 = tid + it * 256;
            int r = i4 >> 4, c4 = i4 & 15;
            qv[it] = *reinterpret_cast<const float4*>(&Q[hb + (size_t)(t0 + r) * 128 + c4 * 4]);
            kv[it] = *reinterpret_cast<const float4*>(&Km[hb + (size_t)(s0 + r) * 128 + c4 * 4]);
        }
        __syncthreads();
#pragma unroll
        for (int it = 0; it < 8; it++) {
            int i4 = tid + it * 256;
            int r = i4 >> 4, c4 = i4 & 15;
            float4 uq, uk;
            uq.x = napply(qv[it].x, ggq, ofq);
            uq.y = napply(qv[it].y, ggq, ofq);
            uq.z = napply(qv[it].z, ggq, ofq);
            uq.w = napply(qv[it].w, ggq, ofq);
            *reinterpret_cast<float4*>(&Qs[r * 68 + c4 * 4]) = uq;
            uk.x = napply(kv[it].x, ggk, ofk);
            uk.y = napply(kv[it].y, ggk, ofk);
            uk.z = napply(kv[it].z, ggk, ofk);
            uk.w = napply(kv[it].w, ggk, ofk);
            *reinterpret_cast<float4*>(&Ks[r * 68 + c4 * 4]) = uk;
        }
        __syncthreads();

#pragma unroll
        for (int ks = 0; ks < 8; ks++) {
            const int kk = ks * 8;
            uint32_t a[4][4], b[4][2];
#pragma unroll
            for (int mt = 0; mt < 4; mt++) {
                int tw = orow * 64 + mt * 16 + fg;
                a[mt][0] = __float_as_uint(Qs[tw * 68 + kk + ft]);
                a[mt][1] = __float_as_uint(Qs[(tw + 8) * 68 + kk + ft]);
                a[mt][2] = __float_as_uint(Qs[tw * 68 + kk + ft + 4]);
                a[mt][3] = __float_as_uint(Qs[(tw + 8) * 68 + kk + ft + 4]);
            }
#pragma unroll
            for (int nt = 0; nt < 4; nt++) {
                int sw = jcol * 32 + nt * 8 + fg;
                b[nt][0] = __float_as_uint(Ks[sw * 68 + kk + ft]);
                b[nt][1] = __float_as_uint(Ks[sw * 68 + kk + ft + 4]);
            }
#pragma unroll
            for (int mt = 0; mt < 4; mt++)
#pragma unroll
                for (int nt = 0; nt < 4; nt++)
                    mma_tf32(acc[mt][nt], a[mt], b[nt]);
        }
        __syncthreads();
    }

    const float scale = 0.011048543456039806f;   // 1/sqrt(8192)
    float* Sg = g_Sp + (size_t)c * 2097152 + (size_t)g * 262144;
#pragma unroll
    for (int mt = 0; mt < 4; mt++) {
        const int tl = t0 + orow * 64 + mt * 16 + fg;
#pragma unroll
        for (int nt = 0; nt < 4; nt++) {
            const int sl = s0 + jcol * 32 + nt * 8 + 2 * ft;
            *reinterpret_cast<float2*>(&Sg[(size_t)tl * 512 + sl]) =
                make_float2(acc[mt][nt][0] * scale, acc[mt][nt][1] * scale);
            *reinterpret_cast<float2*>(&Sg[(size_t)(tl + 8) * 512 + sl]) =
                make_float2(acc[mt][nt][2] * scale, acc[mt][nt][3] * scale);
        }
    }
}

// ---------------------------------------------------------------------------
// Row softmax over 512, fusing the split-K (x2) partial sum. 4096 blocks.
// ---------------------------------------------------------------------------
__global__ void __launch_bounds__(256) softmax_kernel()
{
    const size_t row = (size_t)blockIdx.x * 512;
    const int t = threadIdx.x;
    float a = 0.f, b = 0.f;
#pragma unroll
    for (int c = 0; c < 2; c++) {
        const float* p = g_Sp + (size_t)c * 2097152 + row;
        a += p[t]; b += p[t + 256];
    }
    __shared__ float sh[256];
    sh[t] = fmaxf(a, b);
    __syncthreads();
    for (int off = 128; off > 0; off >>= 1) {
        if (t < off) sh[t] = fmaxf(sh[t], sh[t + off]);
        __syncthreads();
    }
    float m = sh[0];
    __syncthreads();
    float e0 = __expf(a - m), e1 = __expf(b - m);
    sh[t] = e0 + e1;
    __syncthreads();
    for (int off = 128; off > 0; off >>= 1) {
        if (t < off) sh[t] += sh[t + off];
        __syncthreads();
    }
    float inv = 1.0f / sh[0];
    float* q = g_S + row;
    q[t] = e0 * inv;
    q[t + 256] = e1 * inv;
}

// ---------------------------------------------------------------------------
// PV via tf32 mma.sync, output-transposed: M=f(128), N=t(128), K=s(512).
// Zt[f][t] = sum_s V'[s][f] * P[t][s]  ->  Z[b][n*64+cn][f*512+t]
// Norm+PReLU at smem store (raw bits). grid (64 cn, 4 t-tiles, 8 groups).
// ---------------------------------------------------------------------------
__global__ void __launch_bounds__(256, 2) pv_mma_kernel(
    const float* __restrict__ gv, const float* __restrict__ betav)
{
    __shared__ __align__(16) float Vs[32][136];   // [s][f]
    __shared__ __align__(16) float Ps[128][36];   // [t][s]

    const int g = blockIdx.z;
    const int n = g & 3, bb = g >> 2;
    const float* P = g_S + (size_t)g * 262144;
    const int cn = blockIdx.x;
    const float* Vb = g_Y3 + 16ull * 4194304 + (size_t)g * 4194304 + (size_t)cn * 65536;
    const int t0 = blockIdx.y * 128;
    float* Zb = g_Z + ((size_t)bb * 256 + (size_t)(n * 64 + cn)) * 65536;

    const int tid = threadIdx.x;
    const int w = tid >> 5, l = tid & 31;
    const int fg = l >> 2, ft = l & 3;
    const int orow = w >> 2, jcol = w & 3;

    float2 stv = g_stats[16 + g];
    const float ggv = gv[n * 64 + cn] * stv.y;
    const float ofv = betav[n * 64 + cn] - stv.x * ggv;

    float acc[4][4][4];
#pragma unroll
    for (int mt = 0; mt < 4; mt++)
#pragma unroll
        for (int nt = 0; nt < 4; nt++)
#pragma unroll
            for (int i = 0; i < 4; i++) acc[mt][nt][i] = 0.f;

    for (int kc = 0; kc < 16; kc++) {
        float4 vv[4], pp[4];
#pragma unroll
        for (int it = 0; it < 4; it++) {
            int i4 = tid + it * 256;
            int vr = i4 >> 5, vc4 = i4 & 31;
            vv[it] = *reinterpret_cast<const float4*>(&Vb[(size_t)(kc * 32 + vr) * 128 + vc4 * 4]);
            int pr = i4 >> 3, pc4 = i4 & 7;
            pp[it] = *reinterpret_cast<const float4*>(&P[(size_t)(t0 + pr) * 512 + kc * 32 + pc4 * 4]);
        }
        __syncthreads();
#pragma unroll
        for (int it = 0; it < 4; it++) {
            int i4 = tid + it * 256;
            int vr = i4 >> 5, vc4 = i4 & 31;
            float4 u;
            u.x = napply(vv[it].x, ggv, ofv);
            u.y = napply(vv[it].y, ggv, ofv);
            u.z = napply(vv[it].z, ggv, ofv);
            u.w = napply(vv[it].w, ggv, ofv);
            *reinterpret_cast<float4*>(&Vs[vr][vc4 * 4]) = u;
            int pr = i4 >> 3, pc4 = i4 & 7;
            *reinterpret_cast<float4*>(&Ps[pr][pc4 * 4]) = pp[it];
        }
        __syncthreads();

#pragma unroll
        for (int ks = 0; ks < 4; ks++) {
            const int kk = ks * 8;
            uint32_t a[4][4], b[4][2];
#pragma unroll
            for (int mt = 0; mt < 4; mt++) {
                int fw = orow * 64 + mt * 16 + fg;
                a[mt][0] = __float_as_uint(Vs[kk + ft][fw]);
                a[mt][1] = __float_as_uint(Vs[kk + ft][fw + 8]);
                a[mt][2] = __float_as_uint(Vs[kk + ft + 4][fw]);
                a[mt][3] = __float_as_uint(Vs[kk + ft + 4][fw + 8]);
            }
#pragma unroll
            for (int nt = 0; nt < 4; nt++) {
                int tw = jcol * 32 + nt * 8 + fg;
                b[nt][0] = __float_as_uint(Ps[tw][kk + ft]);
                b[nt][1] = __float_as_uint(Ps[tw][kk + ft + 4]);
            }
#pragma unroll
            for (int mt = 0; mt < 4; mt++)
#pragma unroll
                for (int nt = 0; nt < 4; nt++)
                    mma_tf32(acc[mt][nt], a[mt], b[nt]);
        }
        __syncthreads();
    }

    // C: (m=f, n=t_local); c0/c1 consecutive t, c2/c3 at f+8
#pragma unroll
    for (int mt = 0; mt < 4; mt++) {
        const int f = orow * 64 + mt * 16 + fg;
#pragma unroll
        for (int nt = 0; nt < 4; nt++) {
            const int tt = t0 + jcol * 32 + nt * 8 + 2 * ft;
            *reinterpret_cast<float2*>(&Zb[(size_t)f * 512 + tt]) =
                make_float2(acc[mt][nt][0], acc[mt][nt][1]);
            *reinterpret_cast<float2*>(&Zb[(size_t)(f + 8) * 512 + tt]) =
                make_float2(acc[mt][nt][2], acc[mt][nt][3]);
        }
    }
}

// ---------------------------------------------------------------------------
// Final: out = PReLU(norm(Yp)*gp + betap) + x
// ---------------------------------------------------------------------------
__global__ void __launch_bounds__(256) apply_final_kernel(
    const float* __restrict__ x, const float* __restrict__ gp,
    const float* __restrict__ betap, const float2* __restrict__ stats2,
    float* __restrict__ out)
{
    size_t i = ((size_t)blockIdx.x * 256 + threadIdx.x) * 4;
    int r = (int)(i >> 16);
    int bidx = r >> 8;
    int o = r & 255;
    float2 st = stats2[bidx];
    float gg = gp[o] * st.y;
    float ofs = betap[o] - st.x * gg;
    float4 v  = *reinterpret_cast<const float4*>(&g_Yp[i]);
    float4 xr = *reinterpret_cast<const float4*>(&x[i]);
    v.x = fmaf(v.x, gg, ofs); v.x = ((v.x >= 0.f) ? v.x : 0.25f * v.x) + xr.x;
    v.y = fmaf(v.y, gg, ofs); v.y = ((v.y >= 0.f) ? v.y : 0.25f * v.y) + xr.y;
    v.z = fmaf(v.z, gg, ofs); v.z = ((v.z >= 0.f) ? v.z : 0.25f * v.z) + xr.z;
    v.w = fmaf(v.w, gg, ofs); v.w = ((v.w >= 0.f) ? v.w : 0.25f * v.w) + xr.w;
    *reinterpret_cast<float4*>(&out[i]) = v;
}

// ---------------------------------------------------------------------------
extern "C" void kernel_launch(void* const* d_in, const int* in_sizes, int n_in,
                              void* d_out, int out_size)
{
    const float* x     = (const float*)d_in[0];
    const float* Wq    = (const float*)d_in[1];
    const float* bq    = (const float*)d_in[2];
    const float* gq    = (const float*)d_in[3];
    const float* betaq = (const float*)d_in[4];
    const float* Wk    = (const float*)d_in[5];
    const float* bk    = (const float*)d_in[6];
    const float* gk    = (const float*)d_in[7];
    const float* betak = (const float*)d_in[8];
    const float* Wv    = (const float*)d_in[9];
    const float* bv    = (const float*)d_in[10];
    const float* gv    = (const float*)d_in[11];
    const float* betav = (const float*)d_in[12];
    const float* Wp    = (const float*)d_in[13];
    const float* bp    = (const float*)d_in[14];
    const float* gp    = (const float*)d_in[15];
    const float* betap = (const float*)d_in[16];

    float *Y3, *Z, *Yp;
    float2 *part, *stats;
    cudaGetSymbolAddress((void**)&Y3,   g_Y3);
    cudaGetSymbolAddress((void**)&Z,    g_Z);
    cudaGetSymbolAddress((void**)&Yp,   g_Yp);
    cudaGetSymbolAddress((void**)&part, g_part);
    cudaGetSymbolAddress((void**)&stats, g_stats);

    const int SM_CONV = 107520;  // 3*(128*36 + 32*136) words * 4B
    const int SM_QK   = 69632;   // 2*(128*68) words * 4B
    cudaFuncSetAttribute(conv_mma_kernel, cudaFuncAttributeMaxDynamicSharedMemorySize, SM_CONV);
    cudaFuncSetAttribute(qk_mma_kernel,   cudaFuncAttributeMaxDynamicSharedMemorySize, SM_QK);

    // 1) QKV projections via tf32 mma.sync (3-stage cp.async, + norm partials)
    conv_mma_kernel<<<dim3(512, 6, 2), 256, SM_CONV>>>(x, Y3, Wq, Wk, Wv, bq, bk, bv, part);
    // 2) finalize QKV GroupNorm stats: 24 groups x 512 partials
    reduce_final_kernel<<<24, 256>>>(part, stats, 512, 1.0f / 4194304.0f);
    // 3) S partials = scale * Q'K'^T  (split-K x2, 256 blocks = one wave)
    qk_mma_kernel<<<dim3(4, 4, 16), 256, SM_QK>>>(gq, betaq, gk, betak);
    // 4) softmax rows (fuses split-K x2 reduction)
    softmax_kernel<<<4096, 256>>>();
    // 5) Vo = P V' (mma.sync, norm fused), permuted write into Z
    pv_mma_kernel<<<dim3(64, 4, 8), 256>>>(gv, betav);
    // 6) final projection via tf32 mma.sync (3-stage cp.async, + norm partials)
    conv_mma_kernel<<<dim3(512, 2, 2), 256, SM_CONV>>>(Z, Yp, Wp, Wp, Wp, bp, bp, bp, part);
    // 7) finalize per-sample stats: 2 groups x 2048 partials
    reduce_final_kernel<<<2, 256>>>(part, stats + 24, 2048, 1.0f / 16777216.0f);
    // 8) normalize + PReLU + residual
    apply_final_kernel<<<32768, 256>>>(x, gp, betap, stats + 24, (float*)d_out);
}

// round 13
// speedup vs baseline: 1.3557x; 1.2284x over previous
#include <cuda_runtime.h>
#include <cuda_fp16.h>
#include <cstdint>

// Problem constants: B=2, C=256, T=512, F=128, N=4 heads, H=CN=64, D=H*F=8192
#define TFsz 65536            // T*F
typedef unsigned long long u64;

// -------- scratch (device globals; no allocations allowed) --------
__device__ float g_Y3[100663296];   // [3][B][256][TF] Q,K,V (pre-norm, f32)
__device__ float g_Sp[4194304];     // [2 kchunks][8 g][512][512] partial scores
__device__ float g_S[2097152];      // [8][512][512] attention probs
__device__ float g_Z[33554432];     // [B][256][TF] permuted attention output
__device__ float g_Yp[33554432];    // [B][256][TF] final conv output (pre-norm)
__device__ __half g_Xh[33554432];   // [B][TF][256] transpose-packed X (then Z)
__device__ __half g_Wh[262144];     // [4][256][256] packed weights (q,k,v,p)
__device__ float2 g_part[12288];    // partial (sum, sumsq) from GEMM epilogues
__device__ float2 g_stats[32];      // (mu, rstd): [0..23] qkv groups, [24..25] final

// -------- PTX helpers (portable; no "a"-gated features) --------
__device__ __forceinline__ uint32_t smem_u32(const void* p) {
    uint32_t a;
    asm("{ .reg .u64 t; cvta.to.shared.u64 t, %1; cvt.u32.u64 %0, t; }" : "=r"(a) : "l"(p));
    return a;
}
#define CP16(dst, src) \
    asm volatile("cp.async.cg.shared.global [%0], [%1], 16;" :: "r"(dst), "l"(src))
#define CP_COMMIT() asm volatile("cp.async.commit_group;" ::: "memory")
#define CP_WAIT1()  asm volatile("cp.async.wait_group 1;" ::: "memory")
#define CP_WAIT0()  asm volatile("cp.async.wait_group 0;" ::: "memory")

// fp16 pair pack: h0 = lo, h1 = hi (cvt.rn.f16x2.f32 d, a, b -> d.h1=a, d.h0=b)
__device__ __forceinline__ uint32_t pack_h2(float lo, float hi) {
    uint32_t r; asm("cvt.rn.f16x2.f32 %0, %1, %2;" : "=r"(r) : "f"(hi), "f"(lo)); return r;
}
__device__ __forceinline__ void mma_f16(float c[4], const uint32_t a[4], const uint32_t b[2]) {
    asm volatile(
        "mma.sync.aligned.m16n8k16.row.col.f32.f16.f16.f32 "
        "{%0,%1,%2,%3}, {%4,%5,%6,%7}, {%8,%9}, {%0,%1,%2,%3};"
        : "+f"(c[0]), "+f"(c[1]), "+f"(c[2]), "+f"(c[3])
        : "r"(a[0]), "r"(a[1]), "r"(a[2]), "r"(a[3]), "r"(b[0]), "r"(b[1]));
}
// tf32 (raw fp32 bits, truncation) for PV only
__device__ __forceinline__ void mma_tf32(float c[4], const uint32_t a[4], const uint32_t b[2]) {
    asm volatile(
        "mma.sync.aligned.m16n8k8.row.col.f32.tf32.tf32.f32 "
        "{%0,%1,%2,%3}, {%4,%5,%6,%7}, {%8,%9}, {%0,%1,%2,%3};"
        : "+f"(c[0]), "+f"(c[1]), "+f"(c[2]), "+f"(c[3])
        : "r"(a[0]), "r"(a[1]), "r"(a[2]), "r"(a[3]), "r"(b[0]), "r"(b[1]));
}
__device__ __forceinline__ float napply(float v, float gg, float of) {
    float y = fmaf(v, gg, of);
    return (y >= 0.f) ? y : 0.25f * y;
}

// ---------------------------------------------------------------------------
// Pack all 4 weight matrices to half: g_Wh[t][o][c], t in {q,k,v,p}.
// ---------------------------------------------------------------------------
__global__ void __launch_bounds__(256) pack_w_kernel(
    const float* __restrict__ Wq, const float* __restrict__ Wk,
    const float* __restrict__ Wv, const float* __restrict__ Wp, __half* __restrict__ dst)
{
    int i = blockIdx.x * 256 + threadIdx.x;          // 0..262143
    int s = i >> 16;
    const float* src = (s == 0) ? Wq : (s == 1) ? Wk : (s == 2) ? Wv : Wp;
    dst[i] = __float2half_rn(src[i & 65535]);
}

// ---------------------------------------------------------------------------
// Transpose-pack: src f32 [b][256][TF] -> dst half [b][TF][256].
// grid (2048, 8, 2), block (32, 8).
// ---------------------------------------------------------------------------
__global__ void __launch_bounds__(256) transpose_pack_kernel(
    const float* __restrict__ src, __half* __restrict__ dst)
{
    __shared__ float tile[32][33];
    const int b = blockIdx.z;
    const int j0 = blockIdx.x * 32, c0 = blockIdx.y * 32;
    const float* s = src + (size_t)b * 16777216;
    __half* d = dst + (size_t)b * 16777216;
    const int tx = threadIdx.x, ty = threadIdx.y;
#pragma unroll
    for (int r = 0; r < 4; r++)
        tile[ty + r * 8][tx] = s[(size_t)(c0 + ty + r * 8) * TFsz + j0 + tx];
    __syncthreads();
#pragma unroll
    for (int r = 0; r < 4; r++)
        d[(size_t)(j0 + ty + r * 8) * 256 + c0 + tx] = __float2half_rn(tile[tx][ty + r * 8]);
}

// ---------------------------------------------------------------------------
// fp16 mma.sync conv GEMM (cp.async 3-buffer prefetch-2):
//   Out[slab][o][j] = bias[o] + sum_c W[o][c] * Xh[b][j][c]
// Block 128(o) x 128(j). K-chunks of 64 channels = 32 half2 pairs; 4 chunks.
// Tiles: Wt[128 o][36 u32-pairs], Xt[128 j][36] (pitch 36 = 4 mod 32: no cfl).
// Fragments (m16n8k16, pair units): address-identical to validated tf32 maps.
// Epilogue (f32): bias + stores + per-64-channel-group (sum,sumsq) partials.
// Dynamic smem u32: W bufs @0/4608/9216, X bufs @13824/18432/23040.
// ---------------------------------------------------------------------------
__global__ void __launch_bounds__(256, 2) conv_f16_kernel(
    const __half* __restrict__ Xh, float* __restrict__ Out,
    const __half* __restrict__ Whall,
    const float* __restrict__ b0_, const float* __restrict__ b1_, const float* __restrict__ b2_,
    float2* __restrict__ part, int nTens)
{
    extern __shared__ __align__(16) uint32_t dsm[];
    const uint32_t sb = smem_u32(dsm);

    const int bb = blockIdx.z;
    const int y = blockIdx.y;
    const int tens = y >> 1;
    const int o0 = (y & 1) * 128;
    const int j0 = blockIdx.x * 128;
    const int wsel = (nTens == 3) ? tens : 3;
    const __half* W = Whall + (size_t)wsel * 65536;
    const float* bias = (tens == 0) ? b0_ : (tens == 1) ? b1_ : b2_;
    const __half* Xb = Xh + (size_t)bb * 16777216;
    const int slab = (nTens == 3) ? (tens * 2 + bb) : bb;
    float* O = Out + (size_t)slab * (256 * (size_t)TFsz);

    const int tid = threadIdx.x;
    const int w = tid >> 5, l = tid & 31;
    const int g = l >> 2, t = l & 3;
    const int orow = w >> 2, jcol = w & 3;
    const int wrow0 = tid >> 3, wc4 = tid & 7;   // both tiles: rows +it*32, 8x16B per row

    float c[4][4][4];
#pragma unroll
    for (int mt = 0; mt < 4; mt++)
#pragma unroll
        for (int nt = 0; nt < 4; nt++)
#pragma unroll
            for (int i = 0; i < 4; i++) c[mt][nt][i] = 0.f;

#define CONV_ISSUE(KC, BUF) do {                                              \
    uint32_t wdst = sb + (BUF) * 18432;                                       \
    uint32_t xdst = sb + 55296 + (BUF) * 18432;                               \
    _Pragma("unroll")                                                         \
    for (int it = 0; it < 4; it++) {                                          \
        int row = wrow0 + it * 32;                                            \
        CP16(wdst + (row * 36 + wc4 * 4) * 4,                                 \
             &W[(size_t)(o0 + row) * 256 + (KC) * 64 + wc4 * 8]);             \
        CP16(xdst + (row * 36 + wc4 * 4) * 4,                                 \
             &Xb[(size_t)(j0 + row) * 256 + (KC) * 64 + wc4 * 8]);            \
    }                                                                         \
    CP_COMMIT();                                                              \
} while (0)

    CONV_ISSUE(0, 0);
    CONV_ISSUE(1, 1);
    for (int kc = 0; kc < 4; kc++) {
        const int buf = kc % 3;
        if (kc < 3) CP_WAIT1();
        else        CP_WAIT0();
        __syncthreads();
        if (kc + 2 < 4) CONV_ISSUE(kc + 2, (kc + 2) % 3);

        const uint32_t* Wsb = dsm + buf * 4608;
        const uint32_t* Xsb = dsm + 13824 + buf * 4608;
#pragma unroll
        for (int ks = 0; ks < 4; ks++) {
            const int kk = ks * 8;             // pair units
            uint32_t a[4][4], b[4][2];
#pragma unroll
            for (int mt = 0; mt < 4; mt++) {
                int ow = orow * 64 + mt * 16 + g;
                a[mt][0] = Wsb[ow * 36 + kk + t];
                a[mt][1] = Wsb[(ow + 8) * 36 + kk + t];
                a[mt][2] = Wsb[ow * 36 + kk + t + 4];
                a[mt][3] = Wsb[(ow + 8) * 36 + kk + t + 4];
            }
#pragma unroll
            for (int nt = 0; nt < 4; nt++) {
                int jw = jcol * 32 + nt * 8 + g;
                b[nt][0] = Xsb[jw * 36 + kk + t];
                b[nt][1] = Xsb[jw * 36 + kk + t + 4];
            }
#pragma unroll
            for (int mt = 0; mt < 4; mt++)
#pragma unroll
                for (int nt = 0; nt < 4; nt++)
                    mma_f16(c[mt][nt], a[mt], b[nt]);
        }
    }
#undef CONV_ISSUE

    float bl[4], bh[4];
#pragma unroll
    for (int mt = 0; mt < 4; mt++) {
        bl[mt] = __ldg(&bias[o0 + orow * 64 + mt * 16 + g]);
        bh[mt] = __ldg(&bias[o0 + orow * 64 + mt * 16 + g + 8]);
    }
    float s = 0.f, sq = 0.f;
#pragma unroll
    for (int mt = 0; mt < 4; mt++) {
        const int o_lo = o0 + orow * 64 + mt * 16 + g;
#pragma unroll
        for (int nt = 0; nt < 4; nt++) {
            const int jj = j0 + jcol * 32 + nt * 8 + 2 * t;
            float v0 = c[mt][nt][0] + bl[mt];
            float v1 = c[mt][nt][1] + bl[mt];
            float v2 = c[mt][nt][2] + bh[mt];
            float v3 = c[mt][nt][3] + bh[mt];
            *reinterpret_cast<float2*>(&O[(size_t)o_lo * TFsz + jj]) = make_float2(v0, v1);
            *reinterpret_cast<float2*>(&O[(size_t)(o_lo + 8) * TFsz + jj]) = make_float2(v2, v3);
            s  += (v0 + v1) + (v2 + v3);
            sq += (v0 * v0 + v1 * v1) + (v2 * v2 + v3 * v3);
        }
    }

    __syncthreads();
    float* redS = reinterpret_cast<float*>(dsm);
    float* redQ = redS + 256;
    redS[tid] = s; redQ[tid] = sq;
    __syncthreads();
    const int r = tid & 127;
    for (int off = 64; off > 0; off >>= 1) {
        if (r < off) { redS[tid] += redS[tid + off]; redQ[tid] += redQ[tid + off]; }
        __syncthreads();
    }
    if (r == 0) {
        int og = (y & 1) * 2 + (tid >> 7);
        part[((size_t)((nTens == 3) ? (tens * 2 + bb) : (6 + bb)) * 4 + og) * 512 + blockIdx.x] =
            make_float2(redS[tid], redQ[tid]);
    }
}

// ---------------------------------------------------------------------------
// Final reduction over `count` consecutive partials per group -> (mu, rstd)
// ---------------------------------------------------------------------------
__global__ void __launch_bounds__(256) reduce_final_kernel(
    const float2* __restrict__ part, float2* __restrict__ stats, int count, float inv_n)
{
    const int g = blockIdx.x;
    float s = 0.f, s2 = 0.f;
    for (int i = threadIdx.x; i < count; i += 256) {
        float2 v = part[(size_t)g * count + i];
        s += v.x; s2 += v.y;
    }
    __shared__ float sh[256], sh2[256];
    int t = threadIdx.x;
    sh[t] = s; sh2[t] = s2;
    __syncthreads();
    for (int off = 128; off > 0; off >>= 1) {
        if (t < off) { sh[t] += sh[t + off]; sh2[t] += sh2[t + off]; }
        __syncthreads();
    }
    if (t == 0) {
        float mu = sh[0] * inv_n;
        float var = fmaxf(sh2[0] * inv_n - mu * mu, 0.f);
        stats[g] = make_float2(mu, rsqrtf(var + 1e-6f));
    }
}

// ---------------------------------------------------------------------------
// QK via fp16 mma.sync (NT, split-K x2, 64-k chunks = 32 pairs):
//   Sp[c][g][t][s] = scale * sum Q'(t,k) K'(s,k)
// Norm+PReLU at staging; pack pairs along k (natural: Y3 rows are k-contig).
// Tiles u32 [128][36] pairs. grid (4, 4, 16 = g*2+c), 256 thr, one wave.
// ---------------------------------------------------------------------------
__global__ void __launch_bounds__(256, 2) qk_f16_kernel(
    const float* __restrict__ gq, const float* __restrict__ betaq,
    const float* __restrict__ gk, const float* __restrict__ betak)
{
    extern __shared__ __align__(16) uint32_t dsm[];
    uint32_t* Qs = dsm;            // [128][36] pairs
    uint32_t* Ks = dsm + 4608;
    __shared__ float sgg[2][64], sof[2][64];

    const int z = blockIdx.z;
    const int g = z >> 1, c = z & 1;
    const int n = g & 3;
    const float* Q  = g_Y3 + (size_t)g * 4194304;
    const float* Km = g_Y3 + 8ull * 4194304 + (size_t)g * 4194304;
    const int t0 = blockIdx.y * 128, s0 = blockIdx.x * 128;
    const int tid = threadIdx.x;
    const int w = tid >> 5, l = tid & 31;
    const int fg = l >> 2, ft = l & 3;
    const int orow = w >> 2, jcol = w & 3;

    if (tid < 128) {
        int which = tid >> 6, h = tid & 63, o = n * 64 + h;
        float2 st = g_stats[which * 8 + g];
        const float* gw = which ? gk : gq;
        const float* bw = which ? betak : betaq;
        float gg = gw[o] * st.y;
        sgg[which][h] = gg;
        sof[which][h] = bw[o] - st.x * gg;
    }
    __syncthreads();

    float acc[4][4][4];
#pragma unroll
    for (int mt = 0; mt < 4; mt++)
#pragma unroll
        for (int nt = 0; nt < 4; nt++)
#pragma unroll
            for (int i = 0; i < 4; i++) acc[mt][nt][i] = 0.f;

    for (int kc = 0; kc < 64; kc++) {
        const int k0 = c * 4096 + kc * 64;      // chunk within one channel h
        const int h = k0 >> 7;
        const size_t hb = (size_t)h * 65536 + (size_t)(k0 & 127);
        const float ggq = sgg[0][h], ofq = sof[0][h];
        const float ggk = sgg[1][h], ofk = sof[1][h];
        float4 qv[8], kv[8];
#pragma unroll
        for (int it = 0; it < 8; it++) {
            int i4 = tid + it * 256;
            int r = i4 >> 4, c4 = i4 & 15;
            qv[it] = *reinterpret_cast<const float4*>(&Q[hb + (size_t)(t0 + r) * 128 + c4 * 4]);
            kv[it] = *reinterpret_cast<const float4*>(&Km[hb + (size_t)(s0 + r) * 128 + c4 * 4]);
        }
        __syncthreads();
#pragma unroll
        for (int it = 0; it < 8; it++) {
            int i4 = tid + it * 256;
            int r = i4 >> 4, c4 = i4 & 15;
            uint2 uq, uk;
            uq.x = pack_h2(napply(qv[it].x, ggq, ofq), napply(qv[it].y, ggq, ofq));
            uq.y = pack_h2(napply(qv[it].z, ggq, ofq), napply(qv[it].w, ggq, ofq));
            *reinterpret_cast<uint2*>(&Qs[r * 36 + c4 * 2]) = uq;
            uk.x = pack_h2(napply(kv[it].x, ggk, ofk), napply(kv[it].y, ggk, ofk));
            uk.y = pack_h2(napply(kv[it].z, ggk, ofk), napply(kv[it].w, ggk, ofk));
            *reinterpret_cast<uint2*>(&Ks[r * 36 + c4 * 2]) = uk;
        }
        __syncthreads();

#pragma unroll
        for (int ks = 0; ks < 4; ks++) {
            const int kk = ks * 8;             // pair units
            uint32_t a[4][4], b[4][2];
#pragma unroll
            for (int mt = 0; mt < 4; mt++) {
                int tw = orow * 64 + mt * 16 + fg;
                a[mt][0] = Qs[tw * 36 + kk + ft];
                a[mt][1] = Qs[(tw + 8) * 36 + kk + ft];
                a[mt][2] = Qs[tw * 36 + kk + ft + 4];
                a[mt][3] = Qs[(tw + 8) * 36 + kk + ft + 4];
            }
#pragma unroll
            for (int nt = 0; nt < 4; nt++) {
                int sw = jcol * 32 + nt * 8 + fg;
                b[nt][0] = Ks[sw * 36 + kk + ft];
                b[nt][1] = Ks[sw * 36 + kk + ft + 4];
            }
#pragma unroll
            for (int mt = 0; mt < 4; mt++)
#pragma unroll
                for (int nt = 0; nt < 4; nt++)
                    mma_f16(acc[mt][nt], a[mt], b[nt]);
        }
        __syncthreads();
    }

    const float scale = 0.011048543456039806f;   // 1/sqrt(8192)
    float* Sg = g_Sp + (size_t)c * 2097152 + (size_t)g * 262144;
#pragma unroll
    for (int mt = 0; mt < 4; mt++) {
        const int tl = t0 + orow * 64 + mt * 16 + fg;
#pragma unroll
        for (int nt = 0; nt < 4; nt++) {
            const int sl = s0 + jcol * 32 + nt * 8 + 2 * ft;
            *reinterpret_cast<float2*>(&Sg[(size_t)tl * 512 + sl]) =
                make_float2(acc[mt][nt][0] * scale, acc[mt][nt][1] * scale);
            *reinterpret_cast<float2*>(&Sg[(size_t)(tl + 8) * 512 + sl]) =
                make_float2(acc[mt][nt][2] * scale, acc[mt][nt][3] * scale);
        }
    }
}

// ---------------------------------------------------------------------------
// Row softmax over 512, fusing the split-K (x2) partial sum. 4096 blocks.
// ---------------------------------------------------------------------------
__global__ void __launch_bounds__(256) softmax_kernel()
{
    const size_t row = (size_t)blockIdx.x * 512;
    const int t = threadIdx.x;
    float a = 0.f, b = 0.f;
#pragma unroll
    for (int c = 0; c < 2; c++) {
        const float* p = g_Sp + (size_t)c * 2097152 + row;
        a += p[t]; b += p[t + 256];
    }
    __shared__ float sh[256];
    sh[t] = fmaxf(a, b);
    __syncthreads();
    for (int off = 128; off > 0; off >>= 1) {
        if (t < off) sh[t] = fmaxf(sh[t], sh[t + off]);
        __syncthreads();
    }
    float m = sh[0];
    __syncthreads();
    float e0 = __expf(a - m), e1 = __expf(b - m);
    sh[t] = e0 + e1;
    __syncthreads();
    for (int off = 128; off > 0; off >>= 1) {
        if (t < off) sh[t] += sh[t + off];
        __syncthreads();
    }
    float inv = 1.0f / sh[0];
    float* q = g_S + row;
    q[t] = e0 * inv;
    q[t + 256] = e1 * inv;
}

// ---------------------------------------------------------------------------
// PV via tf32 mma.sync (unchanged from round 12), output-transposed.
// ---------------------------------------------------------------------------
__global__ void __launch_bounds__(256, 2) pv_mma_kernel(
    const float* __restrict__ gv, const float* __restrict__ betav)
{
    __shared__ __align__(16) float Vs[32][136];   // [s][f]
    __shared__ __align__(16) float Ps[128][36];   // [t][s]

    const int g = blockIdx.z;
    const int n = g & 3, bb = g >> 2;
    const float* P = g_S + (size_t)g * 262144;
    const int cn = blockIdx.x;
    const float* Vb = g_Y3 + 16ull * 4194304 + (size_t)g * 4194304 + (size_t)cn * 65536;
    const int t0 = blockIdx.y * 128;
    float* Zb = g_Z + ((size_t)bb * 256 + (size_t)(n * 64 + cn)) * 65536;

    const int tid = threadIdx.x;
    const int w = tid >> 5, l = tid & 31;
    const int fg = l >> 2, ft = l & 3;
    const int orow = w >> 2, jcol = w & 3;

    float2 stv = g_stats[16 + g];
    const float ggv = gv[n * 64 + cn] * stv.y;
    const float ofv = betav[n * 64 + cn] - stv.x * ggv;

    float acc[4][4][4];
#pragma unroll
    for (int mt = 0; mt < 4; mt++)
#pragma unroll
        for (int nt = 0; nt < 4; nt++)
#pragma unroll
            for (int i = 0; i < 4; i++) acc[mt][nt][i] = 0.f;

    for (int kc = 0; kc < 16; kc++) {
        float4 vv[4], pp[4];
#pragma unroll
        for (int it = 0; it < 4; it++) {
            int i4 = tid + it * 256;
            int vr = i4 >> 5, vc4 = i4 & 31;
            vv[it] = *reinterpret_cast<const float4*>(&Vb[(size_t)(kc * 32 + vr) * 128 + vc4 * 4]);
            int pr = i4 >> 3, pc4 = i4 & 7;
            pp[it] = *reinterpret_cast<const float4*>(&P[(size_t)(t0 + pr) * 512 + kc * 32 + pc4 * 4]);
        }
        __syncthreads();
#pragma unroll
        for (int it = 0; it < 4; it++) {
            int i4 = tid + it * 256;
            int vr = i4 >> 5, vc4 = i4 & 31;
            float4 u;
            u.x = napply(vv[it].x, ggv, ofv);
            u.y = napply(vv[it].y, ggv, ofv);
            u.z = napply(vv[it].z, ggv, ofv);
            u.w = napply(vv[it].w, ggv, ofv);
            *reinterpret_cast<float4*>(&Vs[vr][vc4 * 4]) = u;
            int pr = i4 >> 3, pc4 = i4 & 7;
            *reinterpret_cast<float4*>(&Ps[pr][pc4 * 4]) = pp[it];
        }
        __syncthreads();

#pragma unroll
        for (int ks = 0; ks < 4; ks++) {
            const int kk = ks * 8;
            uint32_t a[4][4], b[4][2];
#pragma unroll
            for (int mt = 0; mt < 4; mt++) {
                int fw = orow * 64 + mt * 16 + fg;
                a[mt][0] = __float_as_uint(Vs[kk + ft][fw]);
                a[mt][1] = __float_as_uint(Vs[kk + ft][fw + 8]);
                a[mt][2] = __float_as_uint(Vs[kk + ft + 4][fw]);
                a[mt][3] = __float_as_uint(Vs[kk + ft + 4][fw + 8]);
            }
#pragma unroll
            for (int nt = 0; nt < 4; nt++) {
                int tw = jcol * 32 + nt * 8 + fg;
                b[nt][0] = __float_as_uint(Ps[tw][kk + ft]);
                b[nt][1] = __float_as_uint(Ps[tw][kk + ft + 4]);
            }
#pragma unroll
            for (int mt = 0; mt < 4; mt++)
#pragma unroll
                for (int nt = 0; nt < 4; nt++)
                    mma_tf32(acc[mt][nt], a[mt], b[nt]);
        }
        __syncthreads();
    }

#pragma unroll
    for (int mt = 0; mt < 4; mt++) {
        const int f = orow * 64 + mt * 16 + fg;
#pragma unroll
        for (int nt = 0; nt < 4; nt++) {
            const int tt = t0 + jcol * 32 + nt * 8 + 2 * ft;
            *reinterpret_cast<float2*>(&Zb[(size_t)f * 512 + tt]) =
                make_float2(acc[mt][nt][0], acc[mt][nt][1]);
            *reinterpret_cast<float2*>(&Zb[(size_t)(f + 8) * 512 + tt]) =
                make_float2(acc[mt][nt][2], acc[mt][nt][3]);
        }
    }
}

// ---------------------------------------------------------------------------
// Final: out = PReLU(norm(Yp)*gp + betap) + x
// ---------------------------------------------------------------------------
__global__ void __launch_bounds__(256) apply_final_kernel(
    const float* __restrict__ x, const float* __restrict__ gp,
    const float* __restrict__ betap, const float2* __restrict__ stats2,
    float* __restrict__ out)
{
    size_t i = ((size_t)blockIdx.x * 256 + threadIdx.x) * 4;
    int r = (int)(i >> 16);
    int bidx = r >> 8;
    int o = r & 255;
    float2 st = stats2[bidx];
    float gg = gp[o] * st.y;
    float ofs = betap[o] - st.x * gg;
    float4 v  = *reinterpret_cast<const float4*>(&g_Yp[i]);
    float4 xr = *reinterpret_cast<const float4*>(&x[i]);
    v.x = fmaf(v.x, gg, ofs); v.x = ((v.x >= 0.f) ? v.x : 0.25f * v.x) + xr.x;
    v.y = fmaf(v.y, gg, ofs); v.y = ((v.y >= 0.f) ? v.y : 0.25f * v.y) + xr.y;
    v.z = fmaf(v.z, gg, ofs); v.z = ((v.z >= 0.f) ? v.z : 0.25f * v.z) + xr.z;
    v.w = fmaf(v.w, gg, ofs); v.w = ((v.w >= 0.f) ? v.w : 0.25f * v.w) + xr.w;
    *reinterpret_cast<float4*>(&out[i]) = v;
}

// ---------------------------------------------------------------------------
extern "C" void kernel_launch(void* const* d_in, const int* in_sizes, int n_in,
                              void* d_out, int out_size)
{
    const float* x     = (const float*)d_in[0];
    const float* Wq    = (const float*)d_in[1];
    const float* bq    = (const float*)d_in[2];
    const float* gq    = (const float*)d_in[3];
    const float* betaq = (const float*)d_in[4];
    const float* Wk    = (const float*)d_in[5];
    const float* bk    = (const float*)d_in[6];
    const float* gk    = (const float*)d_in[7];
    const float* betak = (const float*)d_in[8];
    const float* Wv    = (const float*)d_in[9];
    const float* bv    = (const float*)d_in[10];
    const float* gv    = (const float*)d_in[11];
    const float* betav = (const float*)d_in[12];
    const float* Wp    = (const float*)d_in[13];
    const float* bp    = (const float*)d_in[14];
    const float* gp    = (const float*)d_in[15];
    const float* betap = (const float*)d_in[16];

    float *Y3, *Z, *Yp;
    __half *Xh, *Wh;
    float2 *part, *stats;
    cudaGetSymbolAddress((void**)&Y3,   g_Y3);
    cudaGetSymbolAddress((void**)&Z,    g_Z);
    cudaGetSymbolAddress((void**)&Yp,   g_Yp);
    cudaGetSymbolAddress((void**)&Xh,   g_Xh);
    cudaGetSymbolAddress((void**)&Wh,   g_Wh);
    cudaGetSymbolAddress((void**)&part, g_part);
    cudaGetSymbolAddress((void**)&stats, g_stats);

    const int SM_CONV = 110592;  // 6 tiles x 4608 u32 x 4B
    const int SM_QK   = 36864;   // 2 tiles x 4608 u32 x 4B
    cudaFuncSetAttribute(conv_f16_kernel, cudaFuncAttributeMaxDynamicSharedMemorySize, SM_CONV);
    cudaFuncSetAttribute(qk_f16_kernel,   cudaFuncAttributeMaxDynamicSharedMemorySize, SM_QK);

    // 0) pack weights + transpose-pack X to half
    pack_w_kernel<<<1024, 256>>>(Wq, Wk, Wv, Wp, Wh);
    transpose_pack_kernel<<<dim3(2048, 8, 2), dim3(32, 8)>>>(x, Xh);
    // 1) QKV projections via fp16 mma.sync (+ fused norm partials)
    conv_f16_kernel<<<dim3(512, 6, 2), 256, SM_CONV>>>(Xh, Y3, Wh, bq, bk, bv, part, 3);
    // 2) finalize QKV GroupNorm stats: 24 groups x 512 partials
    reduce_final_kernel<<<24, 256>>>(part, stats, 512, 1.0f / 4194304.0f);
    // 3) S partials = scale * Q'K'^T  (fp16 mma, split-K x2, norm fused)
    qk_f16_kernel<<<dim3(4, 4, 16), 256, SM_QK>>>(gq, betaq, gk, betak);
    // 4) softmax rows (fuses split-K x2 reduction)
    softmax_kernel<<<4096, 256>>>();
    // 5) Vo = P V' (tf32 mma, norm fused), permuted write into Z
    pv_mma_kernel<<<dim3(64, 4, 8), 256>>>(gv, betav);
    // 6) transpose-pack Z -> Xh (reused as Zh), then fp16 projection
    transpose_pack_kernel<<<dim3(2048, 8, 2), dim3(32, 8)>>>(Z, Xh);
    conv_f16_kernel<<<dim3(512, 2, 2), 256, SM_CONV>>>(Xh, Yp, Wh, bp, bp, bp, part, 1);
    // 7) finalize per-sample stats: 2 groups (slabs 6,7) x 2048 partials
    reduce_final_kernel<<<2, 256>>>(part + 6ull * 4 * 512, stats + 24, 2048, 1.0f / 16777216.0f);
    // 8) normalize + PReLU + residual
    apply_final_kernel<<<32768, 256>>>(x, gp, betap, stats + 24, (float*)d_out);
}

// round 14
// speedup vs baseline: 1.4811x; 1.0926x over previous
#include <cuda_runtime.h>
#include <cuda_fp16.h>
#include <cstdint>

// Problem constants: B=2, C=256, T=512, F=128, N=4 heads, H=CN=64, D=H*F=8192
#define TFsz 65536            // T*F
typedef unsigned long long u64;

// -------- scratch (device globals; no allocations allowed) --------
__device__ float g_Y3[100663296];   // [3][B][256][TF] Q,K,V (pre-norm, f32)
__device__ float g_Sp[4194304];     // [2 kchunks][8 g][512][512] partial scores
__device__ float g_S[2097152];      // [8][512][512] attention probs
__device__ float g_Z[33554432];     // [B][256][TF] permuted attention output
__device__ float g_Yp[33554432];    // [B][256][TF] final conv output (pre-norm)
__device__ __half g_Xh[33554432];   // [B][TF][256] transpose-packed X (then Z)
__device__ __half g_Wh[262144];     // [4][256][256] packed weights (q,k,v,p)
__device__ float2 g_part[12288];    // partial (sum, sumsq) from GEMM epilogues
__device__ float2 g_stats[32];      // (mu, rstd): [0..23] qkv groups, [24..25] final

// -------- PTX helpers (portable; no "a"-gated features) --------
__device__ __forceinline__ uint32_t smem_u32(const void* p) {
    uint32_t a;
    asm("{ .reg .u64 t; cvta.to.shared.u64 t, %1; cvt.u32.u64 %0, t; }" : "=r"(a) : "l"(p));
    return a;
}
#define CP16(dst, src) \
    asm volatile("cp.async.cg.shared.global [%0], [%1], 16;" :: "r"(dst), "l"(src))
#define CP_COMMIT() asm volatile("cp.async.commit_group;" ::: "memory")
#define CP_WAIT1()  asm volatile("cp.async.wait_group 1;" ::: "memory")
#define CP_WAIT0()  asm volatile("cp.async.wait_group 0;" ::: "memory")

// fp16 pair pack: h0 = lo, h1 = hi (cvt.rn.f16x2.f32 d, a, b -> d.h1=a, d.h0=b)
__device__ __forceinline__ uint32_t pack_h2(float lo, float hi) {
    uint32_t r; asm("cvt.rn.f16x2.f32 %0, %1, %2;" : "=r"(r) : "f"(hi), "f"(lo)); return r;
}
__device__ __forceinline__ void mma_f16(float c[4], const uint32_t a[4], const uint32_t b[2]) {
    asm volatile(
        "mma.sync.aligned.m16n8k16.row.col.f32.f16.f16.f32 "
        "{%0,%1,%2,%3}, {%4,%5,%6,%7}, {%8,%9}, {%0,%1,%2,%3};"
        : "+f"(c[0]), "+f"(c[1]), "+f"(c[2]), "+f"(c[3])
        : "r"(a[0]), "r"(a[1]), "r"(a[2]), "r"(a[3]), "r"(b[0]), "r"(b[1]));
}
__device__ __forceinline__ float napply(float v, float gg, float of) {
    float y = fmaf(v, gg, of);
    return (y >= 0.f) ? y : 0.25f * y;
}

// ---------------------------------------------------------------------------
// Pack all 4 weight matrices to half: g_Wh[t][o][c], t in {q,k,v,p}.
// ---------------------------------------------------------------------------
__global__ void __launch_bounds__(256) pack_w_kernel(
    const float* __restrict__ Wq, const float* __restrict__ Wk,
    const float* __restrict__ Wv, const float* __restrict__ Wp, __half* __restrict__ dst)
{
    int i = blockIdx.x * 256 + threadIdx.x;          // 0..262143
    int s = i >> 16;
    const float* src = (s == 0) ? Wq : (s == 1) ? Wk : (s == 2) ? Wv : Wp;
    dst[i] = __float2half_rn(src[i & 65535]);
}

// ---------------------------------------------------------------------------
// Transpose-pack: src f32 [b][256][TF] -> dst half [b][TF][256].
// grid (2048, 8, 2), block (32, 8).
// ---------------------------------------------------------------------------
__global__ void __launch_bounds__(256) transpose_pack_kernel(
    const float* __restrict__ src, __half* __restrict__ dst)
{
    __shared__ float tile[32][33];
    const int b = blockIdx.z;
    const int j0 = blockIdx.x * 32, c0 = blockIdx.y * 32;
    const float* s = src + (size_t)b * 16777216;
    __half* d = dst + (size_t)b * 16777216;
    const int tx = threadIdx.x, ty = threadIdx.y;
#pragma unroll
    for (int r = 0; r < 4; r++)
        tile[ty + r * 8][tx] = s[(size_t)(c0 + ty + r * 8) * TFsz + j0 + tx];
    __syncthreads();
#pragma unroll
    for (int r = 0; r < 4; r++)
        d[(size_t)(j0 + ty + r * 8) * 256 + c0 + tx] = __float2half_rn(tile[tx][ty + r * 8]);
}

// ---------------------------------------------------------------------------
// fp16 mma.sync conv GEMM (cp.async 3-buffer prefetch-2):
//   Out[slab][o][j] = bias[o] + sum_c W[o][c] * Xh[b][j][c]
// Block 128(o) x 128(j). K-chunks of 64 channels = 32 half2 pairs; 4 chunks.
// Tiles: Wt[128 o][36 u32-pairs], Xt[128 j][36] (pitch 36 = 4 mod 32: no cfl).
// Epilogue (f32): bias + stores + per-64-channel-group (sum,sumsq) partials.
// Dynamic smem u32: W bufs @0/4608/9216, X bufs @13824/18432/23040.
// ---------------------------------------------------------------------------
__global__ void __launch_bounds__(256, 2) conv_f16_kernel(
    const __half* __restrict__ Xh, float* __restrict__ Out,
    const __half* __restrict__ Whall,
    const float* __restrict__ b0_, const float* __restrict__ b1_, const float* __restrict__ b2_,
    float2* __restrict__ part, int nTens)
{
    extern __shared__ __align__(16) uint32_t dsm[];
    const uint32_t sb = smem_u32(dsm);

    const int bb = blockIdx.z;
    const int y = blockIdx.y;
    const int tens = y >> 1;
    const int o0 = (y & 1) * 128;
    const int j0 = blockIdx.x * 128;
    const int wsel = (nTens == 3) ? tens : 3;
    const __half* W = Whall + (size_t)wsel * 65536;
    const float* bias = (tens == 0) ? b0_ : (tens == 1) ? b1_ : b2_;
    const __half* Xb = Xh + (size_t)bb * 16777216;
    const int slab = (nTens == 3) ? (tens * 2 + bb) : bb;
    float* O = Out + (size_t)slab * (256 * (size_t)TFsz);

    const int tid = threadIdx.x;
    const int w = tid >> 5, l = tid & 31;
    const int g = l >> 2, t = l & 3;
    const int orow = w >> 2, jcol = w & 3;
    const int wrow0 = tid >> 3, wc4 = tid & 7;

    float c[4][4][4];
#pragma unroll
    for (int mt = 0; mt < 4; mt++)
#pragma unroll
        for (int nt = 0; nt < 4; nt++)
#pragma unroll
            for (int i = 0; i < 4; i++) c[mt][nt][i] = 0.f;

#define CONV_ISSUE(KC, BUF) do {                                              \
    uint32_t wdst = sb + (BUF) * 18432;                                       \
    uint32_t xdst = sb + 55296 + (BUF) * 18432;                               \
    _Pragma("unroll")                                                         \
    for (int it = 0; it < 4; it++) {                                          \
        int row = wrow0 + it * 32;                                            \
        CP16(wdst + (row * 36 + wc4 * 4) * 4,                                 \
             &W[(size_t)(o0 + row) * 256 + (KC) * 64 + wc4 * 8]);             \
        CP16(xdst + (row * 36 + wc4 * 4) * 4,                                 \
             &Xb[(size_t)(j0 + row) * 256 + (KC) * 64 + wc4 * 8]);            \
    }                                                                         \
    CP_COMMIT();                                                              \
} while (0)

    CONV_ISSUE(0, 0);
    CONV_ISSUE(1, 1);
    for (int kc = 0; kc < 4; kc++) {
        const int buf = kc % 3;
        if (kc < 3) CP_WAIT1();
        else        CP_WAIT0();
        __syncthreads();
        if (kc + 2 < 4) CONV_ISSUE(kc + 2, (kc + 2) % 3);

        const uint32_t* Wsb = dsm + buf * 4608;
        const uint32_t* Xsb = dsm + 13824 + buf * 4608;
#pragma unroll
        for (int ks = 0; ks < 4; ks++) {
            const int kk = ks * 8;             // pair units
            uint32_t a[4][4], b[4][2];
#pragma unroll
            for (int mt = 0; mt < 4; mt++) {
                int ow = orow * 64 + mt * 16 + g;
                a[mt][0] = Wsb[ow * 36 + kk + t];
                a[mt][1] = Wsb[(ow + 8) * 36 + kk + t];
                a[mt][2] = Wsb[ow * 36 + kk + t + 4];
                a[mt][3] = Wsb[(ow + 8) * 36 + kk + t + 4];
            }
#pragma unroll
            for (int nt = 0; nt < 4; nt++) {
                int jw = jcol * 32 + nt * 8 + g;
                b[nt][0] = Xsb[jw * 36 + kk + t];
                b[nt][1] = Xsb[jw * 36 + kk + t + 4];
            }
#pragma unroll
            for (int mt = 0; mt < 4; mt++)
#pragma unroll
                for (int nt = 0; nt < 4; nt++)
                    mma_f16(c[mt][nt], a[mt], b[nt]);
        }
    }
#undef CONV_ISSUE

    float bl[4], bh[4];
#pragma unroll
    for (int mt = 0; mt < 4; mt++) {
        bl[mt] = __ldg(&bias[o0 + orow * 64 + mt * 16 + g]);
        bh[mt] = __ldg(&bias[o0 + orow * 64 + mt * 16 + g + 8]);
    }
    float s = 0.f, sq = 0.f;
#pragma unroll
    for (int mt = 0; mt < 4; mt++) {
        const int o_lo = o0 + orow * 64 + mt * 16 + g;
#pragma unroll
        for (int nt = 0; nt < 4; nt++) {
            const int jj = j0 + jcol * 32 + nt * 8 + 2 * t;
            float v0 = c[mt][nt][0] + bl[mt];
            float v1 = c[mt][nt][1] + bl[mt];
            float v2 = c[mt][nt][2] + bh[mt];
            float v3 = c[mt][nt][3] + bh[mt];
            *reinterpret_cast<float2*>(&O[(size_t)o_lo * TFsz + jj]) = make_float2(v0, v1);
            *reinterpret_cast<float2*>(&O[(size_t)(o_lo + 8) * TFsz + jj]) = make_float2(v2, v3);
            s  += (v0 + v1) + (v2 + v3);
            sq += (v0 * v0 + v1 * v1) + (v2 * v2 + v3 * v3);
        }
    }

    __syncthreads();
    float* redS = reinterpret_cast<float*>(dsm);
    float* redQ = redS + 256;
    redS[tid] = s; redQ[tid] = sq;
    __syncthreads();
    const int r = tid & 127;
    for (int off = 64; off > 0; off >>= 1) {
        if (r < off) { redS[tid] += redS[tid + off]; redQ[tid] += redQ[tid + off]; }
        __syncthreads();
    }
    if (r == 0) {
        int og = (y & 1) * 2 + (tid >> 7);
        part[((size_t)((nTens == 3) ? (tens * 2 + bb) : (6 + bb)) * 4 + og) * 512 + blockIdx.x] =
            make_float2(redS[tid], redQ[tid]);
    }
}

// ---------------------------------------------------------------------------
// Final reduction over `count` consecutive partials per group -> (mu, rstd)
// ---------------------------------------------------------------------------
__global__ void __launch_bounds__(256) reduce_final_kernel(
    const float2* __restrict__ part, float2* __restrict__ stats, int count, float inv_n)
{
    const int g = blockIdx.x;
    float s = 0.f, s2 = 0.f;
    for (int i = threadIdx.x; i < count; i += 256) {
        float2 v = part[(size_t)g * count + i];
        s += v.x; s2 += v.y;
    }
    __shared__ float sh[256], sh2[256];
    int t = threadIdx.x;
    sh[t] = s; sh2[t] = s2;
    __syncthreads();
    for (int off = 128; off > 0; off >>= 1) {
        if (t < off) { sh[t] += sh[t + off]; sh2[t] += sh2[t + off]; }
        __syncthreads();
    }
    if (t == 0) {
        float mu = sh[0] * inv_n;
        float var = fmaxf(sh2[0] * inv_n - mu * mu, 0.f);
        stats[g] = make_float2(mu, rsqrtf(var + 1e-6f));
    }
}

// ---------------------------------------------------------------------------
// QK via fp16 mma.sync (NT, split-K x2, 64-k chunks = 32 pairs):
//   Sp[c][g][t][s] = scale * sum Q'(t,k) K'(s,k)
// Norm+PReLU at staging; pairs packed along k. Tiles u32 [128][36].
// grid (4, 4, 16 = g*2+c), 256 thr, one wave.
// ---------------------------------------------------------------------------
__global__ void __launch_bounds__(256, 2) qk_f16_kernel(
    const float* __restrict__ gq, const float* __restrict__ betaq,
    const float* __restrict__ gk, const float* __restrict__ betak)
{
    extern __shared__ __align__(16) uint32_t dsm[];
    uint32_t* Qs = dsm;            // [128][36] pairs
    uint32_t* Ks = dsm + 4608;
    __shared__ float sgg[2][64], sof[2][64];

    const int z = blockIdx.z;
    const int g = z >> 1, c = z & 1;
    const int n = g & 3;
    const float* Q  = g_Y3 + (size_t)g * 4194304;
    const float* Km = g_Y3 + 8ull * 4194304 + (size_t)g * 4194304;
    const int t0 = blockIdx.y * 128, s0 = blockIdx.x * 128;
    const int tid = threadIdx.x;
    const int w = tid >> 5, l = tid & 31;
    const int fg = l >> 2, ft = l & 3;
    const int orow = w >> 2, jcol = w & 3;

    if (tid < 128) {
        int which = tid >> 6, h = tid & 63, o = n * 64 + h;
        float2 st = g_stats[which * 8 + g];
        const float* gw = which ? gk : gq;
        const float* bw = which ? betak : betaq;
        float gg = gw[o] * st.y;
        sgg[which][h] = gg;
        sof[which][h] = bw[o] - st.x * gg;
    }
    __syncthreads();

    float acc[4][4][4];
#pragma unroll
    for (int mt = 0; mt < 4; mt++)
#pragma unroll
        for (int nt = 0; nt < 4; nt++)
#pragma unroll
            for (int i = 0; i < 4; i++) acc[mt][nt][i] = 0.f;

    for (int kc = 0; kc < 64; kc++) {
        const int k0 = c * 4096 + kc * 64;      // chunk within one channel h
        const int h = k0 >> 7;
        const size_t hb = (size_t)h * 65536 + (size_t)(k0 & 127);
        const float ggq = sgg[0][h], ofq = sof[0][h];
        const float ggk = sgg[1][h], ofk = sof[1][h];
        float4 qv[8], kv[8];
#pragma unroll
        for (int it = 0; it < 8; it++) {
            int i4 = tid + it * 256;
            int r = i4 >> 4, c4 = i4 & 15;
            qv[it] = *reinterpret_cast<const float4*>(&Q[hb + (size_t)(t0 + r) * 128 + c4 * 4]);
            kv[it] = *reinterpret_cast<const float4*>(&Km[hb + (size_t)(s0 + r) * 128 + c4 * 4]);
        }
        __syncthreads();
#pragma unroll
        for (int it = 0; it < 8; it++) {
            int i4 = tid + it * 256;
            int r = i4 >> 4, c4 = i4 & 15;
            uint2 uq, uk;
            uq.x = pack_h2(napply(qv[it].x, ggq, ofq), napply(qv[it].y, ggq, ofq));
            uq.y = pack_h2(napply(qv[it].z, ggq, ofq), napply(qv[it].w, ggq, ofq));
            *reinterpret_cast<uint2*>(&Qs[r * 36 + c4 * 2]) = uq;
            uk.x = pack_h2(napply(kv[it].x, ggk, ofk), napply(kv[it].y, ggk, ofk));
            uk.y = pack_h2(napply(kv[it].z, ggk, ofk), napply(kv[it].w, ggk, ofk));
            *reinterpret_cast<uint2*>(&Ks[r * 36 + c4 * 2]) = uk;
        }
        __syncthreads();

#pragma unroll
        for (int ks = 0; ks < 4; ks++) {
            const int kk = ks * 8;             // pair units
            uint32_t a[4][4], b[4][2];
#pragma unroll
            for (int mt = 0; mt < 4; mt++) {
                int tw = orow * 64 + mt * 16 + fg;
                a[mt][0] = Qs[tw * 36 + kk + ft];
                a[mt][1] = Qs[(tw + 8) * 36 + kk + ft];
                a[mt][2] = Qs[tw * 36 + kk + ft + 4];
                a[mt][3] = Qs[(tw + 8) * 36 + kk + ft + 4];
            }
#pragma unroll
            for (int nt = 0; nt < 4; nt++) {
                int sw = jcol * 32 + nt * 8 + fg;
                b[nt][0] = Ks[sw * 36 + kk + ft];
                b[nt][1] = Ks[sw * 36 + kk + ft + 4];
            }
#pragma unroll
            for (int mt = 0; mt < 4; mt++)
#pragma unroll
                for (int nt = 0; nt < 4; nt++)
                    mma_f16(acc[mt][nt], a[mt], b[nt]);
        }
        __syncthreads();
    }

    const float scale = 0.011048543456039806f;   // 1/sqrt(8192)
    float* Sg = g_Sp + (size_t)c * 2097152 + (size_t)g * 262144;
#pragma unroll
    for (int mt = 0; mt < 4; mt++) {
        const int tl = t0 + orow * 64 + mt * 16 + fg;
#pragma unroll
        for (int nt = 0; nt < 4; nt++) {
            const int sl = s0 + jcol * 32 + nt * 8 + 2 * ft;
            *reinterpret_cast<float2*>(&Sg[(size_t)tl * 512 + sl]) =
                make_float2(acc[mt][nt][0] * scale, acc[mt][nt][1] * scale);
            *reinterpret_cast<float2*>(&Sg[(size_t)(tl + 8) * 512 + sl]) =
                make_float2(acc[mt][nt][2] * scale, acc[mt][nt][3] * scale);
        }
    }
}

// ---------------------------------------------------------------------------
// Row softmax over 512, fusing the split-K (x2) partial sum. 4096 blocks.
// ---------------------------------------------------------------------------
__global__ void __launch_bounds__(256) softmax_kernel()
{
    const size_t row = (size_t)blockIdx.x * 512;
    const int t = threadIdx.x;
    float a = 0.f, b = 0.f;
#pragma unroll
    for (int c = 0; c < 2; c++) {
        const float* p = g_Sp + (size_t)c * 2097152 + row;
        a += p[t]; b += p[t + 256];
    }
    __shared__ float sh[256];
    sh[t] = fmaxf(a, b);
    __syncthreads();
    for (int off = 128; off > 0; off >>= 1) {
        if (t < off) sh[t] = fmaxf(sh[t], sh[t + off]);
        __syncthreads();
    }
    float m = sh[0];
    __syncthreads();
    float e0 = __expf(a - m), e1 = __expf(b - m);
    sh[t] = e0 + e1;
    __syncthreads();
    for (int off = 128; off > 0; off >>= 1) {
        if (t < off) sh[t] += sh[t + off];
        __syncthreads();
    }
    float inv = 1.0f / sh[0];
    float* q = g_S + row;
    q[t] = e0 * inv;
    q[t + 256] = e1 * inv;
}

// ---------------------------------------------------------------------------
// PV via fp16 mma.sync, M=t(128), N=f(128), K=s(512):
//   Z[b][n*64+cn][f*512+t] = sum_s P[t][s] * V'[s][f]
// A = P pairs (packed at staging, tile [128 t][20 pairs], banks (20fg+ft) ok).
// B = V' from f32 tile [32 s][132 f] (pitch 132: pack-LDS banks 8ft+fg+8nt ok),
// pairs packed at fragment build (2 LDS + 1 cvt per reg, 8 regs/ks).
// grid (64 cn, 4 t-tiles, 8 groups), 256 threads.
// ---------------------------------------------------------------------------
__global__ void __launch_bounds__(256, 2) pv_f16_kernel(
    const float* __restrict__ gv, const float* __restrict__ betav)
{
    __shared__ __align__(16) float Vs[32][132];      // [s][f] f32 (normed)
    __shared__ __align__(16) uint32_t Pp[128][20];   // [t][s-pair] fp16x2

    const int g = blockIdx.z;
    const int n = g & 3, bb = g >> 2;
    const float* P = g_S + (size_t)g * 262144;
    const int cn = blockIdx.x;
    const float* Vb = g_Y3 + 16ull * 4194304 + (size_t)g * 4194304 + (size_t)cn * 65536;
    const int t0 = blockIdx.y * 128;
    float* Zb = g_Z + ((size_t)bb * 256 + (size_t)(n * 64 + cn)) * 65536;

    const int tid = threadIdx.x;
    const int w = tid >> 5, l = tid & 31;
    const int fg = l >> 2, ft = l & 3;
    const int trow = w >> 2, fcol = w & 3;

    float2 stv = g_stats[16 + g];
    const float ggv = gv[n * 64 + cn] * stv.y;
    const float ofv = betav[n * 64 + cn] - stv.x * ggv;

    float acc[4][4][4];
#pragma unroll
    for (int mt = 0; mt < 4; mt++)
#pragma unroll
        for (int nt = 0; nt < 4; nt++)
#pragma unroll
            for (int i = 0; i < 4; i++) acc[mt][nt][i] = 0.f;

    for (int kc = 0; kc < 16; kc++) {
        float4 vv[4], pp[4];
#pragma unroll
        for (int it = 0; it < 4; it++) {
            int i4 = tid + it * 256;
            int vr = i4 >> 5, vc4 = i4 & 31;
            vv[it] = *reinterpret_cast<const float4*>(&Vb[(size_t)(kc * 32 + vr) * 128 + vc4 * 4]);
            int pr = i4 >> 3, pc4 = i4 & 7;
            pp[it] = *reinterpret_cast<const float4*>(&P[(size_t)(t0 + pr) * 512 + kc * 32 + pc4 * 4]);
        }
        __syncthreads();
#pragma unroll
        for (int it = 0; it < 4; it++) {
            int i4 = tid + it * 256;
            int vr = i4 >> 5, vc4 = i4 & 31;
            float4 u;
            u.x = napply(vv[it].x, ggv, ofv);
            u.y = napply(vv[it].y, ggv, ofv);
            u.z = napply(vv[it].z, ggv, ofv);
            u.w = napply(vv[it].w, ggv, ofv);
            *reinterpret_cast<float4*>(&Vs[vr][vc4 * 4]) = u;
            int pr = i4 >> 3, pc4 = i4 & 7;
            uint2 up;
            up.x = pack_h2(pp[it].x, pp[it].y);
            up.y = pack_h2(pp[it].z, pp[it].w);
            *reinterpret_cast<uint2*>(&Pp[pr][pc4 * 2]) = up;
        }
        __syncthreads();

#pragma unroll
        for (int ks = 0; ks < 2; ks++) {
            const int kk = ks * 8;             // pair units (A), s offset 16*ks (B)
            const int sk = ks * 16;
            uint32_t a[4][4], b[4][2];
#pragma unroll
            for (int mt = 0; mt < 4; mt++) {
                int tw = trow * 64 + mt * 16 + fg;
                a[mt][0] = Pp[tw][kk + ft];
                a[mt][1] = Pp[tw + 8][kk + ft];
                a[mt][2] = Pp[tw][kk + ft + 4];
                a[mt][3] = Pp[tw + 8][kk + ft + 4];
            }
#pragma unroll
            for (int nt = 0; nt < 4; nt++) {
                int fw = fcol * 32 + nt * 8 + fg;
                b[nt][0] = pack_h2(Vs[sk + 2 * ft][fw], Vs[sk + 2 * ft + 1][fw]);
                b[nt][1] = pack_h2(Vs[sk + 2 * ft + 8][fw], Vs[sk + 2 * ft + 9][fw]);
            }
#pragma unroll
            for (int mt = 0; mt < 4; mt++)
#pragma unroll
                for (int nt = 0; nt < 4; nt++)
                    mma_f16(acc[mt][nt], a[mt], b[nt]);
        }
        __syncthreads();
    }

    // C: (m=t, n=f). c0/c1 -> f, f+1 (stride-512 rows); c2/c3 -> t+8.
#pragma unroll
    for (int mt = 0; mt < 4; mt++) {
        const int tl = t0 + trow * 64 + mt * 16 + fg;
#pragma unroll
        for (int nt = 0; nt < 4; nt++) {
            const int f0 = fcol * 32 + nt * 8 + 2 * ft;
            Zb[(size_t)f0 * 512 + tl]           = acc[mt][nt][0];
            Zb[(size_t)(f0 + 1) * 512 + tl]     = acc[mt][nt][1];
            Zb[(size_t)f0 * 512 + tl + 8]       = acc[mt][nt][2];
            Zb[(size_t)(f0 + 1) * 512 + tl + 8] = acc[mt][nt][3];
        }
    }
}

// ---------------------------------------------------------------------------
// Final: out = PReLU(norm(Yp)*gp + betap) + x
// ---------------------------------------------------------------------------
__global__ void __launch_bounds__(256) apply_final_kernel(
    const float* __restrict__ x, const float* __restrict__ gp,
    const float* __restrict__ betap, const float2* __restrict__ stats2,
    float* __restrict__ out)
{
    size_t i = ((size_t)blockIdx.x * 256 + threadIdx.x) * 4;
    int r = (int)(i >> 16);
    int bidx = r >> 8;
    int o = r & 255;
    float2 st = stats2[bidx];
    float gg = gp[o] * st.y;
    float ofs = betap[o] - st.x * gg;
    float4 v  = *reinterpret_cast<const float4*>(&g_Yp[i]);
    float4 xr = *reinterpret_cast<const float4*>(&x[i]);
    v.x = fmaf(v.x, gg, ofs); v.x = ((v.x >= 0.f) ? v.x : 0.25f * v.x) + xr.x;
    v.y = fmaf(v.y, gg, ofs); v.y = ((v.y >= 0.f) ? v.y : 0.25f * v.y) + xr.y;
    v.z = fmaf(v.z, gg, ofs); v.z = ((v.z >= 0.f) ? v.z : 0.25f * v.z) + xr.z;
    v.w = fmaf(v.w, gg, ofs); v.w = ((v.w >= 0.f) ? v.w : 0.25f * v.w) + xr.w;
    *reinterpret_cast<float4*>(&out[i]) = v;
}

// ---------------------------------------------------------------------------
extern "C" void kernel_launch(void* const* d_in, const int* in_sizes, int n_in,
                              void* d_out, int out_size)
{
    const float* x     = (const float*)d_in[0];
    const float* Wq    = (const float*)d_in[1];
    const float* bq    = (const float*)d_in[2];
    const float* gq    = (const float*)d_in[3];
    const float* betaq = (const float*)d_in[4];
    const float* Wk    = (const float*)d_in[5];
    const float* bk    = (const float*)d_in[6];
    const float* gk    = (const float*)d_in[7];
    const float* betak = (const float*)d_in[8];
    const float* Wv    = (const float*)d_in[9];
    const float* bv    = (const float*)d_in[10];
    const float* gv    = (const float*)d_in[11];
    const float* betav = (const float*)d_in[12];
    const float* Wp    = (const float*)d_in[13];
    const float* bp    = (const float*)d_in[14];
    const float* gp    = (const float*)d_in[15];
    const float* betap = (const float*)d_in[16];

    float *Y3, *Z, *Yp;
    __half *Xh, *Wh;
    float2 *part, *stats;
    cudaGetSymbolAddress((void**)&Y3,   g_Y3);
    cudaGetSymbolAddress((void**)&Z,    g_Z);
    cudaGetSymbolAddress((void**)&Yp,   g_Yp);
    cudaGetSymbolAddress((void**)&Xh,   g_Xh);
    cudaGetSymbolAddress((void**)&Wh,   g_Wh);
    cudaGetSymbolAddress((void**)&part, g_part);
    cudaGetSymbolAddress((void**)&stats, g_stats);

    const int SM_CONV = 110592;  // 6 tiles x 4608 u32 x 4B
    const int SM_QK   = 36864;   // 2 tiles x 4608 u32 x 4B
    cudaFuncSetAttribute(conv_f16_kernel, cudaFuncAttributeMaxDynamicSharedMemorySize, SM_CONV);
    cudaFuncSetAttribute(qk_f16_kernel,   cudaFuncAttributeMaxDynamicSharedMemorySize, SM_QK);

    // 0) pack weights + transpose-pack X to half
    pack_w_kernel<<<1024, 256>>>(Wq, Wk, Wv, Wp, Wh);
    transpose_pack_kernel<<<dim3(2048, 8, 2), dim3(32, 8)>>>(x, Xh);
    // 1) QKV projections via fp16 mma.sync (+ fused norm partials)
    conv_f16_kernel<<<dim3(512, 6, 2), 256, SM_CONV>>>(Xh, Y3, Wh, bq, bk, bv, part, 3);
    // 2) finalize QKV GroupNorm stats: 24 groups x 512 partials
    reduce_final_kernel<<<24, 256>>>(part, stats, 512, 1.0f / 4194304.0f);
    // 3) S partials = scale * Q'K'^T  (fp16 mma, split-K x2, norm fused)
    qk_f16_kernel<<<dim3(4, 4, 16), 256, SM_QK>>>(gq, betaq, gk, betak);
    // 4) softmax rows (fuses split-K x2 reduction)
    softmax_kernel<<<4096, 256>>>();
    // 5) Vo = P V' (fp16 mma, norm fused), permuted write into Z
    pv_f16_kernel<<<dim3(64, 4, 8), 256>>>(gv, betav);
    // 6) transpose-pack Z -> Xh (reused as Zh), then fp16 projection
    transpose_pack_kernel<<<dim3(2048, 8, 2), dim3(32, 8)>>>(Z, Xh);
    conv_f16_kernel<<<dim3(512, 2, 2), 256, SM_CONV>>>(Xh, Yp, Wh, bp, bp, bp, part, 1);
    // 7) finalize per-sample stats: 2 groups (slabs 6,7) x 2048 partials
    reduce_final_kernel<<<2, 256>>>(part + 6ull * 4 * 512, stats + 24, 2048, 1.0f / 16777216.0f);
    // 8) normalize + PReLU + residual
    apply_final_kernel<<<32768, 256>>>(x, gp, betap, stats + 24, (float*)d_out);
}

// round 15
// speedup vs baseline: 1.5200x; 1.0262x over previous
#include <cuda_runtime.h>
#include <cuda_fp16.h>
#include <cstdint>

// Problem constants: B=2, C=256, T=512, F=128, N=4 heads, H=CN=64, D=H*F=8192
#define TFsz 65536            // T*F
typedef unsigned long long u64;

// -------- scratch (device globals; no allocations allowed) --------
__device__ float g_Y3[100663296];   // [3][B][256][TF] Q,K,V (pre-norm, f32)
__device__ float g_Sp[4194304];     // [2 kchunks][8 g][512][512] partial scores
__device__ float g_Z[33554432];     // [B][256][TF] permuted attention output
__device__ float g_Yp[33554432];    // [B][256][TF] final conv output (pre-norm)
__device__ __half g_Xh[33554432];   // [B][TF][256] transpose-packed X (then Z)
__device__ __half g_Wh[262144];     // [4][256][256] packed weights (q,k,v,p)
__device__ __half g_QKh[67108864];  // [2][8][512][8192] normalized Q,K (k-contig)
__device__ __half g_Vt[33554432];   // [8][64][128 f][512 s] normalized V^T
__device__ __half g_Sh[2097152];    // [8][512][512] attention probs (half)
__device__ float2 g_part[12288];    // partial (sum, sumsq) from GEMM epilogues
__device__ float2 g_stats[32];      // (mu, rstd): [0..23] qkv groups, [24..25] final

// -------- PTX helpers (portable; no "a"-gated features) --------
__device__ __forceinline__ uint32_t smem_u32(const void* p) {
    uint32_t a;
    asm("{ .reg .u64 t; cvta.to.shared.u64 t, %1; cvt.u32.u64 %0, t; }" : "=r"(a) : "l"(p));
    return a;
}
#define CP16(dst, src) \
    asm volatile("cp.async.cg.shared.global [%0], [%1], 16;" :: "r"(dst), "l"(src))
#define CP_COMMIT() asm volatile("cp.async.commit_group;" ::: "memory")
#define CP_WAIT1()  asm volatile("cp.async.wait_group 1;" ::: "memory")
#define CP_WAIT0()  asm volatile("cp.async.wait_group 0;" ::: "memory")

// fp16 pair pack: h0 = lo, h1 = hi
__device__ __forceinline__ uint32_t pack_h2(float lo, float hi) {
    uint32_t r; asm("cvt.rn.f16x2.f32 %0, %1, %2;" : "=r"(r) : "f"(hi), "f"(lo)); return r;
}
__device__ __forceinline__ void mma_f16(float c[4], const uint32_t a[4], const uint32_t b[2]) {
    asm volatile(
        "mma.sync.aligned.m16n8k16.row.col.f32.f16.f16.f32 "
        "{%0,%1,%2,%3}, {%4,%5,%6,%7}, {%8,%9}, {%0,%1,%2,%3};"
        : "+f"(c[0]), "+f"(c[1]), "+f"(c[2]), "+f"(c[3])
        : "r"(a[0]), "r"(a[1]), "r"(a[2]), "r"(a[3]), "r"(b[0]), "r"(b[1]));
}
__device__ __forceinline__ float napply(float v, float gg, float of) {
    float y = fmaf(v, gg, of);
    return (y >= 0.f) ? y : 0.25f * y;
}

// ---------------------------------------------------------------------------
// Pack all 4 weight matrices to half: g_Wh[t][o][c], t in {q,k,v,p}.
// ---------------------------------------------------------------------------
__global__ void __launch_bounds__(256) pack_w_kernel(
    const float* __restrict__ Wq, const float* __restrict__ Wk,
    const float* __restrict__ Wv, const float* __restrict__ Wp, __half* __restrict__ dst)
{
    int i = blockIdx.x * 256 + threadIdx.x;
    int s = i >> 16;
    const float* src = (s == 0) ? Wq : (s == 1) ? Wk : (s == 2) ? Wv : Wp;
    dst[i] = __float2half_rn(src[i & 65535]);
}

// ---------------------------------------------------------------------------
// Transpose-pack: src f32 [b][256][TF] -> dst half [b][TF][256].
// grid (2048, 8, 2), block (32, 8).
// ---------------------------------------------------------------------------
__global__ void __launch_bounds__(256) transpose_pack_kernel(
    const float* __restrict__ src, __half* __restrict__ dst)
{
    __shared__ float tile[32][33];
    const int b = blockIdx.z;
    const int j0 = blockIdx.x * 32, c0 = blockIdx.y * 32;
    const float* s = src + (size_t)b * 16777216;
    __half* d = dst + (size_t)b * 16777216;
    const int tx = threadIdx.x, ty = threadIdx.y;
#pragma unroll
    for (int r = 0; r < 4; r++)
        tile[ty + r * 8][tx] = s[(size_t)(c0 + ty + r * 8) * TFsz + j0 + tx];
    __syncthreads();
#pragma unroll
    for (int r = 0; r < 4; r++)
        d[(size_t)(j0 + ty + r * 8) * 256 + c0 + tx] = __float2half_rn(tile[tx][ty + r * 8]);
}

// ---------------------------------------------------------------------------
// fp16 mma.sync conv GEMM (cp.async 3-buffer prefetch-2):
//   Out[slab][o][j] = bias[o] + sum_c W[o][c] * Xh[b][j][c]
// Tiles: Wt[128 o][36 u32-pairs], Xt[128 j][36]. 4 chunks of 64 channels.
// Epilogue fuses bias + per-64-channel-group (sum,sumsq) partials.
// ---------------------------------------------------------------------------
__global__ void __launch_bounds__(256, 2) conv_f16_kernel(
    const __half* __restrict__ Xh, float* __restrict__ Out,
    const __half* __restrict__ Whall,
    const float* __restrict__ b0_, const float* __restrict__ b1_, const float* __restrict__ b2_,
    float2* __restrict__ part, int nTens)
{
    extern __shared__ __align__(16) uint32_t dsm[];
    const uint32_t sb = smem_u32(dsm);

    const int bb = blockIdx.z;
    const int y = blockIdx.y;
    const int tens = y >> 1;
    const int o0 = (y & 1) * 128;
    const int j0 = blockIdx.x * 128;
    const int wsel = (nTens == 3) ? tens : 3;
    const __half* W = Whall + (size_t)wsel * 65536;
    const float* bias = (tens == 0) ? b0_ : (tens == 1) ? b1_ : b2_;
    const __half* Xb = Xh + (size_t)bb * 16777216;
    const int slab = (nTens == 3) ? (tens * 2 + bb) : bb;
    float* O = Out + (size_t)slab * (256 * (size_t)TFsz);

    const int tid = threadIdx.x;
    const int w = tid >> 5, l = tid & 31;
    const int g = l >> 2, t = l & 3;
    const int orow = w >> 2, jcol = w & 3;
    const int wrow0 = tid >> 3, wc4 = tid & 7;

    float c[4][4][4];
#pragma unroll
    for (int mt = 0; mt < 4; mt++)
#pragma unroll
        for (int nt = 0; nt < 4; nt++)
#pragma unroll
            for (int i = 0; i < 4; i++) c[mt][nt][i] = 0.f;

#define CONV_ISSUE(KC, BUF) do {                                              \
    uint32_t wdst = sb + (BUF) * 18432;                                       \
    uint32_t xdst = sb + 55296 + (BUF) * 18432;                               \
    _Pragma("unroll")                                                         \
    for (int it = 0; it < 4; it++) {                                          \
        int row = wrow0 + it * 32;                                            \
        CP16(wdst + (row * 36 + wc4 * 4) * 4,                                 \
             &W[(size_t)(o0 + row) * 256 + (KC) * 64 + wc4 * 8]);             \
        CP16(xdst + (row * 36 + wc4 * 4) * 4,                                 \
             &Xb[(size_t)(j0 + row) * 256 + (KC) * 64 + wc4 * 8]);            \
    }                                                                         \
    CP_COMMIT();                                                              \
} while (0)

    CONV_ISSUE(0, 0);
    CONV_ISSUE(1, 1);
    for (int kc = 0; kc < 4; kc++) {
        const int buf = kc % 3;
        if (kc < 3) CP_WAIT1();
        else        CP_WAIT0();
        __syncthreads();
        if (kc + 2 < 4) CONV_ISSUE(kc + 2, (kc + 2) % 3);

        const uint32_t* Wsb = dsm + buf * 4608;
        const uint32_t* Xsb = dsm + 13824 + buf * 4608;
#pragma unroll
        for (int ks = 0; ks < 4; ks++) {
            const int kk = ks * 8;
            uint32_t a[4][4], b[4][2];
#pragma unroll
            for (int mt = 0; mt < 4; mt++) {
                int ow = orow * 64 + mt * 16 + g;
                a[mt][0] = Wsb[ow * 36 + kk + t];
                a[mt][1] = Wsb[(ow + 8) * 36 + kk + t];
                a[mt][2] = Wsb[ow * 36 + kk + t + 4];
                a[mt][3] = Wsb[(ow + 8) * 36 + kk + t + 4];
            }
#pragma unroll
            for (int nt = 0; nt < 4; nt++) {
                int jw = jcol * 32 + nt * 8 + g;
                b[nt][0] = Xsb[jw * 36 + kk + t];
                b[nt][1] = Xsb[jw * 36 + kk + t + 4];
            }
#pragma unroll
            for (int mt = 0; mt < 4; mt++)
#pragma unroll
                for (int nt = 0; nt < 4; nt++)
                    mma_f16(c[mt][nt], a[mt], b[nt]);
        }
    }
#undef CONV_ISSUE

    float bl[4], bh[4];
#pragma unroll
    for (int mt = 0; mt < 4; mt++) {
        bl[mt] = __ldg(&bias[o0 + orow * 64 + mt * 16 + g]);
        bh[mt] = __ldg(&bias[o0 + orow * 64 + mt * 16 + g + 8]);
    }
    float s = 0.f, sq = 0.f;
#pragma unroll
    for (int mt = 0; mt < 4; mt++) {
        const int o_lo = o0 + orow * 64 + mt * 16 + g;
#pragma unroll
        for (int nt = 0; nt < 4; nt++) {
            const int jj = j0 + jcol * 32 + nt * 8 + 2 * t;
            float v0 = c[mt][nt][0] + bl[mt];
            float v1 = c[mt][nt][1] + bl[mt];
            float v2 = c[mt][nt][2] + bh[mt];
            float v3 = c[mt][nt][3] + bh[mt];
            *reinterpret_cast<float2*>(&O[(size_t)o_lo * TFsz + jj]) = make_float2(v0, v1);
            *reinterpret_cast<float2*>(&O[(size_t)(o_lo + 8) * TFsz + jj]) = make_float2(v2, v3);
            s  += (v0 + v1) + (v2 + v3);
            sq += (v0 * v0 + v1 * v1) + (v2 * v2 + v3 * v3);
        }
    }

    __syncthreads();
    float* redS = reinterpret_cast<float*>(dsm);
    float* redQ = redS + 256;
    redS[tid] = s; redQ[tid] = sq;
    __syncthreads();
    const int r = tid & 127;
    for (int off = 64; off > 0; off >>= 1) {
        if (r < off) { redS[tid] += redS[tid + off]; redQ[tid] += redQ[tid + off]; }
        __syncthreads();
    }
    if (r == 0) {
        int og = (y & 1) * 2 + (tid >> 7);
        part[((size_t)((nTens == 3) ? (tens * 2 + bb) : (6 + bb)) * 4 + og) * 512 + blockIdx.x] =
            make_float2(redS[tid], redQ[tid]);
    }
}

// ---------------------------------------------------------------------------
// Final reduction over `count` consecutive partials per group -> (mu, rstd)
// ---------------------------------------------------------------------------
__global__ void __launch_bounds__(256) reduce_final_kernel(
    const float2* __restrict__ part, float2* __restrict__ stats, int count, float inv_n)
{
    const int g = blockIdx.x;
    float s = 0.f, s2 = 0.f;
    for (int i = threadIdx.x; i < count; i += 256) {
        float2 v = part[(size_t)g * count + i];
        s += v.x; s2 += v.y;
    }
    __shared__ float sh[256], sh2[256];
    int t = threadIdx.x;
    sh[t] = s; sh2[t] = s2;
    __syncthreads();
    for (int off = 128; off > 0; off >>= 1) {
        if (t < off) { sh[t] += sh[t + off]; sh2[t] += sh2[t + off]; }
        __syncthreads();
    }
    if (t == 0) {
        float mu = sh[0] * inv_n;
        float var = fmaxf(sh2[0] * inv_n - mu * mu, 0.f);
        stats[g] = make_float2(mu, rsqrtf(var + 1e-6f));
    }
}

// ---------------------------------------------------------------------------
// QK pack prepass: normalize+PReLU Q,K once, write half k-contiguous:
//   QKh[slab=which*8+g][t][h*128+f] = napply(Y3[which][g slab][h][t][f])
// grid (64 h, 16 slabs), 256 threads. Coalesced both sides.
// ---------------------------------------------------------------------------
__global__ void __launch_bounds__(256) qk_pack_kernel(
    const float* __restrict__ gq, const float* __restrict__ betaq,
    const float* __restrict__ gk, const float* __restrict__ betak)
{
    const int slab = blockIdx.y;
    const int h = blockIdx.x;
    const int which = slab >> 3, g = slab & 7, n = g & 3;
    const int ch = n * 64 + h;
    float2 st = g_stats[which * 8 + g];
    const float* gw = which ? gk : gq;
    const float* bw = which ? betak : betaq;
    const float gg = gw[ch] * st.y;
    const float of = bw[ch] - st.x * gg;
    const float* src = g_Y3 + (size_t)(which * 8 + g) * 4194304 + (size_t)h * 65536;
    __half* dst = g_QKh + (size_t)slab * 4194304 + (size_t)h * 128;
    const int f4 = (threadIdx.x & 31) * 4, tr = threadIdx.x >> 5;
#pragma unroll 4
    for (int t0 = 0; t0 < 512; t0 += 8) {
        int t = t0 + tr;
        float4 v = *reinterpret_cast<const float4*>(&src[(size_t)t * 128 + f4]);
        uint2 u;
        u.x = pack_h2(napply(v.x, gg, of), napply(v.y, gg, of));
        u.y = pack_h2(napply(v.z, gg, of), napply(v.w, gg, of));
        *reinterpret_cast<uint2*>(&dst[(size_t)t * 8192 + f4]) = u;
    }
}

// ---------------------------------------------------------------------------
// V pack prepass: normalize+PReLU V, transposed so k=s is contiguous:
//   Vt[g*64+cn][f][s] = napply(V[g][cn][s][f])
// grid (16 s-tiles, 4 f-tiles, 512 = g*64+cn), block (32, 8).
// ---------------------------------------------------------------------------
__global__ void __launch_bounds__(256) v_pack_kernel(
    const float* __restrict__ gv, const float* __restrict__ betav)
{
    __shared__ float tile[32][33];
    const int z = blockIdx.z, g = z >> 6, cn = z & 63, n = g & 3;
    float2 st = g_stats[16 + g];
    const float gg = gv[n * 64 + cn] * st.y;
    const float of = betav[n * 64 + cn] - st.x * gg;
    const float* src = g_Y3 + 16ull * 4194304 + (size_t)g * 4194304 + (size_t)cn * 65536;
    __half* dst = g_Vt + (size_t)z * 65536;
    const int s0 = blockIdx.x * 32, f0 = blockIdx.y * 32;
    const int tx = threadIdx.x, ty = threadIdx.y;
#pragma unroll
    for (int r = 0; r < 4; r++)
        tile[ty + r * 8][tx] = src[(size_t)(s0 + ty + r * 8) * 128 + f0 + tx];
    __syncthreads();
#pragma unroll
    for (int r = 0; r < 4; r++)
        dst[(size_t)(f0 + ty + r * 8) * 512 + s0 + tx] =
            __float2half_rn(napply(tile[tx][ty + r * 8], gg, of));
}

// ---------------------------------------------------------------------------
// QK GEMM (conv clone, pure cp.async): Sp[c][g][t][s] = scale*sum Q'(t,k)K'(s,k)
// split-K x2: each block sums 4096 k = 64 chunks of 64k (32 pairs).
// grid (4 s-tiles, 4 t-tiles, 16 = g*2+c), 256 threads, 3-buffer pipeline.
// ---------------------------------------------------------------------------
__global__ void __launch_bounds__(256, 2) qk_mma2_kernel()
{
    extern __shared__ __align__(16) uint32_t dsm[];
    const uint32_t sb = smem_u32(dsm);
    const int z = blockIdx.z, g = z >> 1, c = z & 1;
    const __half* Qb = g_QKh + (size_t)g * 4194304 + (size_t)c * 4096;
    const __half* Kb = g_QKh + (size_t)(8 + g) * 4194304 + (size_t)c * 4096;
    const int t0 = blockIdx.y * 128, s0 = blockIdx.x * 128;
    const int tid = threadIdx.x;
    const int w = tid >> 5, l = tid & 31;
    const int fg = l >> 2, ft = l & 3;
    const int orow = w >> 2, jcol = w & 3;
    const int wrow0 = tid >> 3, wc4 = tid & 7;

    float acc[4][4][4];
#pragma unroll
    for (int mt = 0; mt < 4; mt++)
#pragma unroll
        for (int nt = 0; nt < 4; nt++)
#pragma unroll
            for (int i = 0; i < 4; i++) acc[mt][nt][i] = 0.f;

#define QK_ISSUE(KC, BUF) do {                                                \
    uint32_t adst = sb + (BUF) * 18432;                                       \
    uint32_t bdst = sb + 55296 + (BUF) * 18432;                               \
    _Pragma("unroll")                                                         \
    for (int it = 0; it < 4; it++) {                                          \
        int row = wrow0 + it * 32;                                            \
        CP16(adst + (row * 36 + wc4 * 4) * 4,                                 \
             &Qb[(size_t)(t0 + row) * 8192 + (KC) * 64 + wc4 * 8]);           \
        CP16(bdst + (row * 36 + wc4 * 4) * 4,                                 \
             &Kb[(size_t)(s0 + row) * 8192 + (KC) * 64 + wc4 * 8]);           \
    }                                                                         \
    CP_COMMIT();                                                              \
} while (0)

    QK_ISSUE(0, 0);
    QK_ISSUE(1, 1);
    for (int kc = 0; kc < 64; kc++) {
        const int buf = kc % 3;
        if (kc < 63) CP_WAIT1();
        else         CP_WAIT0();
        __syncthreads();
        if (kc + 2 < 64) QK_ISSUE(kc + 2, (kc + 2) % 3);

        const uint32_t* Asb = dsm + buf * 4608;
        const uint32_t* Bsb = dsm + 13824 + buf * 4608;
#pragma unroll
        for (int ks = 0; ks < 4; ks++) {
            const int kk = ks * 8;
            uint32_t a[4][4], b[4][2];
#pragma unroll
            for (int mt = 0; mt < 4; mt++) {
                int tw = orow * 64 + mt * 16 + fg;
                a[mt][0] = Asb[tw * 36 + kk + ft];
                a[mt][1] = Asb[(tw + 8) * 36 + kk + ft];
                a[mt][2] = Asb[tw * 36 + kk + ft + 4];
                a[mt][3] = Asb[(tw + 8) * 36 + kk + ft + 4];
            }
#pragma unroll
            for (int nt = 0; nt < 4; nt++) {
                int sw = jcol * 32 + nt * 8 + fg;
                b[nt][0] = Bsb[sw * 36 + kk + ft];
                b[nt][1] = Bsb[sw * 36 + kk + ft + 4];
            }
#pragma unroll
            for (int mt = 0; mt < 4; mt++)
#pragma unroll
                for (int nt = 0; nt < 4; nt++)
                    mma_f16(acc[mt][nt], a[mt], b[nt]);
        }
    }
#undef QK_ISSUE

    const float scale = 0.011048543456039806f;   // 1/sqrt(8192)
    float* Sg = g_Sp + (size_t)c * 2097152 + (size_t)g * 262144;
#pragma unroll
    for (int mt = 0; mt < 4; mt++) {
        const int tl = t0 + orow * 64 + mt * 16 + fg;
#pragma unroll
        for (int nt = 0; nt < 4; nt++) {
            const int sl = s0 + jcol * 32 + nt * 8 + 2 * ft;
            *reinterpret_cast<float2*>(&Sg[(size_t)tl * 512 + sl]) =
                make_float2(acc[mt][nt][0] * scale, acc[mt][nt][1] * scale);
            *reinterpret_cast<float2*>(&Sg[(size_t)(tl + 8) * 512 + sl]) =
                make_float2(acc[mt][nt][2] * scale, acc[mt][nt][3] * scale);
        }
    }
}

// ---------------------------------------------------------------------------
// Row softmax over 512, fusing the split-K (x2) partial sum; writes half Sh.
// ---------------------------------------------------------------------------
__global__ void __launch_bounds__(256) softmax_kernel()
{
    const size_t row = (size_t)blockIdx.x * 512;
    const int t = threadIdx.x;
    float a = 0.f, b = 0.f;
#pragma unroll
    for (int c = 0; c < 2; c++) {
        const float* p = g_Sp + (size_t)c * 2097152 + row;
        a += p[t]; b += p[t + 256];
    }
    __shared__ float sh[256];
    sh[t] = fmaxf(a, b);
    __syncthreads();
    for (int off = 128; off > 0; off >>= 1) {
        if (t < off) sh[t] = fmaxf(sh[t], sh[t + off]);
        __syncthreads();
    }
    float m = sh[0];
    __syncthreads();
    float e0 = __expf(a - m), e1 = __expf(b - m);
    sh[t] = e0 + e1;
    __syncthreads();
    for (int off = 128; off > 0; off >>= 1) {
        if (t < off) sh[t] += sh[t + off];
        __syncthreads();
    }
    float inv = 1.0f / sh[0];
    __half* q = g_Sh + row;
    q[t] = __float2half_rn(e0 * inv);
    q[t + 256] = __float2half_rn(e1 * inv);
}

// ---------------------------------------------------------------------------
// PV GEMM (conv clone, pure cp.async): Z[ch][f*512+t] = sum_s P[t][s] V'[s][f]
// A = Sh[g][t][s-pairs], B = Vt[g*64+cn][f][s-pairs]; K=512 = 8 chunks.
// grid (64 cn, 4 t-tiles, 8 g), 256 threads, 3-buffer pipeline.
// ---------------------------------------------------------------------------
__global__ void __launch_bounds__(256, 2) pv_mma2_kernel()
{
    extern __shared__ __align__(16) uint32_t dsm[];
    const uint32_t sb = smem_u32(dsm);
    const int g = blockIdx.z;
    const int n = g & 3, bb = g >> 2;
    const int cn = blockIdx.x;
    const int t0 = blockIdx.y * 128;
    const __half* Pb = g_Sh + (size_t)g * 262144;
    const __half* Vb = g_Vt + (size_t)(g * 64 + cn) * 65536;
    float* Zb = g_Z + ((size_t)bb * 256 + (size_t)(n * 64 + cn)) * 65536;

    const int tid = threadIdx.x;
    const int w = tid >> 5, l = tid & 31;
    const int fg = l >> 2, ft = l & 3;
    const int orow = w >> 2, jcol = w & 3;
    const int wrow0 = tid >> 3, wc4 = tid & 7;

    float acc[4][4][4];
#pragma unroll
    for (int mt = 0; mt < 4; mt++)
#pragma unroll
        for (int nt = 0; nt < 4; nt++)
#pragma unroll
            for (int i = 0; i < 4; i++) acc[mt][nt][i] = 0.f;

#define PV_ISSUE(KC, BUF) do {                                                \
    uint32_t adst = sb + (BUF) * 18432;                                       \
    uint32_t bdst = sb + 55296 + (BUF) * 18432;                               \
    _Pragma("unroll")                                                         \
    for (int it = 0; it < 4; it++) {                                          \
        int row = wrow0 + it * 32;                                            \
        CP16(adst + (row * 36 + wc4 * 4) * 4,                                 \
             &Pb[(size_t)(t0 + row) * 512 + (KC) * 64 + wc4 * 8]);            \
        CP16(bdst + (row * 36 + wc4 * 4) * 4,                                 \
             &Vb[(size_t)row * 512 + (KC) * 64 + wc4 * 8]);                   \
    }                                                                         \
    CP_COMMIT();                                                              \
} while (0)

    PV_ISSUE(0, 0);
    PV_ISSUE(1, 1);
    for (int kc = 0; kc < 8; kc++) {
        const int buf = kc % 3;
        if (kc < 7) CP_WAIT1();
        else        CP_WAIT0();
        __syncthreads();
        if (kc + 2 < 8) PV_ISSUE(kc + 2, (kc + 2) % 3);

        const uint32_t* Asb = dsm + buf * 4608;
        const uint32_t* Bsb = dsm + 13824 + buf * 4608;
#pragma unroll
        for (int ks = 0; ks < 4; ks++) {
            const int kk = ks * 8;
            uint32_t a[4][4], b[4][2];
#pragma unroll
            for (int mt = 0; mt < 4; mt++) {
                int tw = orow * 64 + mt * 16 + fg;
                a[mt][0] = Asb[tw * 36 + kk + ft];
                a[mt][1] = Asb[(tw + 8) * 36 + kk + ft];
                a[mt][2] = Asb[tw * 36 + kk + ft + 4];
                a[mt][3] = Asb[(tw + 8) * 36 + kk + ft + 4];
            }
#pragma unroll
            for (int nt = 0; nt < 4; nt++) {
                int fw = jcol * 32 + nt * 8 + fg;
                b[nt][0] = Bsb[fw * 36 + kk + ft];
                b[nt][1] = Bsb[fw * 36 + kk + ft + 4];
            }
#pragma unroll
            for (int mt = 0; mt < 4; mt++)
#pragma unroll
                for (int nt = 0; nt < 4; nt++)
                    mma_f16(acc[mt][nt], a[mt], b[nt]);
        }
    }
#undef PV_ISSUE

    // C: (m=t, n=f). c0/c1 -> f, f+1 (stride-512 rows); c2/c3 -> t+8.
#pragma unroll
    for (int mt = 0; mt < 4; mt++) {
        const int tl = t0 + orow * 64 + mt * 16 + fg;
#pragma unroll
        for (int nt = 0; nt < 4; nt++) {
            const int f0 = jcol * 32 + nt * 8 + 2 * ft;
            Zb[(size_t)f0 * 512 + tl]           = acc[mt][nt][0];
            Zb[(size_t)(f0 + 1) * 512 + tl]     = acc[mt][nt][1];
            Zb[(size_t)f0 * 512 + tl + 8]       = acc[mt][nt][2];
            Zb[(size_t)(f0 + 1) * 512 + tl + 8] = acc[mt][nt][3];
        }
    }
}

// ---------------------------------------------------------------------------
// Final: out = PReLU(norm(Yp)*gp + betap) + x
// ---------------------------------------------------------------------------
__global__ void __launch_bounds__(256) apply_final_kernel(
    const float* __restrict__ x, const float* __restrict__ gp,
    const float* __restrict__ betap, const float2* __restrict__ stats2,
    float* __restrict__ out)
{
    size_t i = ((size_t)blockIdx.x * 256 + threadIdx.x) * 4;
    int r = (int)(i >> 16);
    int bidx = r >> 8;
    int o = r & 255;
    float2 st = stats2[bidx];
    float gg = gp[o] * st.y;
    float ofs = betap[o] - st.x * gg;
    float4 v  = *reinterpret_cast<const float4*>(&g_Yp[i]);
    float4 xr = *reinterpret_cast<const float4*>(&x[i]);
    v.x = fmaf(v.x, gg, ofs); v.x = ((v.x >= 0.f) ? v.x : 0.25f * v.x) + xr.x;
    v.y = fmaf(v.y, gg, ofs); v.y = ((v.y >= 0.f) ? v.y : 0.25f * v.y) + xr.y;
    v.z = fmaf(v.z, gg, ofs); v.z = ((v.z >= 0.f) ? v.z : 0.25f * v.z) + xr.z;
    v.w = fmaf(v.w, gg, ofs); v.w = ((v.w >= 0.f) ? v.w : 0.25f * v.w) + xr.w;
    *reinterpret_cast<float4*>(&out[i]) = v;
}

// ---------------------------------------------------------------------------
extern "C" void kernel_launch(void* const* d_in, const int* in_sizes, int n_in,
                              void* d_out, int out_size)
{
    const float* x     = (const float*)d_in[0];
    const float* Wq    = (const float*)d_in[1];
    const float* bq    = (const float*)d_in[2];
    const float* gq    = (const float*)d_in[3];
    const float* betaq = (const float*)d_in[4];
    const float* Wk    = (const float*)d_in[5];
    const float* bk    = (const float*)d_in[6];
    const float* gk    = (const float*)d_in[7];
    const float* betak = (const float*)d_in[8];
    const float* Wv    = (const float*)d_in[9];
    const float* bv    = (const float*)d_in[10];
    const float* gv    = (const float*)d_in[11];
    const float* betav = (const float*)d_in[12];
    const float* Wp    = (const float*)d_in[13];
    const float* bp    = (const float*)d_in[14];
    const float* gp    = (const float*)d_in[15];
    const float* betap = (const float*)d_in[16];

    float *Y3, *Z, *Yp;
    __half *Xh, *Wh;
    float2 *part, *stats;
    cudaGetSymbolAddress((void**)&Y3,   g_Y3);
    cudaGetSymbolAddress((void**)&Z,    g_Z);
    cudaGetSymbolAddress((void**)&Yp,   g_Yp);
    cudaGetSymbolAddress((void**)&Xh,   g_Xh);
    cudaGetSymbolAddress((void**)&Wh,   g_Wh);
    cudaGetSymbolAddress((void**)&part, g_part);
    cudaGetSymbolAddress((void**)&stats, g_stats);

    const int SM_G = 110592;  // 6 tiles x 4608 u32 x 4B
    cudaFuncSetAttribute(conv_f16_kernel, cudaFuncAttributeMaxDynamicSharedMemorySize, SM_G);
    cudaFuncSetAttribute(qk_mma2_kernel,  cudaFuncAttributeMaxDynamicSharedMemorySize, SM_G);
    cudaFuncSetAttribute(pv_mma2_kernel,  cudaFuncAttributeMaxDynamicSharedMemorySize, SM_G);

    // 0) pack weights + transpose-pack X to half
    pack_w_kernel<<<1024, 256>>>(Wq, Wk, Wv, Wp, Wh);
    transpose_pack_kernel<<<dim3(2048, 8, 2), dim3(32, 8)>>>(x, Xh);
    // 1) QKV projections via fp16 mma.sync (+ fused norm partials)
    conv_f16_kernel<<<dim3(512, 6, 2), 256, SM_G>>>(Xh, Y3, Wh, bq, bk, bv, part, 3);
    // 2) finalize QKV GroupNorm stats: 24 groups x 512 partials
    reduce_final_kernel<<<24, 256>>>(part, stats, 512, 1.0f / 4194304.0f);
    // 3) normalize+pack prepasses: Q/K -> QKh (k-contig), V -> Vt (transposed)
    qk_pack_kernel<<<dim3(64, 16), 256>>>(gq, betaq, gk, betak);
    v_pack_kernel<<<dim3(16, 4, 512), dim3(32, 8)>>>(gv, betav);
    // 4) S partials = scale * Q'K'^T  (pure cp.async fp16 GEMM, split-K x2)
    qk_mma2_kernel<<<dim3(4, 4, 16), 256, SM_G>>>();
    // 5) softmax rows (fuses split-K reduction), writes half Sh
    softmax_kernel<<<4096, 256>>>();
    // 6) Vo = P V' (pure cp.async fp16 GEMM), permuted write into Z
    pv_mma2_kernel<<<dim3(64, 4, 8), 256, SM_G>>>();
    // 7) transpose-pack Z -> Xh (reused as Zh), then fp16 projection
    transpose_pack_kernel<<<dim3(2048, 8, 2), dim3(32, 8)>>>(Z, Xh);
    conv_f16_kernel<<<dim3(512, 2, 2), 256, SM_G>>>(Xh, Yp, Wh, bp, bp, bp, part, 1);
    // 8) finalize per-sample stats: 2 groups (slabs 6,7) x 2048 partials
    reduce_final_kernel<<<2, 256>>>(part + 6ull * 4 * 512, stats + 24, 2048, 1.0f / 16777216.0f);
    // 9) normalize + PReLU + residual
    apply_final_kernel<<<32768, 256>>>(x, gp, betap, stats + 24, (float*)d_out);
}

// round 17
// speedup vs baseline: 1.5551x; 1.0231x over previous
#include <cuda_runtime.h>
#include <cuda_fp16.h>
#include <cstdint>

// Problem constants: B=2, C=256, T=512, F=128, N=4 heads, H=CN=64, D=H*F=8192
#define TFsz 65536            // T*F
typedef unsigned long long u64;

// -------- scratch (device globals; no allocations allowed) --------
__device__ __half g_Y3h[100663296]; // [3][B][256][TF] Q,K,V pre-norm (half)
__device__ float g_Sp[4194304];     // [2 kchunks][8 g][512][512] partial scores
__device__ __half g_Zh[33554432];   // [B][256][TF] permuted attn output (half)
__device__ float g_Yp[33554432];    // [B][256][TF] final conv output (f32)
__device__ __half g_Xh[33554432];   // [B][TF][256] transpose-packed X (then Z)
__device__ __half g_Wh[262144];     // [4][256][256] packed weights (q,k,v,p)
__device__ __half g_QKh[67108864];  // [2][8][512][8192] normalized Q,K (k-contig)
__device__ __half g_Vt[33554432];   // [8][64][128 f][512 s] normalized V^T
__device__ __half g_Sh[2097152];    // [8][512][512] attention probs (half)
__device__ float2 g_part[12288];    // partial (sum, sumsq) from GEMM epilogues
__device__ float2 g_stats[32];      // (mu, rstd): [0..23] qkv groups, [24..25] final

// -------- PTX helpers (portable; no "a"-gated features) --------
__device__ __forceinline__ uint32_t smem_u32(const void* p) {
    uint32_t a;
    asm("{ .reg .u64 t; cvta.to.shared.u64 t, %1; cvt.u32.u64 %0, t; }" : "=r"(a) : "l"(p));
    return a;
}
#define CP16(dst, src) \
    asm volatile("cp.async.cg.shared.global [%0], [%1], 16;" :: "r"(dst), "l"(src))
#define CP_COMMIT() asm volatile("cp.async.commit_group;" ::: "memory")
#define CP_WAIT1()  asm volatile("cp.async.wait_group 1;" ::: "memory")
#define CP_WAIT0()  asm volatile("cp.async.wait_group 0;" ::: "memory")

// fp16 pair pack: h0 = lo, h1 = hi
__device__ __forceinline__ uint32_t pack_h2(float lo, float hi) {
    uint32_t r; asm("cvt.rn.f16x2.f32 %0, %1, %2;" : "=r"(r) : "f"(hi), "f"(lo)); return r;
}
__device__ __forceinline__ void mma_f16(float c[4], const uint32_t a[4], const uint32_t b[2]) {
    asm volatile(
        "mma.sync.aligned.m16n8k16.row.col.f32.f16.f16.f32 "
        "{%0,%1,%2,%3}, {%4,%5,%6,%7}, {%8,%9}, {%0,%1,%2,%3};"
        : "+f"(c[0]), "+f"(c[1]), "+f"(c[2]), "+f"(c[3])
        : "r"(a[0]), "r"(a[1]), "r"(a[2]), "r"(a[3]), "r"(b[0]), "r"(b[1]));
}
__device__ __forceinline__ float napply(float v, float gg, float of) {
    float y = fmaf(v, gg, of);
    return (y >= 0.f) ? y : 0.25f * y;
}

// ---------------------------------------------------------------------------
// Pack all 4 weight matrices to half: g_Wh[t][o][c], t in {q,k,v,p}.
// ---------------------------------------------------------------------------
__global__ void __launch_bounds__(256) pack_w_kernel(
    const float* __restrict__ Wq, const float* __restrict__ Wk,
    const float* __restrict__ Wv, const float* __restrict__ Wp, __half* __restrict__ dst)
{
    int i = blockIdx.x * 256 + threadIdx.x;
    int s = i >> 16;
    const float* src = (s == 0) ? Wq : (s == 1) ? Wk : (s == 2) ? Wv : Wp;
    dst[i] = __float2half_rn(src[i & 65535]);
}

// ---------------------------------------------------------------------------
// Transpose-pack f32->half: src [b][256][TF] f32 -> dst [b][TF][256] half.
// grid (2048, 8, 2), block (32, 8).
// ---------------------------------------------------------------------------
__global__ void __launch_bounds__(256) transpose_pack_kernel(
    const float* __restrict__ src, __half* __restrict__ dst)
{
    __shared__ float tile[32][33];
    const int b = blockIdx.z;
    const int j0 = blockIdx.x * 32, c0 = blockIdx.y * 32;
    const float* s = src + (size_t)b * 16777216;
    __half* d = dst + (size_t)b * 16777216;
    const int tx = threadIdx.x, ty = threadIdx.y;
#pragma unroll
    for (int r = 0; r < 4; r++)
        tile[ty + r * 8][tx] = s[(size_t)(c0 + ty + r * 8) * TFsz + j0 + tx];
    __syncthreads();
#pragma unroll
    for (int r = 0; r < 4; r++)
        d[(size_t)(j0 + ty + r * 8) * 256 + c0 + tx] = __float2half_rn(tile[tx][ty + r * 8]);
}

// ---------------------------------------------------------------------------
// Transpose half->half: src [b][256][TF] half -> dst [b][TF][256] half.
// grid (2048, 8, 2), block (32, 8). Pitch 34 halfs: odd bank stride, no cfl.
// ---------------------------------------------------------------------------
__global__ void __launch_bounds__(256) transpose_h_kernel(
    const __half* __restrict__ src, __half* __restrict__ dst)
{
    __shared__ __half tile[32][34];
    const int b = blockIdx.z;
    const int j0 = blockIdx.x * 32, c0 = blockIdx.y * 32;
    const __half* s = src + (size_t)b * 16777216;
    __half* d = dst + (size_t)b * 16777216;
    const int tx = threadIdx.x, ty = threadIdx.y;
#pragma unroll
    for (int r = 0; r < 4; r++)
        tile[ty + r * 8][tx] = s[(size_t)(c0 + ty + r * 8) * TFsz + j0 + tx];
    __syncthreads();
#pragma unroll
    for (int r = 0; r < 4; r++)
        d[(size_t)(j0 + ty + r * 8) * 256 + c0 + tx] = tile[tx][ty + r * 8];
}

// ---------------------------------------------------------------------------
// fp16 mma.sync conv GEMM (cp.async 3-buffer prefetch-2):
//   Out[slab][o][j] = bias[o] + sum_c W[o][c] * Xh[b][j][c]
// grid (2*nTens [FAST: slabs sharing X tile co-scheduled], 512 j-tiles, B).
// nTens==3 -> half output (Y3h); nTens==1 -> f32 output (Yp).
// Epilogue fuses bias + per-64-channel-group (sum,sumsq) partials (f32 accs).
// ---------------------------------------------------------------------------
__global__ void __launch_bounds__(256, 2) conv_f16_kernel(
    const __half* __restrict__ Xh, __half* __restrict__ OutH, float* __restrict__ OutF,
    const __half* __restrict__ Whall,
    const float* __restrict__ b0_, const float* __restrict__ b1_, const float* __restrict__ b2_,
    float2* __restrict__ part, int nTens)
{
    extern __shared__ __align__(16) uint32_t dsm[];
    const uint32_t sb = smem_u32(dsm);

    const int bb = blockIdx.z;
    const int y = blockIdx.x;                  // slab dim fastest: X-tile L2 reuse
    const int jt = blockIdx.y;
    const int tens = y >> 1;
    const int o0 = (y & 1) * 128;
    const int j0 = jt * 128;
    const int wsel = (nTens == 3) ? tens : 3;
    const __half* W = Whall + (size_t)wsel * 65536;
    const float* bias = (tens == 0) ? b0_ : (tens == 1) ? b1_ : b2_;
    const __half* Xb = Xh + (size_t)bb * 16777216;
    const int slab = (nTens == 3) ? (tens * 2 + bb) : bb;

    const int tid = threadIdx.x;
    const int w = tid >> 5, l = tid & 31;
    const int g = l >> 2, t = l & 3;
    const int orow = w >> 2, jcol = w & 3;
    const int wrow0 = tid >> 3, wc4 = tid & 7;

    float c[4][4][4];
#pragma unroll
    for (int mt = 0; mt < 4; mt++)
#pragma unroll
        for (int nt = 0; nt < 4; nt++)
#pragma unroll
            for (int i = 0; i < 4; i++) c[mt][nt][i] = 0.f;

#define CONV_ISSUE(KC, BUF) do {                                              \
    uint32_t wdst = sb + (BUF) * 18432;                                       \
    uint32_t xdst = sb + 55296 + (BUF) * 18432;                               \
    _Pragma("unroll")                                                         \
    for (int it = 0; it < 4; it++) {                                          \
        int row = wrow0 + it * 32;                                            \
        CP16(wdst + (row * 36 + wc4 * 4) * 4,                                 \
             &W[(size_t)(o0 + row) * 256 + (KC) * 64 + wc4 * 8]);             \
        CP16(xdst + (row * 36 + wc4 * 4) * 4,                                 \
             &Xb[(size_t)(j0 + row) * 256 + (KC) * 64 + wc4 * 8]);            \
    }                                                                         \
    CP_COMMIT();                                                              \
} while (0)

    CONV_ISSUE(0, 0);
    CONV_ISSUE(1, 1);
    for (int kc = 0; kc < 4; kc++) {
        const int buf = kc % 3;
        if (kc < 3) CP_WAIT1();
        else        CP_WAIT0();
        __syncthreads();
        if (kc + 2 < 4) CONV_ISSUE(kc + 2, (kc + 2) % 3);

        const uint32_t* Wsb = dsm + buf * 4608;
        const uint32_t* Xsb = dsm + 13824 + buf * 4608;
#pragma unroll
        for (int ks = 0; ks < 4; ks++) {
            const int kk = ks * 8;
            uint32_t a[4][4], b[4][2];
#pragma unroll
            for (int mt = 0; mt < 4; mt++) {
                int ow = orow * 64 + mt * 16 + g;
                a[mt][0] = Wsb[ow * 36 + kk + t];
                a[mt][1] = Wsb[(ow + 8) * 36 + kk + t];
                a[mt][2] = Wsb[ow * 36 + kk + t + 4];
                a[mt][3] = Wsb[(ow + 8) * 36 + kk + t + 4];
            }
#pragma unroll
            for (int nt = 0; nt < 4; nt++) {
                int jw = jcol * 32 + nt * 8 + g;
                b[nt][0] = Xsb[jw * 36 + kk + t];
                b[nt][1] = Xsb[jw * 36 + kk + t + 4];
            }
#pragma unroll
            for (int mt = 0; mt < 4; mt++)
#pragma unroll
                for (int nt = 0; nt < 4; nt++)
                    mma_f16(c[mt][nt], a[mt], b[nt]);
        }
    }
#undef CONV_ISSUE

    float bl[4], bh[4];
#pragma unroll
    for (int mt = 0; mt < 4; mt++) {
        bl[mt] = __ldg(&bias[o0 + orow * 64 + mt * 16 + g]);
        bh[mt] = __ldg(&bias[o0 + orow * 64 + mt * 16 + g + 8]);
    }
    float s = 0.f, sq = 0.f;
    __half* OH = OutH + (size_t)slab * (256 * (size_t)TFsz);
    float*  OF = OutF + (size_t)slab * (256 * (size_t)TFsz);
#pragma unroll
    for (int mt = 0; mt < 4; mt++) {
        const int o_lo = o0 + orow * 64 + mt * 16 + g;
#pragma unroll
        for (int nt = 0; nt < 4; nt++) {
            const int jj = j0 + jcol * 32 + nt * 8 + 2 * t;
            float v0 = c[mt][nt][0] + bl[mt];
            float v1 = c[mt][nt][1] + bl[mt];
            float v2 = c[mt][nt][2] + bh[mt];
            float v3 = c[mt][nt][3] + bh[mt];
            if (nTens == 3) {
                *reinterpret_cast<uint32_t*>(&OH[(size_t)o_lo * TFsz + jj]) = pack_h2(v0, v1);
                *reinterpret_cast<uint32_t*>(&OH[(size_t)(o_lo + 8) * TFsz + jj]) = pack_h2(v2, v3);
            } else {
                *reinterpret_cast<float2*>(&OF[(size_t)o_lo * TFsz + jj]) = make_float2(v0, v1);
                *reinterpret_cast<float2*>(&OF[(size_t)(o_lo + 8) * TFsz + jj]) = make_float2(v2, v3);
            }
            s  += (v0 + v1) + (v2 + v3);
            sq += (v0 * v0 + v1 * v1) + (v2 * v2 + v3 * v3);
        }
    }

    __syncthreads();
    float* redS = reinterpret_cast<float*>(dsm);
    float* redQ = redS + 256;
    redS[tid] = s; redQ[tid] = sq;
    __syncthreads();
    const int r = tid & 127;
    for (int off = 64; off > 0; off >>= 1) {
        if (r < off) { redS[tid] += redS[tid + off]; redQ[tid] += redQ[tid + off]; }
        __syncthreads();
    }
    if (r == 0) {
        int og = (y & 1) * 2 + (tid >> 7);
        part[((size_t)((nTens == 3) ? (tens * 2 + bb) : (6 + bb)) * 4 + og) * 512 + jt] =
            make_float2(redS[tid], redQ[tid]);
    }
}

// ---------------------------------------------------------------------------
// Final reduction over `count` consecutive partials per group -> (mu, rstd)
// ---------------------------------------------------------------------------
__global__ void __launch_bounds__(256) reduce_final_kernel(
    const float2* __restrict__ part, float2* __restrict__ stats, int count, float inv_n)
{
    const int g = blockIdx.x;
    float s = 0.f, s2 = 0.f;
    for (int i = threadIdx.x; i < count; i += 256) {
        float2 v = part[(size_t)g * count + i];
        s += v.x; s2 += v.y;
    }
    __shared__ float sh[256], sh2[256];
    int t = threadIdx.x;
    sh[t] = s; sh2[t] = s2;
    __syncthreads();
    for (int off = 128; off > 0; off >>= 1) {
        if (t < off) { sh[t] += sh[t + off]; sh2[t] += sh2[t + off]; }
        __syncthreads();
    }
    if (t == 0) {
        float mu = sh[0] * inv_n;
        float var = fmaxf(sh2[0] * inv_n - mu * mu, 0.f);
        stats[g] = make_float2(mu, rsqrtf(var + 1e-6f));
    }
}

// ---------------------------------------------------------------------------
// QK pack prepass: normalize+PReLU Q,K (half src), write half k-contiguous:
//   QKh[slab][t][h*128+f] = napply(Y3h[...])
// grid (64 h, 16 slabs), 256 threads.
// ---------------------------------------------------------------------------
__global__ void __launch_bounds__(256) qk_pack_kernel(
    const float* __restrict__ gq, const float* __restrict__ betaq,
    const float* __restrict__ gk, const float* __restrict__ betak)
{
    const int slab = blockIdx.y;
    const int h = blockIdx.x;
    const int which = slab >> 3, g = slab & 7, n = g & 3;
    const int ch = n * 64 + h;
    float2 st = g_stats[which * 8 + g];
    const float* gw = which ? gk : gq;
    const float* bw = which ? betak : betaq;
    const float gg = gw[ch] * st.y;
    const float of = bw[ch] - st.x * gg;
    const __half* src = g_Y3h + (size_t)(which * 8 + g) * 4194304 + (size_t)h * 65536;
    __half* dst = g_QKh + (size_t)slab * 4194304 + (size_t)h * 128;
    const int f4 = (threadIdx.x & 31) * 4, tr = threadIdx.x >> 5;
#pragma unroll 4
    for (int t0 = 0; t0 < 512; t0 += 8) {
        int t = t0 + tr;
        uint2 hv = *reinterpret_cast<const uint2*>(&src[(size_t)t * 128 + f4]);
        __half2 p0 = *reinterpret_cast<__half2*>(&hv.x);
        __half2 p1 = *reinterpret_cast<__half2*>(&hv.y);
        uint2 u;
        u.x = pack_h2(napply(__half2float(p0.x), gg, of), napply(__half2float(p0.y), gg, of));
        u.y = pack_h2(napply(__half2float(p1.x), gg, of), napply(__half2float(p1.y), gg, of));
        *reinterpret_cast<uint2*>(&dst[(size_t)t * 8192 + f4]) = u;
    }
}

// ---------------------------------------------------------------------------
// V pack prepass: normalize+PReLU V (half src), transposed (k=s contiguous):
//   Vt[g*64+cn][f][s] = napply(V[g][cn][s][f])
// grid (16 s-tiles, 4 f-tiles, 512 = g*64+cn), block (32, 8).
// ---------------------------------------------------------------------------
__global__ void __launch_bounds__(256) v_pack_kernel(
    const float* __restrict__ gv, const float* __restrict__ betav)
{
    __shared__ float tile[32][33];
    const int z = blockIdx.z, g = z >> 6, cn = z & 63, n = g & 3;
    float2 st = g_stats[16 + g];
    const float gg = gv[n * 64 + cn] * st.y;
    const float of = betav[n * 64 + cn] - st.x * gg;
    const __half* src = g_Y3h + 16ull * 4194304 + (size_t)g * 4194304 + (size_t)cn * 65536;
    __half* dst = g_Vt + (size_t)z * 65536;
    const int s0 = blockIdx.x * 32, f0 = blockIdx.y * 32;
    const int tx = threadIdx.x, ty = threadIdx.y;
#pragma unroll
    for (int r = 0; r < 4; r++)
        tile[ty + r * 8][tx] = __half2float(src[(size_t)(s0 + ty + r * 8) * 128 + f0 + tx]);
    __syncthreads();
#pragma unroll
    for (int r = 0; r < 4; r++)
        dst[(size_t)(f0 + ty + r * 8) * 512 + s0 + tx] =
            __float2half_rn(napply(tile[tx][ty + r * 8], gg, of));
}

// ---------------------------------------------------------------------------
// QK GEMM (pure cp.async): Sp[c][g][t][s] = scale*sum Q'(t,k)K'(s,k)
// split-K x2. grid (4 s-tiles, 4 t-tiles, 16 = g*2+c), 3-buffer pipeline.
// ---------------------------------------------------------------------------
__global__ void __launch_bounds__(256, 2) qk_mma2_kernel()
{
    extern __shared__ __align__(16) uint32_t dsm[];
    const uint32_t sb = smem_u32(dsm);
    const int z = blockIdx.z, g = z >> 1, c = z & 1;
    const __half* Qb = g_QKh + (size_t)g * 4194304 + (size_t)c * 4096;
    const __half* Kb = g_QKh + (size_t)(8 + g) * 4194304 + (size_t)c * 4096;
    const int t0 = blockIdx.y * 128, s0 = blockIdx.x * 128;
    const int tid = threadIdx.x;
    const int w = tid >> 5, l = tid & 31;
    const int fg = l >> 2, ft = l & 3;
    const int orow = w >> 2, jcol = w & 3;
    const int wrow0 = tid >> 3, wc4 = tid & 7;

    float acc[4][4][4];
#pragma unroll
    for (int mt = 0; mt < 4; mt++)
#pragma unroll
        for (int nt = 0; nt < 4; nt++)
#pragma unroll
            for (int i = 0; i < 4; i++) acc[mt][nt][i] = 0.f;

#define QK_ISSUE(KC, BUF) do {                                                \
    uint32_t adst = sb + (BUF) * 18432;                                       \
    uint32_t bdst = sb + 55296 + (BUF) * 18432;                               \
    _Pragma("unroll")                                                         \
    for (int it = 0; it < 4; it++) {                                          \
        int row = wrow0 + it * 32;                                            \
        CP16(adst + (row * 36 + wc4 * 4) * 4,                                 \
             &Qb[(size_t)(t0 + row) * 8192 + (KC) * 64 + wc4 * 8]);           \
        CP16(bdst + (row * 36 + wc4 * 4) * 4,                                 \
             &Kb[(size_t)(s0 + row) * 8192 + (KC) * 64 + wc4 * 8]);           \
    }                                                                         \
    CP_COMMIT();                                                              \
} while (0)

    QK_ISSUE(0, 0);
    QK_ISSUE(1, 1);
    for (int kc = 0; kc < 64; kc++) {
        const int buf = kc % 3;
        if (kc < 63) CP_WAIT1();
        else         CP_WAIT0();
        __syncthreads();
        if (kc + 2 < 64) QK_ISSUE(kc + 2, (kc + 2) % 3);

        const uint32_t* Asb = dsm + buf * 4608;
        const uint32_t* Bsb = dsm + 13824 + buf * 4608;
#pragma unroll
        for (int ks = 0; ks < 4; ks++) {
            const int kk = ks * 8;
            uint32_t a[4][4], b[4][2];
#pragma unroll
            for (int mt = 0; mt < 4; mt++) {
                int tw = orow * 64 + mt * 16 + fg;
                a[mt][0] = Asb[tw * 36 + kk + ft];
                a[mt][1] = Asb[(tw + 8) * 36 + kk + ft];
                a[mt][2] = Asb[tw * 36 + kk + ft + 4];
                a[mt][3] = Asb[(tw + 8) * 36 + kk + ft + 4];
            }
#pragma unroll
            for (int nt = 0; nt < 4; nt++) {
                int sw = jcol * 32 + nt * 8 + fg;
                b[nt][0] = Bsb[sw * 36 + kk + ft];
                b[nt][1] = Bsb[sw * 36 + kk + ft + 4];
            }
#pragma unroll
            for (int mt = 0; mt < 4; mt++)
#pragma unroll
                for (int nt = 0; nt < 4; nt++)
                    mma_f16(acc[mt][nt], a[mt], b[nt]);
        }
    }
#undef QK_ISSUE

    const float scale = 0.011048543456039806f;   // 1/sqrt(8192)
    float* Sg = g_Sp + (size_t)c * 2097152 + (size_t)g * 262144;
#pragma unroll
    for (int mt = 0; mt < 4; mt++) {
        const int tl = t0 + orow * 64 + mt * 16 + fg;
#pragma unroll
        for (int nt = 0; nt < 4; nt++) {
            const int sl = s0 + jcol * 32 + nt * 8 + 2 * ft;
            *reinterpret_cast<float2*>(&Sg[(size_t)tl * 512 + sl]) =
                make_float2(acc[mt][nt][0] * scale, acc[mt][nt][1] * scale);
            *reinterpret_cast<float2*>(&Sg[(size_t)(tl + 8) * 512 + sl]) =
                make_float2(acc[mt][nt][2] * scale, acc[mt][nt][3] * scale);
        }
    }
}

// ---------------------------------------------------------------------------
// Row softmax over 512, fusing the split-K (x2) partial sum; writes half Sh.
// ---------------------------------------------------------------------------
__global__ void __launch_bounds__(256) softmax_kernel()
{
    const size_t row = (size_t)blockIdx.x * 512;
    const int t = threadIdx.x;
    float a = 0.f, b = 0.f;
#pragma unroll
    for (int c = 0; c < 2; c++) {
        const float* p = g_Sp + (size_t)c * 2097152 + row;
        a += p[t]; b += p[t + 256];
    }
    __shared__ float sh[256];
    sh[t] = fmaxf(a, b);
    __syncthreads();
    for (int off = 128; off > 0; off >>= 1) {
        if (t < off) sh[t] = fmaxf(sh[t], sh[t + off]);
        __syncthreads();
    }
    float m = sh[0];
    __syncthreads();
    float e0 = __expf(a - m), e1 = __expf(b - m);
    sh[t] = e0 + e1;
    __syncthreads();
    for (int off = 128; off > 0; off >>= 1) {
        if (t < off) sh[t] += sh[t + off];
        __syncthreads();
    }
    float inv = 1.0f / sh[0];
    __half* q = g_Sh + row;
    q[t] = __float2half_rn(e0 * inv);
    q[t + 256] = __float2half_rn(e1 * inv);
}

// ---------------------------------------------------------------------------
// PV GEMM (pure cp.async): Zh[ch][f*512+t] = sum_s P[t][s] V'[s][f]  (half out)
// grid (64 cn, 4 t-tiles, 8 g), 3-buffer pipeline.
// ---------------------------------------------------------------------------
__global__ void __launch_bounds__(256, 2) pv_mma2_kernel()
{
    extern __shared__ __align__(16) uint32_t dsm[];
    const uint32_t sb = smem_u32(dsm);
    const int g = blockIdx.z;
    const int n = g & 3, bb = g >> 2;
    const int cn = blockIdx.x;
    const int t0 = blockIdx.y * 128;
    const __half* Pb = g_Sh + (size_t)g * 262144;
    const __half* Vb = g_Vt + (size_t)(g * 64 + cn) * 65536;
    __half* Zb = g_Zh + ((size_t)bb * 256 + (size_t)(n * 64 + cn)) * 65536;

    const int tid = threadIdx.x;
    const int w = tid >> 5, l = tid & 31;
    const int fg = l >> 2, ft = l & 3;
    const int orow = w >> 2, jcol = w & 3;
    const int wrow0 = tid >> 3, wc4 = tid & 7;

    float acc[4][4][4];
#pragma unroll
    for (int mt = 0; mt < 4; mt++)
#pragma unroll
        for (int nt = 0; nt < 4; nt++)
#pragma unroll
            for (int i = 0; i < 4; i++) acc[mt][nt][i] = 0.f;

#define PV_ISSUE(KC, BUF) do {                                                \
    uint32_t adst = sb + (BUF) * 18432;                                       \
    uint32_t bdst = sb + 55296 + (BUF) * 18432;                               \
    _Pragma("unroll")                                                         \
    for (int it = 0; it < 4; it++) {                                          \
        int row = wrow0 + it * 32;                                            \
        CP16(adst + (row * 36 + wc4 * 4) * 4,                                 \
             &Pb[(size_t)(t0 + row) * 512 + (KC) * 64 + wc4 * 8]);            \
        CP16(bdst + (row * 36 + wc4 * 4) * 4,                                 \
             &Vb[(size_t)row * 512 + (KC) * 64 + wc4 * 8]);                   \
    }                                                                         \
    CP_COMMIT();                                                              \
} while (0)

    PV_ISSUE(0, 0);
    PV_ISSUE(1, 1);
    for (int kc = 0; kc < 8; kc++) {
        const int buf = kc % 3;
        if (kc < 7) CP_WAIT1();
        else        CP_WAIT0();
        __syncthreads();
        if (kc + 2 < 8) PV_ISSUE(kc + 2, (kc + 2) % 3);

        const uint32_t* Asb = dsm + buf * 4608;
        const uint32_t* Bsb = dsm + 13824 + buf * 4608;
#pragma unroll
        for (int ks = 0; ks < 4; ks++) {
            const int kk = ks * 8;
            uint32_t a[4][4], b[4][2];
#pragma unroll
            for (int mt = 0; mt < 4; mt++) {
                int tw = orow * 64 + mt * 16 + fg;
                a[mt][0] = Asb[tw * 36 + kk + ft];
                a[mt][1] = Asb[(tw + 8) * 36 + kk + ft];
                a[mt][2] = Asb[tw * 36 + kk + ft + 4];
                a[mt][3] = Asb[(tw + 8) * 36 + kk + ft + 4];
            }
#pragma unroll
            for (int nt = 0; nt < 4; nt++) {
                int fw = jcol * 32 + nt * 8 + fg;
                b[nt][0] = Bsb[fw * 36 + kk + ft];
                b[nt][1] = Bsb[fw * 36 + kk + ft + 4];
            }
#pragma unroll
            for (int mt = 0; mt < 4; mt++)
#pragma unroll
                for (int nt = 0; nt < 4; nt++)
                    mma_f16(acc[mt][nt], a[mt], b[nt]);
        }
    }
#undef PV_ISSUE

    // C: (m=t, n=f). Half scalar stores into permuted layout.
#pragma unroll
    for (int mt = 0; mt < 4; mt++) {
        const int tl = t0 + orow * 64 + mt * 16 + fg;
#pragma unroll
        for (int nt = 0; nt < 4; nt++) {
            const int f0 = jcol * 32 + nt * 8 + 2 * ft;
            Zb[(size_t)f0 * 512 + tl]           = __float2half_rn(acc[mt][nt][0]);
            Zb[(size_t)(f0 + 1) * 512 + tl]     = __float2half_rn(acc[mt][nt][1]);
            Zb[(size_t)f0 * 512 + tl + 8]       = __float2half_rn(acc[mt][nt][2]);
            Zb[(size_t)(f0 + 1) * 512 + tl + 8] = __float2half_rn(acc[mt][nt][3]);
        }
    }
}

// ---------------------------------------------------------------------------
// Final: out = PReLU(norm(Yp)*gp + betap) + x
// ---------------------------------------------------------------------------
__global__ void __launch_bounds__(256) apply_final_kernel(
    const float* __restrict__ x, const float* __restrict__ gp,
    const float* __restrict__ betap, const float2* __restrict__ stats2,
    float* __restrict__ out)
{
    size_t i = ((size_t)blockIdx.x * 256 + threadIdx.x) * 4;
    int r = (int)(i >> 16);
    int bidx = r >> 8;
    int o = r & 255;
    float2 st = stats2[bidx];
    float gg = gp[o] * st.y;
    float ofs = betap[o] - st.x * gg;
    float4 v  = *reinterpret_cast<const float4*>(&g_Yp[i]);
    float4 xr = *reinterpret_cast<const float4*>(&x[i]);
    v.x = fmaf(v.x, gg, ofs); v.x = ((v.x >= 0.f) ? v.x : 0.25f * v.x) + xr.x;
    v.y = fmaf(v.y, gg, ofs); v.y = ((v.y >= 0.f) ? v.y : 0.25f * v.y) + xr.y;
    v.z = fmaf(v.z, gg, ofs); v.z = ((v.z >= 0.f) ? v.z : 0.25f * v.z) + xr.z;
    v.w = fmaf(v.w, gg, ofs); v.w = ((v.w >= 0.f) ? v.w : 0.25f * v.w) + xr.w;
    *reinterpret_cast<float4*>(&out[i]) = v;
}

// ---------------------------------------------------------------------------
extern "C" void kernel_launch(void* const* d_in, const int* in_sizes, int n_in,
                              void* d_out, int out_size)
{
    const float* x     = (const float*)d_in[0];
    const float* Wq    = (const float*)d_in[1];
    const float* bq    = (const float*)d_in[2];
    const float* gq    = (const float*)d_in[3];
    const float* betaq = (const float*)d_in[4];
    const float* Wk    = (const float*)d_in[5];
    const float* bk    = (const float*)d_in[6];
    const float* gk    = (const float*)d_in[7];
    const float* betak = (const float*)d_in[8];
    const float* Wv    = (const float*)d_in[9];
    const float* bv    = (const float*)d_in[10];
    const float* gv    = (const float*)d_in[11];
    const float* betav = (const float*)d_in[12];
    const float* Wp    = (const float*)d_in[13];
    const float* bp    = (const float*)d_in[14];
    const float* gp    = (const float*)d_in[15];
    const float* betap = (const float*)d_in[16];

    float *Yp;
    __half *Y3h, *Zh, *Xh, *Wh;
    float2 *part, *stats;
    cudaGetSymbolAddress((void**)&Y3h,  g_Y3h);
    cudaGetSymbolAddress((void**)&Zh,   g_Zh);
    cudaGetSymbolAddress((void**)&Yp,   g_Yp);
    cudaGetSymbolAddress((void**)&Xh,   g_Xh);
    cudaGetSymbolAddress((void**)&Wh,   g_Wh);
    cudaGetSymbolAddress((void**)&part, g_part);
    cudaGetSymbolAddress((void**)&stats, g_stats);

    const int SM_G = 110592;  // 6 tiles x 4608 u32 x 4B
    cudaFuncSetAttribute(conv_f16_kernel, cudaFuncAttributeMaxDynamicSharedMemorySize, SM_G);
    cudaFuncSetAttribute(qk_mma2_kernel,  cudaFuncAttributeMaxDynamicSharedMemorySize, SM_G);
    cudaFuncSetAttribute(pv_mma2_kernel,  cudaFuncAttributeMaxDynamicSharedMemorySize, SM_G);

    // 0) pack weights + transpose-pack X to half
    pack_w_kernel<<<1024, 256>>>(Wq, Wk, Wv, Wp, Wh);
    transpose_pack_kernel<<<dim3(2048, 8, 2), dim3(32, 8)>>>(x, Xh);
    // 1) QKV projections -> Y3h (half), slab dim fastest for X-tile L2 reuse
    conv_f16_kernel<<<dim3(6, 512, 2), 256, SM_G>>>(Xh, Y3h, Yp, Wh, bq, bk, bv, part, 3);
    // 2) finalize QKV GroupNorm stats: 24 groups x 512 partials
    reduce_final_kernel<<<24, 256>>>(part, stats, 512, 1.0f / 4194304.0f);
    // 3) normalize+pack prepasses: Q/K -> QKh (k-contig), V -> Vt (transposed)
    qk_pack_kernel<<<dim3(64, 16), 256>>>(gq, betaq, gk, betak);
    v_pack_kernel<<<dim3(16, 4, 512), dim3(32, 8)>>>(gv, betav);
    // 4) S partials = scale * Q'K'^T  (pure cp.async fp16 GEMM, split-K x2)
    qk_mma2_kernel<<<dim3(4, 4, 16), 256, SM_G>>>();
    // 5) softmax rows (fuses split-K reduction), writes half Sh
    softmax_kernel<<<4096, 256>>>();
    // 6) Vo = P V' -> Zh (half, permuted)
    pv_mma2_kernel<<<dim3(64, 4, 8), 256, SM_G>>>();
    // 7) transpose Zh -> Xh (half->half), then fp16 projection -> Yp (f32)
    transpose_h_kernel<<<dim3(2048, 8, 2), dim3(32, 8)>>>(Zh, Xh);
    conv_f16_kernel<<<dim3(2, 512, 2), 256, SM_G>>>(Xh, Y3h, Yp, Wh, bp, bp, bp, part, 1);
    // 8) finalize per-sample stats: 2 groups (slabs 6,7) x 2048 partials
    reduce_final_kernel<<<2, 256>>>(part + 6ull * 4 * 512, stats + 24, 2048, 1.0f / 16777216.0f);
    // 9) normalize + PReLU + residual
    apply_final_kernel<<<32768, 256>>>(x, gp, betap, stats + 24, (float*)d_out);
}